// round 11
// baseline (speedup 1.0000x reference)
#include <cuda_runtime.h>
#include <math.h>

#define NN 50000
#define NE 320000
#define BB 4096

typedef unsigned long long ull;

__device__ __forceinline__ ull ffma2(ull a, ull b, ull c) {
    ull d;
    asm("fma.rn.f32x2 %0, %1, %2, %3;" : "=l"(d) : "l"(a), "l"(b), "l"(c));
    return d;
}
__device__ __forceinline__ ull dup2(float x) {
    ull d;
    asm("mov.b64 %0, {%1, %1};" : "=l"(d) : "f"(x));
    return d;
}
__device__ __forceinline__ float2 unpack2(ull v) {
    float2 r;
    asm("mov.b64 {%0, %1}, %2;" : "=f"(r.x), "=f"(r.y) : "l"(v));
    return r;
}
__device__ __forceinline__ unsigned s2u(const void* p) {
    unsigned a;
    asm("{ .reg .u64 t; cvta.to.shared.u64 t, %1; cvt.u32.u64 %0, t; }" : "=r"(a) : "l"(p));
    return a;
}
__device__ __forceinline__ void cpa4(const void* smem, const void* gmem, int ok) {
    asm volatile("cp.async.ca.shared.global [%0], [%1], 4, %2;"
                 :: "r"(s2u(smem)), "l"(gmem), "r"(ok ? 4 : 0));
}
#define CP_COMMIT() asm volatile("cp.async.commit_group;" ::: "memory")
#define CP_WAIT0()  asm volatile("cp.async.wait_group 0;" ::: "memory")

// ---------------- scratch (device globals) ----------------
__device__ float g_xwi[NN * 128];
__device__ float g_xwj[NN * 128];
__device__ float g_fn [NN * 256];
__device__ float g_agg[NN * 256];
__device__ float g_scores[NE * 4];
__device__ float g_ui0[NN * 64];
__device__ float g_ui1[NN * 64];
__device__ float g_sg0[NN * 64];
__device__ float g_sg1[NN * 64];
__device__ float g_uix[BB * 256];
__device__ float g_sgx[BB * 128];
__device__ float g_hui[BB * 128];
__device__ float g_hsg[BB * 128];
__device__ int   g_deg[NN];
__device__ int   g_off[NN + 1];
__device__ int   g_cur[NN];
__device__ int   g_eid[NE];

// ---------------- CSR build ----------------
__global__ void hist_kernel(const int* __restrict__ dst, int* __restrict__ deg) {
    int e = blockIdx.x * blockDim.x + threadIdx.x;
    if (e < NE) atomicAdd(&deg[dst[e]], 1);
}

__global__ void scan_kernel(const int* __restrict__ deg, int* __restrict__ off, int n) {
    __shared__ int warp_sums[32];
    __shared__ int carry_s;
    const int tid = threadIdx.x;
    const int lane = tid & 31;
    const int wid = tid >> 5;
    if (tid == 0) carry_s = 0;
    __syncthreads();
    for (int base = 0; base < n; base += 1024) {
        int i = base + tid;
        int v = (i < n) ? deg[i] : 0;
        int x = v;
#pragma unroll
        for (int o = 1; o < 32; o <<= 1) {
            int t = __shfl_up_sync(0xffffffffu, x, o);
            if (lane >= o) x += t;
        }
        if (lane == 31) warp_sums[wid] = x;
        __syncthreads();
        if (wid == 0) {
            int s = warp_sums[lane];
#pragma unroll
            for (int o = 1; o < 32; o <<= 1) {
                int t = __shfl_up_sync(0xffffffffu, s, o);
                if (lane >= o) s += t;
            }
            warp_sums[lane] = s;
        }
        __syncthreads();
        int woff = (wid > 0) ? warp_sums[wid - 1] : 0;
        int carry = carry_s;
        if (i < n) off[i] = carry + woff + x - v;
        int total = warp_sums[31];
        __syncthreads();
        if (tid == 0) carry_s = carry + total;
        __syncthreads();
    }
    if (threadIdx.x == 0) off[n] = carry_s;
}

__global__ void fill_kernel(const int* __restrict__ dst, const int* __restrict__ off,
                            int* __restrict__ cur, int* __restrict__ eid) {
    int e = blockIdx.x * blockDim.x + threadIdx.x;
    if (e < NE) {
        int d = dst[e];
        int p = atomicAdd(&cur[d], 1);
        eid[off[d] + p] = e;
    }
}

// ---------------- generic GEMM (f32x2 4x8, warp-uniform B, cp.async dbuf) --------
// BM=128, BN=64; warp w owns cols w*8..w*8+7 (uniform), lanes span 128 rows.
__global__ __launch_bounds__(256, 2) void gemm_act_kernel(
    const float* __restrict__ A, const float* __restrict__ W,
    const float* __restrict__ bias, float* __restrict__ C,
    int M, int N, int K, int act)
{
    __shared__ __align__(16) float sA[2][16][132];
    __shared__ __align__(16) float sB[2][16][64];
    const int bm = blockIdx.x * 128;
    const int bn = blockIdx.y * 64;
    const int tid = threadIdx.x;
    const int lane = tid & 31;
    const int w = tid >> 5;
    const int la_m = tid >> 4, la_k = tid & 15;
    const int lb_k = tid >> 6, lb_n = tid & 63;
    const int nkb = K >> 4;

    ull acc2[2][8];
#pragma unroll
    for (int r = 0; r < 2; r++)
#pragma unroll
        for (int c = 0; c < 8; c++) acc2[r][c] = 0ull;

    auto issue = [&](int kb) {
        int p = kb & 1, k0 = kb << 4;
#pragma unroll
        for (int j = 0; j < 8; j++) {
            int gm = bm + la_m + 16 * j;
            int ok = gm < M;
            cpa4(&sA[p][la_k][la_m + 16 * j],
                 A + (size_t)(ok ? gm : 0) * K + k0 + la_k, ok);
        }
#pragma unroll
        for (int j = 0; j < 4; j++)
            cpa4(&sB[p][lb_k + 4 * j][lb_n],
                 W + (size_t)(k0 + lb_k + 4 * j) * N + bn + lb_n, 1);
        CP_COMMIT();
    };
    issue(0);
    for (int kb = 0; kb < nkb; kb++) {
        CP_WAIT0();
        __syncthreads();
        if (kb + 1 < nkb) issue(kb + 1);
        const int p = kb & 1;
#pragma unroll
        for (int kk = 0; kk < 16; kk++) {
            float4 b0 = *reinterpret_cast<const float4*>(&sB[p][kk][w * 8]);
            float4 b1 = *reinterpret_cast<const float4*>(&sB[p][kk][w * 8 + 4]);
            ull bd[8] = {dup2(b0.x), dup2(b0.y), dup2(b0.z), dup2(b0.w),
                         dup2(b1.x), dup2(b1.y), dup2(b1.z), dup2(b1.w)};
            ulonglong2 a01 = *reinterpret_cast<const ulonglong2*>(&sA[p][kk][lane * 4]);
            ull ap[2] = {a01.x, a01.y};
#pragma unroll
            for (int rp = 0; rp < 2; rp++)
#pragma unroll
                for (int c = 0; c < 8; c++)
                    acc2[rp][c] = ffma2(ap[rp], bd[c], acc2[rp][c]);
        }
    }
#pragma unroll
    for (int rp = 0; rp < 2; rp++) {
        float rowv[2][8];
#pragma unroll
        for (int c = 0; c < 8; c++) {
            float2 u = unpack2(acc2[rp][c]);
            rowv[0][c] = u.x;
            rowv[1][c] = u.y;
        }
#pragma unroll
        for (int l = 0; l < 2; l++) {
            int gm = bm + lane * 4 + rp * 2 + l;
            if (gm >= M) continue;
            float out8[8];
#pragma unroll
            for (int c = 0; c < 8; c++) {
                int gn = bn + w * 8 + c;
                float v = rowv[l][c];
                if (bias) v += bias[gn];
                if (act == 1) v = (v > 0.f) ? v : (expf(v) - 1.f);
                else if (act == 2) v = (v > 0.f) ? v : 0.01f * v;
                else if (act == 3) v = fmaxf(v, 0.f);
                out8[c] = v;
            }
            float4* cp = reinterpret_cast<float4*>(&C[(size_t)gm * N + bn + w * 8]);
            cp[0] = make_float4(out8[0], out8[1], out8[2], out8[3]);
            cp[1] = make_float4(out8[4], out8[5], out8[6], out8[7]);
        }
    }
}

// ---------------- fused node GEMM (f32x2 4x8, warp-uniform B, cp.async dbuf) -----
__global__ __launch_bounds__(256, 2) void node_gemm_kernel(
    const float* __restrict__ A,
    const float* __restrict__ wni, const float* __restrict__ wnj,
    const float* __restrict__ wnode,
    float* __restrict__ xwi, float* __restrict__ xwj, float* __restrict__ fn,
    int M)
{
    __shared__ __align__(16) float sA[2][16][132];
    __shared__ __align__(16) float sB[2][16][64];
    const int by = blockIdx.y;
    const float* W; float* C; int ldW, ldC, coloff;
    if (by < 2)      { W = wni;   C = xwi; ldW = 128; ldC = 128; coloff = by << 6; }
    else if (by < 4) { W = wnj;   C = xwj; ldW = 128; ldC = 128; coloff = (by - 2) << 6; }
    else             { W = wnode; C = fn;  ldW = 256; ldC = 256; coloff = (by - 4) << 6; }

    const int bm = blockIdx.x * 128;
    const int tid = threadIdx.x;
    const int lane = tid & 31;
    const int w = tid >> 5;
    const int la_m = tid >> 4, la_k = tid & 15;
    const int lb_k = tid >> 6, lb_n = tid & 63;

    ull acc2[2][8];
#pragma unroll
    for (int r = 0; r < 2; r++)
#pragma unroll
        for (int c = 0; c < 8; c++) acc2[r][c] = 0ull;

    auto issue = [&](int kb) {
        int p = kb & 1, k0 = kb << 4;
#pragma unroll
        for (int j = 0; j < 8; j++) {
            int gm = bm + la_m + 16 * j;
            int ok = gm < M;
            cpa4(&sA[p][la_k][la_m + 16 * j],
                 A + (size_t)(ok ? gm : 0) * 64 + k0 + la_k, ok);
        }
#pragma unroll
        for (int j = 0; j < 4; j++)
            cpa4(&sB[p][lb_k + 4 * j][lb_n],
                 W + (size_t)(k0 + lb_k + 4 * j) * ldW + coloff + lb_n, 1);
        CP_COMMIT();
    };
    issue(0);
#pragma unroll
    for (int kb = 0; kb < 4; kb++) {
        CP_WAIT0();
        __syncthreads();
        if (kb < 3) issue(kb + 1);
        const int p = kb & 1;
#pragma unroll
        for (int kk = 0; kk < 16; kk++) {
            float4 b0 = *reinterpret_cast<const float4*>(&sB[p][kk][w * 8]);
            float4 b1 = *reinterpret_cast<const float4*>(&sB[p][kk][w * 8 + 4]);
            ull bd[8] = {dup2(b0.x), dup2(b0.y), dup2(b0.z), dup2(b0.w),
                         dup2(b1.x), dup2(b1.y), dup2(b1.z), dup2(b1.w)};
            ulonglong2 a01 = *reinterpret_cast<const ulonglong2*>(&sA[p][kk][lane * 4]);
            ull ap[2] = {a01.x, a01.y};
#pragma unroll
            for (int rp = 0; rp < 2; rp++)
#pragma unroll
                for (int c = 0; c < 8; c++)
                    acc2[rp][c] = ffma2(ap[rp], bd[c], acc2[rp][c]);
        }
    }
#pragma unroll
    for (int rp = 0; rp < 2; rp++) {
        float rowv[2][8];
#pragma unroll
        for (int c = 0; c < 8; c++) {
            float2 u = unpack2(acc2[rp][c]);
            rowv[0][c] = u.x;
            rowv[1][c] = u.y;
        }
#pragma unroll
        for (int l = 0; l < 2; l++) {
            int gm = bm + lane * 4 + rp * 2 + l;
            if (gm >= M) continue;
            float4* cp = reinterpret_cast<float4*>(&C[(size_t)gm * ldC + coloff + w * 8]);
            cp[0] = make_float4(rowv[l][0], rowv[l][1], rowv[l][2], rowv[l][3]);
            cp[1] = make_float4(rowv[l][4], rowv[l][5], rowv[l][6], rowv[l][7]);
        }
    }
}

// ---------------- fused edge GEMM + attention score (f32x2, cp.async dbuf) ----------------
__global__ __launch_bounds__(256, 2) void edge_score_fused_kernel(
    const float* __restrict__ efeat, const float* __restrict__ we,
    const float* __restrict__ attn,
    const int* __restrict__ src, const int* __restrict__ dst,
    const float* __restrict__ xwi, const float* __restrict__ xwj,
    float* __restrict__ scores, int Ke)
{
    __shared__ __align__(16) float sE[2][16][68];
    __shared__ __align__(16) float sW[2][16][128];
    __shared__ float s_attn[128];
    __shared__ int   s_src[64], s_dst[64];

    const int tid = threadIdx.x;
    const int e0 = blockIdx.x * 64;
    const int tx = tid & 15;   // 8 cols each -> 128 cols
    const int ty = tid >> 4;   // 4 edges each -> 64 edges
    const int le_e = tid >> 4, le_k = tid & 15;
    const int lw_k = tid >> 7, lw_c = tid & 127;
    const int nkb = Ke >> 4;

    if (tid < 128) s_attn[tid] = attn[tid];
    if (tid < 64) {
        int ge = e0 + tid;
        s_src[tid] = (ge < NE) ? src[ge] : 0;
        s_dst[tid] = (ge < NE) ? dst[ge] : 0;
    }

    ull acc2[2][8];
#pragma unroll
    for (int r = 0; r < 2; r++)
#pragma unroll
        for (int c = 0; c < 8; c++) acc2[r][c] = 0ull;

    auto issue = [&](int kb) {
        int p = kb & 1, k0 = kb << 4;
#pragma unroll
        for (int j = 0; j < 4; j++) {
            int e = le_e + 16 * j;
            int ge = e0 + e;
            int ok = ge < NE;
            cpa4(&sE[p][le_k][e],
                 efeat + (size_t)(ok ? ge : 0) * Ke + k0 + le_k, ok);
        }
#pragma unroll
        for (int j = 0; j < 8; j++)
            cpa4(&sW[p][lw_k + 2 * j][lw_c],
                 we + (size_t)(k0 + lw_k + 2 * j) * 128 + lw_c, 1);
        CP_COMMIT();
    };
    issue(0);
    for (int kb = 0; kb < nkb; kb++) {
        CP_WAIT0();
        __syncthreads();
        if (kb + 1 < nkb) issue(kb + 1);
        const int p = kb & 1;
#pragma unroll
        for (int kk = 0; kk < 16; kk++) {
            ulonglong2 a01 = *reinterpret_cast<const ulonglong2*>(&sE[p][kk][ty * 4]);
            ull ap[2] = {a01.x, a01.y};
            float4 w0 = *reinterpret_cast<const float4*>(&sW[p][kk][tx * 8]);
            float4 w1 = *reinterpret_cast<const float4*>(&sW[p][kk][tx * 8 + 4]);
            ull bd[8] = {dup2(w0.x), dup2(w0.y), dup2(w0.z), dup2(w0.w),
                         dup2(w1.x), dup2(w1.y), dup2(w1.z), dup2(w1.w)};
#pragma unroll
            for (int rp = 0; rp < 2; rp++)
#pragma unroll
                for (int c = 0; c < 8; c++)
                    acc2[rp][c] = ffma2(ap[rp], bd[c], acc2[rp][c]);
        }
    }

    float accr[4][8];
#pragma unroll
    for (int rp = 0; rp < 2; rp++)
#pragma unroll
        for (int c = 0; c < 8; c++) {
            float2 u = unpack2(acc2[rp][c]);
            accr[rp * 2][c]     = u.x;
            accr[rp * 2 + 1][c] = u.y;
        }

    const int h = tx >> 2;
    float at[8];
#pragma unroll
    for (int c = 0; c < 8; c++) at[c] = s_attn[tx * 8 + c];

#pragma unroll
    for (int r = 0; r < 4; r++) {
        int eg = ty * 4 + r;
        int ge = e0 + eg;
        float p = 0.f;
        if (ge < NE) {
            const float* gi = &xwi[(size_t)s_src[eg] * 128 + tx * 8];
            const float* gj = &xwj[(size_t)s_dst[eg] * 128 + tx * 8];
            float4 gi0 = *reinterpret_cast<const float4*>(gi);
            float4 gi1 = *reinterpret_cast<const float4*>(gi + 4);
            float4 gj0 = *reinterpret_cast<const float4*>(gj);
            float4 gj1 = *reinterpret_cast<const float4*>(gj + 4);
            float f[8];
            f[0] = accr[r][0] + gi0.x + gj0.x;  f[1] = accr[r][1] + gi0.y + gj0.y;
            f[2] = accr[r][2] + gi0.z + gj0.z;  f[3] = accr[r][3] + gi0.w + gj0.w;
            f[4] = accr[r][4] + gi1.x + gj1.x;  f[5] = accr[r][5] + gi1.y + gj1.y;
            f[6] = accr[r][6] + gi1.z + gj1.z;  f[7] = accr[r][7] + gi1.w + gj1.w;
#pragma unroll
            for (int c = 0; c < 8; c++) {
                float v = f[c];
                v = (v > 0.f) ? v : 0.2f * v;
                p += v * at[c];
            }
        }
        p += __shfl_xor_sync(0xffffffffu, p, 1);
        p += __shfl_xor_sync(0xffffffffu, p, 2);
        if ((tx & 3) == 0 && ge < NE)
            scores[(size_t)ge * 4 + h] = p;
    }
}

// ---------------- fused softmax + aggregation, warp per node (smem-staged alpha) ----------------
__global__ __launch_bounds__(256) void attn_agg_kernel(
    const float* __restrict__ scores, const float* __restrict__ mask,
    const int* __restrict__ src, const float* __restrict__ fn,
    const int* __restrict__ off, const int* __restrict__ eid,
    float* __restrict__ outp)
{
    __shared__ __align__(16) float sm_a[8][32][4];
    __shared__ int sm_s[8][32];
    int w = threadIdx.x >> 5;
    int lane = threadIdx.x & 31;
    int n = blockIdx.x * 8 + w;
    if (n >= NN) return;
    int beg = off[n], end = off[n + 1];

    float4 acc0 = make_float4(0.f, 0.f, 0.f, 0.f);
    float4 acc1 = make_float4(0.f, 0.f, 0.f, 0.f);
    const int h = lane >> 3;

    if (beg < end) {
        float4 m = make_float4(-1e30f, -1e30f, -1e30f, -1e30f);
        for (int i = beg + lane; i < end; i += 32) {
            float4 s = *reinterpret_cast<const float4*>(&scores[(size_t)eid[i] * 4]);
            m.x = fmaxf(m.x, s.x); m.y = fmaxf(m.y, s.y);
            m.z = fmaxf(m.z, s.z); m.w = fmaxf(m.w, s.w);
        }
#pragma unroll
        for (int o = 16; o; o >>= 1) {
            m.x = fmaxf(m.x, __shfl_xor_sync(0xffffffffu, m.x, o));
            m.y = fmaxf(m.y, __shfl_xor_sync(0xffffffffu, m.y, o));
            m.z = fmaxf(m.z, __shfl_xor_sync(0xffffffffu, m.z, o));
            m.w = fmaxf(m.w, __shfl_xor_sync(0xffffffffu, m.w, o));
        }
        float4 d = make_float4(0.f, 0.f, 0.f, 0.f);
        for (int i = beg + lane; i < end; i += 32) {
            float4 s = *reinterpret_cast<const float4*>(&scores[(size_t)eid[i] * 4]);
            d.x += __expf(s.x - m.x); d.y += __expf(s.y - m.y);
            d.z += __expf(s.z - m.z); d.w += __expf(s.w - m.w);
        }
#pragma unroll
        for (int o = 16; o; o >>= 1) {
            d.x += __shfl_xor_sync(0xffffffffu, d.x, o);
            d.y += __shfl_xor_sync(0xffffffffu, d.y, o);
            d.z += __shfl_xor_sync(0xffffffffu, d.z, o);
            d.w += __shfl_xor_sync(0xffffffffu, d.w, o);
        }
        float4 inv = make_float4(1.f / (d.x + 1e-9f), 1.f / (d.y + 1e-9f),
                                 1.f / (d.z + 1e-9f), 1.f / (d.w + 1e-9f));

        for (int c0 = beg; c0 < end; c0 += 32) {
            int i = c0 + lane;
            if (i < end) {
                int e = eid[i];
                float4 s = *reinterpret_cast<const float4*>(&scores[(size_t)e * 4]);
                float mk = mask[e];
                float4 a4;
                a4.x = __expf(s.x - m.x) * inv.x * mk;
                a4.y = __expf(s.y - m.y) * inv.y * mk;
                a4.z = __expf(s.z - m.z) * inv.z * mk;
                a4.w = __expf(s.w - m.w) * inv.w * mk;
                *reinterpret_cast<float4*>(&sm_a[w][lane][0]) = a4;
                sm_s[w][lane] = src[e];
            }
            __syncwarp();
            int cl = min(32, end - c0);
            int j = 0;
            for (; j + 1 < cl; j += 2) {
                float a0 = sm_a[w][j][h];
                float a1 = sm_a[w][j + 1][h];
                const float4* f0p = reinterpret_cast<const float4*>(
                    &fn[(size_t)sm_s[w][j] * 256 + lane * 8]);
                const float4* f1p = reinterpret_cast<const float4*>(
                    &fn[(size_t)sm_s[w][j + 1] * 256 + lane * 8]);
                float4 f00 = f0p[0], f01 = f0p[1];
                float4 f10 = f1p[0], f11 = f1p[1];
                acc0.x += a0 * f00.x; acc0.y += a0 * f00.y;
                acc0.z += a0 * f00.z; acc0.w += a0 * f00.w;
                acc1.x += a0 * f01.x; acc1.y += a0 * f01.y;
                acc1.z += a0 * f01.z; acc1.w += a0 * f01.w;
                acc0.x += a1 * f10.x; acc0.y += a1 * f10.y;
                acc0.z += a1 * f10.z; acc0.w += a1 * f10.w;
                acc1.x += a1 * f11.x; acc1.y += a1 * f11.y;
                acc1.z += a1 * f11.z; acc1.w += a1 * f11.w;
            }
            if (j < cl) {
                float a0 = sm_a[w][j][h];
                const float4* fp = reinterpret_cast<const float4*>(
                    &fn[(size_t)sm_s[w][j] * 256 + lane * 8]);
                float4 f0 = fp[0], f1 = fp[1];
                acc0.x += a0 * f0.x; acc0.y += a0 * f0.y;
                acc0.z += a0 * f0.z; acc0.w += a0 * f0.w;
                acc1.x += a0 * f1.x; acc1.y += a0 * f1.y;
                acc1.z += a0 * f1.z; acc1.w += a0 * f1.w;
            }
            __syncwarp();
        }
    }
    float4* op = reinterpret_cast<float4*>(&outp[(size_t)n * 256 + lane * 8]);
    op[0] = acc0;
    op[1] = acc1;
}

// ---------------- readout gather + final outputs ----------------
__global__ void gather_kernel(
    const float* __restrict__ ui0, const float* __restrict__ ui1,
    const float* __restrict__ sg0, const float* __restrict__ sg1,
    const int* __restrict__ user, const int* __restrict__ item,
    const int* __restrict__ subg,
    float* __restrict__ uix, float* __restrict__ sgx)
{
    int b = blockIdx.x;
    int t = threadIdx.x;
    int u = user[b], it = item[b], s = subg[b];
    float v;
    if (t < 64)       v = ui0[(size_t)u * 64 + t];
    else if (t < 128) v = ui1[(size_t)u * 64 + t - 64];
    else if (t < 192) v = ui0[(size_t)it * 64 + t - 128];
    else              v = ui1[(size_t)it * 64 + t - 192];
    uix[(size_t)b * 256 + t] = v;
    if (t < 128) {
        float w = (t < 64) ? sg0[(size_t)s * 64 + t] : sg1[(size_t)s * 64 + t - 64];
        sgx[(size_t)b * 128 + t] = w;
    }
}

__global__ void final_out_kernel(
    const float* __restrict__ hui, const float* __restrict__ hsg,
    const float* __restrict__ w2ui, const float* __restrict__ b2ui,
    const float* __restrict__ w2sg, const float* __restrict__ b2sg,
    float* __restrict__ out)
{
    int r = blockIdx.x * 8 + (threadIdx.x >> 5);
    int lane = threadIdx.x & 31;
    if (r >= BB) return;
    float su = 0.f, ss = 0.f;
#pragma unroll
    for (int k = lane; k < 128; k += 32) {
        su += hui[(size_t)r * 128 + k] * w2ui[k];
        ss += hsg[(size_t)r * 128 + k] * w2sg[k];
    }
#pragma unroll
    for (int o = 16; o; o >>= 1) {
        su += __shfl_xor_sync(0xffffffffu, su, o);
        ss += __shfl_xor_sync(0xffffffffu, ss, o);
    }
    if (lane == 0) {
        out[r]      = 1.f / (1.f + expf(-(ss + b2sg[0])));   // sg_out
        out[BB + r] = 1.f / (1.f + expf(-(su + b2ui[0])));   // ui_out
    }
}

// ---------------- host orchestration ----------------
static void gemm(const float* A, const float* W, const float* bias, float* C,
                 int M, int N, int K, int act) {
    dim3 g((M + 127) / 128, N / 64);
    gemm_act_kernel<<<g, 256>>>(A, W, bias, C, M, N, K, act);
}

extern "C" void kernel_launch(void* const* d_in, const int* in_sizes, int n_in,
                              void* d_out, int out_size) {
    const float* x        = (const float*)d_in[0];
    const float* efeat    = (const float*)d_in[1];
    const float* efeat2   = (const float*)d_in[2];
    const float* mask1    = (const float*)d_in[3];
    const float* mask2    = (const float*)d_in[4];
    const int*   src      = (const int*)d_in[5];
    const int*   dst      = (const int*)d_in[6];
    const int*   user     = (const int*)d_in[7];
    const int*   item     = (const int*)d_in[8];
    const int*   subg     = (const int*)d_in[9];
    const float* loc_wni  = (const float*)d_in[10];
    const float* loc_wnj  = (const float*)d_in[11];
    const float* loc_we   = (const float*)d_in[12];
    const float* loc_attn = (const float*)d_in[13];
    const float* loc_wnode= (const float*)d_in[14];
    const float* agg1_w   = (const float*)d_in[15];
    const float* agg1_b   = (const float*)d_in[16];
    const float* glob_wni = (const float*)d_in[17];
    const float* glob_wnj = (const float*)d_in[18];
    const float* glob_we  = (const float*)d_in[19];
    const float* glob_attn= (const float*)d_in[20];
    const float* glob_wnode=(const float*)d_in[21];
    const float* agg2_w   = (const float*)d_in[22];
    const float* agg2_b   = (const float*)d_in[23];
    const float* w1_ui    = (const float*)d_in[24];
    const float* b1_ui    = (const float*)d_in[25];
    const float* w1_sg    = (const float*)d_in[26];
    const float* b1_sg    = (const float*)d_in[27];
    const float* w2_ui    = (const float*)d_in[28];
    const float* b2_ui    = (const float*)d_in[29];
    const float* w2_sg    = (const float*)d_in[30];
    const float* b2_sg    = (const float*)d_in[31];

    float *p_xwi, *p_xwj, *p_fn, *p_agg, *p_scores;
    float *p_ui0, *p_ui1, *p_sg0, *p_sg1, *p_uix, *p_sgx, *p_hui, *p_hsg;
    int *p_deg, *p_off, *p_cur, *p_eid;
    cudaGetSymbolAddress((void**)&p_xwi, g_xwi);
    cudaGetSymbolAddress((void**)&p_xwj, g_xwj);
    cudaGetSymbolAddress((void**)&p_fn,  g_fn);
    cudaGetSymbolAddress((void**)&p_agg, g_agg);
    cudaGetSymbolAddress((void**)&p_scores, g_scores);
    cudaGetSymbolAddress((void**)&p_ui0, g_ui0);
    cudaGetSymbolAddress((void**)&p_ui1, g_ui1);
    cudaGetSymbolAddress((void**)&p_sg0, g_sg0);
    cudaGetSymbolAddress((void**)&p_sg1, g_sg1);
    cudaGetSymbolAddress((void**)&p_uix, g_uix);
    cudaGetSymbolAddress((void**)&p_sgx, g_sgx);
    cudaGetSymbolAddress((void**)&p_hui, g_hui);
    cudaGetSymbolAddress((void**)&p_hsg, g_hsg);
    cudaGetSymbolAddress((void**)&p_deg, g_deg);
    cudaGetSymbolAddress((void**)&p_off, g_off);
    cudaGetSymbolAddress((void**)&p_cur, g_cur);
    cudaGetSymbolAddress((void**)&p_eid, g_eid);

    // CSR by dst
    cudaMemsetAsync(p_deg, 0, NN * sizeof(int));
    cudaMemsetAsync(p_cur, 0, NN * sizeof(int));
    hist_kernel<<<(NE + 255) / 256, 256>>>(dst, p_deg);
    scan_kernel<<<1, 1024>>>(p_deg, p_off, NN);
    fill_kernel<<<(NE + 255) / 256, 256>>>(dst, p_off, p_cur, p_eid);

    struct Stage {
        const float* hin; const float* ef; int Ke; const float* mask;
        const float* wni; const float* wnj; const float* we; const float* attn;
        const float* wnode; const float* aggw; const float* aggb; int act; float* hout;
    };
    Stage st[4] = {
        { x,     efeat,  16, mask1, loc_wni,           loc_wnj,           loc_we,           loc_attn,         loc_wnode,           agg1_w,          agg1_b,       1, p_ui0 },
        { p_ui0, efeat2, 64, mask2, glob_wni,          glob_wnj,          glob_we,          glob_attn,        glob_wnode,          agg2_w,          agg2_b,       2, p_sg0 },
        { p_sg0, efeat,  16, mask1, loc_wni  + 64*128, loc_wnj  + 64*128, loc_we  + 16*128, loc_attn  + 128,  loc_wnode  + 64*256, agg1_w + 256*64, agg1_b + 64,  1, p_ui1 },
        { p_ui1, efeat2, 64, mask2, glob_wni + 64*128, glob_wnj + 64*128, glob_we + 64*128, glob_attn + 128,  glob_wnode + 64*256, agg2_w + 256*64, agg2_b + 64,  2, p_sg1 },
    };

    for (int s = 0; s < 4; s++) {
        node_gemm_kernel<<<dim3((NN + 127) / 128, 8), 256>>>(
            st[s].hin, st[s].wni, st[s].wnj, st[s].wnode, p_xwi, p_xwj, p_fn, NN);
        edge_score_fused_kernel<<<(NE + 63) / 64, 256>>>(
            st[s].ef, st[s].we, st[s].attn, src, dst, p_xwi, p_xwj, p_scores, st[s].Ke);
        attn_agg_kernel<<<(NN + 7) / 8, 256>>>(p_scores, st[s].mask, src, p_fn, p_off, p_eid, p_agg);
        gemm(p_agg, st[s].aggw, st[s].aggb, st[s].hout, NN, 64, 256, st[s].act);
    }

    gather_kernel<<<BB, 256>>>(p_ui0, p_ui1, p_sg0, p_sg1, user, item, subg, p_uix, p_sgx);
    gemm(p_uix, w1_ui, b1_ui, p_hui, BB, 128, 256, 3);
    gemm(p_sgx, w1_sg, b1_sg, p_hsg, BB, 128, 128, 3);
    final_out_kernel<<<BB / 8, 256>>>(p_hui, p_hsg, w2_ui, b2_ui, w2_sg, b2_sg, (float*)d_out);
}

// round 12
// speedup vs baseline: 1.0471x; 1.0471x over previous
#include <cuda_runtime.h>
#include <math.h>

#define NN 50000
#define NE 320000
#define BB 4096

typedef unsigned long long ull;

__device__ __forceinline__ ull ffma2(ull a, ull b, ull c) {
    ull d;
    asm("fma.rn.f32x2 %0, %1, %2, %3;" : "=l"(d) : "l"(a), "l"(b), "l"(c));
    return d;
}
__device__ __forceinline__ ull dup2(float x) {
    ull d;
    asm("mov.b64 %0, {%1, %1};" : "=l"(d) : "f"(x));
    return d;
}
__device__ __forceinline__ float2 unpack2(ull v) {
    float2 r;
    asm("mov.b64 {%0, %1}, %2;" : "=f"(r.x), "=f"(r.y) : "l"(v));
    return r;
}
__device__ __forceinline__ unsigned s2u(const void* p) {
    unsigned a;
    asm("{ .reg .u64 t; cvta.to.shared.u64 t, %1; cvt.u32.u64 %0, t; }" : "=r"(a) : "l"(p));
    return a;
}
__device__ __forceinline__ void cpa4(const void* smem, const void* gmem, int ok) {
    asm volatile("cp.async.ca.shared.global [%0], [%1], 4, %2;"
                 :: "r"(s2u(smem)), "l"(gmem), "r"(ok ? 4 : 0));
}
#define CP_COMMIT() asm volatile("cp.async.commit_group;" ::: "memory")
#define CP_WAIT0()  asm volatile("cp.async.wait_group 0;" ::: "memory")

// ---------------- scratch (device globals) ----------------
__device__ float g_xwi[NN * 128];
__device__ float g_xwj[NN * 128];
__device__ float g_fn [NN * 256];
__device__ float g_agg[NN * 256];
__device__ float g_scores[NE * 4];
__device__ float g_ui0[NN * 64];
__device__ float g_ui1[NN * 64];
__device__ float g_sg0[NN * 64];
__device__ float g_sg1[NN * 64];
__device__ float g_uix[BB * 256];
__device__ float g_sgx[BB * 128];
__device__ float g_hui[BB * 128];
__device__ float g_hsg[BB * 128];
__device__ int   g_deg[NN];
__device__ int   g_off[NN + 1];
__device__ int   g_cur[NN];
__device__ int   g_eid[NE];

// ---------------- CSR build ----------------
__global__ void hist_kernel(const int* __restrict__ dst, int* __restrict__ deg) {
    int e = blockIdx.x * blockDim.x + threadIdx.x;
    if (e < NE) atomicAdd(&deg[dst[e]], 1);
}

__global__ void scan_kernel(const int* __restrict__ deg, int* __restrict__ off, int n) {
    __shared__ int warp_sums[32];
    __shared__ int carry_s;
    const int tid = threadIdx.x;
    const int lane = tid & 31;
    const int wid = tid >> 5;
    if (tid == 0) carry_s = 0;
    __syncthreads();
    for (int base = 0; base < n; base += 1024) {
        int i = base + tid;
        int v = (i < n) ? deg[i] : 0;
        int x = v;
#pragma unroll
        for (int o = 1; o < 32; o <<= 1) {
            int t = __shfl_up_sync(0xffffffffu, x, o);
            if (lane >= o) x += t;
        }
        if (lane == 31) warp_sums[wid] = x;
        __syncthreads();
        if (wid == 0) {
            int s = warp_sums[lane];
#pragma unroll
            for (int o = 1; o < 32; o <<= 1) {
                int t = __shfl_up_sync(0xffffffffu, s, o);
                if (lane >= o) s += t;
            }
            warp_sums[lane] = s;
        }
        __syncthreads();
        int woff = (wid > 0) ? warp_sums[wid - 1] : 0;
        int carry = carry_s;
        if (i < n) off[i] = carry + woff + x - v;
        int total = warp_sums[31];
        __syncthreads();
        if (tid == 0) carry_s = carry + total;
        __syncthreads();
    }
    if (threadIdx.x == 0) off[n] = carry_s;
}

__global__ void fill_kernel(const int* __restrict__ dst, const int* __restrict__ off,
                            int* __restrict__ cur, int* __restrict__ eid) {
    int e = blockIdx.x * blockDim.x + threadIdx.x;
    if (e < NE) {
        int d = dst[e];
        int p = atomicAdd(&cur[d], 1);
        eid[off[d] + p] = e;
    }
}

// ---------------- generic GEMM (f32x2 8x4, cp.async dbuf, occ=3) ----------------
__global__ __launch_bounds__(256, 3) void gemm_act_kernel(
    const float* __restrict__ A, const float* __restrict__ W,
    const float* __restrict__ bias, float* __restrict__ C,
    int M, int N, int K, int act)
{
    __shared__ __align__(16) float sA[2][16][132];
    __shared__ __align__(16) float sB[2][16][64];
    const int bm = blockIdx.x * 128;
    const int bn = blockIdx.y * 64;
    const int tid = threadIdx.x;
    const int tx = tid & 15;
    const int ty = tid >> 4;
    const int la_m = tid >> 4, la_k = tid & 15;
    const int lb_k = tid >> 6, lb_n = tid & 63;
    const int nkb = K >> 4;

    ull acc2[4][4];
#pragma unroll
    for (int r = 0; r < 4; r++)
#pragma unroll
        for (int c = 0; c < 4; c++) acc2[r][c] = 0ull;

    auto issue = [&](int kb) {
        int p = kb & 1, k0 = kb << 4;
#pragma unroll
        for (int j = 0; j < 8; j++) {
            int gm = bm + la_m + 16 * j;
            int ok = gm < M;
            cpa4(&sA[p][la_k][la_m + 16 * j],
                 A + (size_t)(ok ? gm : 0) * K + k0 + la_k, ok);
        }
#pragma unroll
        for (int j = 0; j < 4; j++)
            cpa4(&sB[p][lb_k + 4 * j][lb_n],
                 W + (size_t)(k0 + lb_k + 4 * j) * N + bn + lb_n, 1);
        CP_COMMIT();
    };
    issue(0);
    for (int kb = 0; kb < nkb; kb++) {
        CP_WAIT0();
        __syncthreads();
        if (kb + 1 < nkb) issue(kb + 1);
        const int p = kb & 1;
#pragma unroll
        for (int kk = 0; kk < 16; kk++) {
            float4 b4 = *reinterpret_cast<const float4*>(&sB[p][kk][tx * 4]);
            ull bd[4] = {dup2(b4.x), dup2(b4.y), dup2(b4.z), dup2(b4.w)};
            ulonglong2 a01 = *reinterpret_cast<const ulonglong2*>(&sA[p][kk][ty * 8]);
            ulonglong2 a23 = *reinterpret_cast<const ulonglong2*>(&sA[p][kk][ty * 8 + 4]);
            ull ap[4] = {a01.x, a01.y, a23.x, a23.y};
#pragma unroll
            for (int rp = 0; rp < 4; rp++)
#pragma unroll
                for (int c = 0; c < 4; c++)
                    acc2[rp][c] = ffma2(ap[rp], bd[c], acc2[rp][c]);
        }
    }
#pragma unroll
    for (int rp = 0; rp < 4; rp++) {
        float2 u0 = unpack2(acc2[rp][0]);
        float2 u1 = unpack2(acc2[rp][1]);
        float2 u2 = unpack2(acc2[rp][2]);
        float2 u3 = unpack2(acc2[rp][3]);
        float rowv[2][4] = {{u0.x, u1.x, u2.x, u3.x}, {u0.y, u1.y, u2.y, u3.y}};
#pragma unroll
        for (int l = 0; l < 2; l++) {
            int gm = bm + ty * 8 + rp * 2 + l;
            if (gm >= M) continue;
            float4 v4;
            float* vp = &v4.x;
#pragma unroll
            for (int c = 0; c < 4; c++) {
                int gn = bn + tx * 4 + c;
                float v = rowv[l][c];
                if (bias) v += bias[gn];
                if (act == 1) v = (v > 0.f) ? v : (expf(v) - 1.f);
                else if (act == 2) v = (v > 0.f) ? v : 0.01f * v;
                else if (act == 3) v = fmaxf(v, 0.f);
                vp[c] = v;
            }
            *reinterpret_cast<float4*>(&C[(size_t)gm * N + bn + tx * 4]) = v4;
        }
    }
}

// ---------------- fused node GEMM (f32x2 8x4, cp.async dbuf, occ=3) ----------------
__global__ __launch_bounds__(256, 3) void node_gemm_kernel(
    const float* __restrict__ A,
    const float* __restrict__ wni, const float* __restrict__ wnj,
    const float* __restrict__ wnode,
    float* __restrict__ xwi, float* __restrict__ xwj, float* __restrict__ fn,
    int M)
{
    __shared__ __align__(16) float sA[2][16][132];
    __shared__ __align__(16) float sB[2][16][64];
    const int by = blockIdx.y;
    const float* W; float* C; int ldW, ldC, coloff;
    if (by < 2)      { W = wni;   C = xwi; ldW = 128; ldC = 128; coloff = by << 6; }
    else if (by < 4) { W = wnj;   C = xwj; ldW = 128; ldC = 128; coloff = (by - 2) << 6; }
    else             { W = wnode; C = fn;  ldW = 256; ldC = 256; coloff = (by - 4) << 6; }

    const int bm = blockIdx.x * 128;
    const int tid = threadIdx.x;
    const int tx = tid & 15;
    const int ty = tid >> 4;
    const int la_m = tid >> 4, la_k = tid & 15;
    const int lb_k = tid >> 6, lb_n = tid & 63;

    ull acc2[4][4];
#pragma unroll
    for (int r = 0; r < 4; r++)
#pragma unroll
        for (int c = 0; c < 4; c++) acc2[r][c] = 0ull;

    auto issue = [&](int kb) {
        int p = kb & 1, k0 = kb << 4;
#pragma unroll
        for (int j = 0; j < 8; j++) {
            int gm = bm + la_m + 16 * j;
            int ok = gm < M;
            cpa4(&sA[p][la_k][la_m + 16 * j],
                 A + (size_t)(ok ? gm : 0) * 64 + k0 + la_k, ok);
        }
#pragma unroll
        for (int j = 0; j < 4; j++)
            cpa4(&sB[p][lb_k + 4 * j][lb_n],
                 W + (size_t)(k0 + lb_k + 4 * j) * ldW + coloff + lb_n, 1);
        CP_COMMIT();
    };
    issue(0);
#pragma unroll
    for (int kb = 0; kb < 4; kb++) {
        CP_WAIT0();
        __syncthreads();
        if (kb < 3) issue(kb + 1);
        const int p = kb & 1;
#pragma unroll
        for (int kk = 0; kk < 16; kk++) {
            float4 b4 = *reinterpret_cast<const float4*>(&sB[p][kk][tx * 4]);
            ull bd[4] = {dup2(b4.x), dup2(b4.y), dup2(b4.z), dup2(b4.w)};
            ulonglong2 a01 = *reinterpret_cast<const ulonglong2*>(&sA[p][kk][ty * 8]);
            ulonglong2 a23 = *reinterpret_cast<const ulonglong2*>(&sA[p][kk][ty * 8 + 4]);
            ull ap[4] = {a01.x, a01.y, a23.x, a23.y};
#pragma unroll
            for (int rp = 0; rp < 4; rp++)
#pragma unroll
                for (int c = 0; c < 4; c++)
                    acc2[rp][c] = ffma2(ap[rp], bd[c], acc2[rp][c]);
        }
    }
#pragma unroll
    for (int rp = 0; rp < 4; rp++) {
        float2 u0 = unpack2(acc2[rp][0]);
        float2 u1 = unpack2(acc2[rp][1]);
        float2 u2 = unpack2(acc2[rp][2]);
        float2 u3 = unpack2(acc2[rp][3]);
        int gm0 = bm + ty * 8 + rp * 2;
        if (gm0 < M) {
            float4 v4 = make_float4(u0.x, u1.x, u2.x, u3.x);
            *reinterpret_cast<float4*>(&C[(size_t)gm0 * ldC + coloff + tx * 4]) = v4;
        }
        if (gm0 + 1 < M) {
            float4 v4 = make_float4(u0.y, u1.y, u2.y, u3.y);
            *reinterpret_cast<float4*>(&C[(size_t)(gm0 + 1) * ldC + coloff + tx * 4]) = v4;
        }
    }
}

// ---------------- fused edge GEMM + attention score (f32x2, cp.async dbuf) ----------------
__global__ __launch_bounds__(256, 2) void edge_score_fused_kernel(
    const float* __restrict__ efeat, const float* __restrict__ we,
    const float* __restrict__ attn,
    const int* __restrict__ src, const int* __restrict__ dst,
    const float* __restrict__ xwi, const float* __restrict__ xwj,
    float* __restrict__ scores, int Ke)
{
    __shared__ __align__(16) float sE[2][16][68];
    __shared__ __align__(16) float sW[2][16][128];
    __shared__ float s_attn[128];
    __shared__ int   s_src[64], s_dst[64];

    const int tid = threadIdx.x;
    const int e0 = blockIdx.x * 64;
    const int tx = tid & 15;   // 8 cols each -> 128 cols
    const int ty = tid >> 4;   // 4 edges each -> 64 edges
    const int le_e = tid >> 4, le_k = tid & 15;
    const int lw_k = tid >> 7, lw_c = tid & 127;
    const int nkb = Ke >> 4;

    if (tid < 128) s_attn[tid] = attn[tid];
    if (tid < 64) {
        int ge = e0 + tid;
        s_src[tid] = (ge < NE) ? src[ge] : 0;
        s_dst[tid] = (ge < NE) ? dst[ge] : 0;
    }

    ull acc2[2][8];
#pragma unroll
    for (int r = 0; r < 2; r++)
#pragma unroll
        for (int c = 0; c < 8; c++) acc2[r][c] = 0ull;

    auto issue = [&](int kb) {
        int p = kb & 1, k0 = kb << 4;
#pragma unroll
        for (int j = 0; j < 4; j++) {
            int e = le_e + 16 * j;
            int ge = e0 + e;
            int ok = ge < NE;
            cpa4(&sE[p][le_k][e],
                 efeat + (size_t)(ok ? ge : 0) * Ke + k0 + le_k, ok);
        }
#pragma unroll
        for (int j = 0; j < 8; j++)
            cpa4(&sW[p][lw_k + 2 * j][lw_c],
                 we + (size_t)(k0 + lw_k + 2 * j) * 128 + lw_c, 1);
        CP_COMMIT();
    };
    issue(0);
    for (int kb = 0; kb < nkb; kb++) {
        CP_WAIT0();
        __syncthreads();
        if (kb + 1 < nkb) issue(kb + 1);
        const int p = kb & 1;
#pragma unroll
        for (int kk = 0; kk < 16; kk++) {
            ulonglong2 a01 = *reinterpret_cast<const ulonglong2*>(&sE[p][kk][ty * 4]);
            ull ap[2] = {a01.x, a01.y};
            float4 w0 = *reinterpret_cast<const float4*>(&sW[p][kk][tx * 8]);
            float4 w1 = *reinterpret_cast<const float4*>(&sW[p][kk][tx * 8 + 4]);
            ull bd[8] = {dup2(w0.x), dup2(w0.y), dup2(w0.z), dup2(w0.w),
                         dup2(w1.x), dup2(w1.y), dup2(w1.z), dup2(w1.w)};
#pragma unroll
            for (int rp = 0; rp < 2; rp++)
#pragma unroll
                for (int c = 0; c < 8; c++)
                    acc2[rp][c] = ffma2(ap[rp], bd[c], acc2[rp][c]);
        }
    }

    float accr[4][8];
#pragma unroll
    for (int rp = 0; rp < 2; rp++)
#pragma unroll
        for (int c = 0; c < 8; c++) {
            float2 u = unpack2(acc2[rp][c]);
            accr[rp * 2][c]     = u.x;
            accr[rp * 2 + 1][c] = u.y;
        }

    const int h = tx >> 2;
    float at[8];
#pragma unroll
    for (int c = 0; c < 8; c++) at[c] = s_attn[tx * 8 + c];

#pragma unroll
    for (int r = 0; r < 4; r++) {
        int eg = ty * 4 + r;
        int ge = e0 + eg;
        float p = 0.f;
        if (ge < NE) {
            const float* gi = &xwi[(size_t)s_src[eg] * 128 + tx * 8];
            const float* gj = &xwj[(size_t)s_dst[eg] * 128 + tx * 8];
            float4 gi0 = *reinterpret_cast<const float4*>(gi);
            float4 gi1 = *reinterpret_cast<const float4*>(gi + 4);
            float4 gj0 = *reinterpret_cast<const float4*>(gj);
            float4 gj1 = *reinterpret_cast<const float4*>(gj + 4);
            float f[8];
            f[0] = accr[r][0] + gi0.x + gj0.x;  f[1] = accr[r][1] + gi0.y + gj0.y;
            f[2] = accr[r][2] + gi0.z + gj0.z;  f[3] = accr[r][3] + gi0.w + gj0.w;
            f[4] = accr[r][4] + gi1.x + gj1.x;  f[5] = accr[r][5] + gi1.y + gj1.y;
            f[6] = accr[r][6] + gi1.z + gj1.z;  f[7] = accr[r][7] + gi1.w + gj1.w;
#pragma unroll
            for (int c = 0; c < 8; c++) {
                float v = f[c];
                v = (v > 0.f) ? v : 0.2f * v;
                p += v * at[c];
            }
        }
        p += __shfl_xor_sync(0xffffffffu, p, 1);
        p += __shfl_xor_sync(0xffffffffu, p, 2);
        if ((tx & 3) == 0 && ge < NE)
            scores[(size_t)ge * 4 + h] = p;
    }
}

// ---------------- fused softmax + aggregation, warp per node (smem-staged alpha) ----------------
__global__ __launch_bounds__(256) void attn_agg_kernel(
    const float* __restrict__ scores, const float* __restrict__ mask,
    const int* __restrict__ src, const float* __restrict__ fn,
    const int* __restrict__ off, const int* __restrict__ eid,
    float* __restrict__ outp)
{
    __shared__ __align__(16) float sm_a[8][32][4];
    __shared__ int sm_s[8][32];
    int w = threadIdx.x >> 5;
    int lane = threadIdx.x & 31;
    int n = blockIdx.x * 8 + w;
    if (n >= NN) return;
    int beg = off[n], end = off[n + 1];

    float4 acc0 = make_float4(0.f, 0.f, 0.f, 0.f);
    float4 acc1 = make_float4(0.f, 0.f, 0.f, 0.f);
    const int h = lane >> 3;

    if (beg < end) {
        float4 m = make_float4(-1e30f, -1e30f, -1e30f, -1e30f);
        for (int i = beg + lane; i < end; i += 32) {
            float4 s = *reinterpret_cast<const float4*>(&scores[(size_t)eid[i] * 4]);
            m.x = fmaxf(m.x, s.x); m.y = fmaxf(m.y, s.y);
            m.z = fmaxf(m.z, s.z); m.w = fmaxf(m.w, s.w);
        }
#pragma unroll
        for (int o = 16; o; o >>= 1) {
            m.x = fmaxf(m.x, __shfl_xor_sync(0xffffffffu, m.x, o));
            m.y = fmaxf(m.y, __shfl_xor_sync(0xffffffffu, m.y, o));
            m.z = fmaxf(m.z, __shfl_xor_sync(0xffffffffu, m.z, o));
            m.w = fmaxf(m.w, __shfl_xor_sync(0xffffffffu, m.w, o));
        }
        float4 d = make_float4(0.f, 0.f, 0.f, 0.f);
        for (int i = beg + lane; i < end; i += 32) {
            float4 s = *reinterpret_cast<const float4*>(&scores[(size_t)eid[i] * 4]);
            d.x += __expf(s.x - m.x); d.y += __expf(s.y - m.y);
            d.z += __expf(s.z - m.z); d.w += __expf(s.w - m.w);
        }
#pragma unroll
        for (int o = 16; o; o >>= 1) {
            d.x += __shfl_xor_sync(0xffffffffu, d.x, o);
            d.y += __shfl_xor_sync(0xffffffffu, d.y, o);
            d.z += __shfl_xor_sync(0xffffffffu, d.z, o);
            d.w += __shfl_xor_sync(0xffffffffu, d.w, o);
        }
        float4 inv = make_float4(1.f / (d.x + 1e-9f), 1.f / (d.y + 1e-9f),
                                 1.f / (d.z + 1e-9f), 1.f / (d.w + 1e-9f));

        for (int c0 = beg; c0 < end; c0 += 32) {
            int i = c0 + lane;
            if (i < end) {
                int e = eid[i];
                float4 s = *reinterpret_cast<const float4*>(&scores[(size_t)e * 4]);
                float mk = mask[e];
                float4 a4;
                a4.x = __expf(s.x - m.x) * inv.x * mk;
                a4.y = __expf(s.y - m.y) * inv.y * mk;
                a4.z = __expf(s.z - m.z) * inv.z * mk;
                a4.w = __expf(s.w - m.w) * inv.w * mk;
                *reinterpret_cast<float4*>(&sm_a[w][lane][0]) = a4;
                sm_s[w][lane] = src[e];
            }
            __syncwarp();
            int cl = min(32, end - c0);
            int j = 0;
            for (; j + 1 < cl; j += 2) {
                float a0 = sm_a[w][j][h];
                float a1 = sm_a[w][j + 1][h];
                const float4* f0p = reinterpret_cast<const float4*>(
                    &fn[(size_t)sm_s[w][j] * 256 + lane * 8]);
                const float4* f1p = reinterpret_cast<const float4*>(
                    &fn[(size_t)sm_s[w][j + 1] * 256 + lane * 8]);
                float4 f00 = f0p[0], f01 = f0p[1];
                float4 f10 = f1p[0], f11 = f1p[1];
                acc0.x += a0 * f00.x; acc0.y += a0 * f00.y;
                acc0.z += a0 * f00.z; acc0.w += a0 * f00.w;
                acc1.x += a0 * f01.x; acc1.y += a0 * f01.y;
                acc1.z += a0 * f01.z; acc1.w += a0 * f01.w;
                acc0.x += a1 * f10.x; acc0.y += a1 * f10.y;
                acc0.z += a1 * f10.z; acc0.w += a1 * f10.w;
                acc1.x += a1 * f11.x; acc1.y += a1 * f11.y;
                acc1.z += a1 * f11.z; acc1.w += a1 * f11.w;
            }
            if (j < cl) {
                float a0 = sm_a[w][j][h];
                const float4* fp = reinterpret_cast<const float4*>(
                    &fn[(size_t)sm_s[w][j] * 256 + lane * 8]);
                float4 f0 = fp[0], f1 = fp[1];
                acc0.x += a0 * f0.x; acc0.y += a0 * f0.y;
                acc0.z += a0 * f0.z; acc0.w += a0 * f0.w;
                acc1.x += a0 * f1.x; acc1.y += a0 * f1.y;
                acc1.z += a0 * f1.z; acc1.w += a0 * f1.w;
            }
            __syncwarp();
        }
    }
    float4* op = reinterpret_cast<float4*>(&outp[(size_t)n * 256 + lane * 8]);
    op[0] = acc0;
    op[1] = acc1;
}

// ---------------- readout gather + final outputs ----------------
__global__ void gather_kernel(
    const float* __restrict__ ui0, const float* __restrict__ ui1,
    const float* __restrict__ sg0, const float* __restrict__ sg1,
    const int* __restrict__ user, const int* __restrict__ item,
    const int* __restrict__ subg,
    float* __restrict__ uix, float* __restrict__ sgx)
{
    int b = blockIdx.x;
    int t = threadIdx.x;
    int u = user[b], it = item[b], s = subg[b];
    float v;
    if (t < 64)       v = ui0[(size_t)u * 64 + t];
    else if (t < 128) v = ui1[(size_t)u * 64 + t - 64];
    else if (t < 192) v = ui0[(size_t)it * 64 + t - 128];
    else              v = ui1[(size_t)it * 64 + t - 192];
    uix[(size_t)b * 256 + t] = v;
    if (t < 128) {
        float w = (t < 64) ? sg0[(size_t)s * 64 + t] : sg1[(size_t)s * 64 + t - 64];
        sgx[(size_t)b * 128 + t] = w;
    }
}

__global__ void final_out_kernel(
    const float* __restrict__ hui, const float* __restrict__ hsg,
    const float* __restrict__ w2ui, const float* __restrict__ b2ui,
    const float* __restrict__ w2sg, const float* __restrict__ b2sg,
    float* __restrict__ out)
{
    int r = blockIdx.x * 8 + (threadIdx.x >> 5);
    int lane = threadIdx.x & 31;
    if (r >= BB) return;
    float su = 0.f, ss = 0.f;
#pragma unroll
    for (int k = lane; k < 128; k += 32) {
        su += hui[(size_t)r * 128 + k] * w2ui[k];
        ss += hsg[(size_t)r * 128 + k] * w2sg[k];
    }
#pragma unroll
    for (int o = 16; o; o >>= 1) {
        su += __shfl_xor_sync(0xffffffffu, su, o);
        ss += __shfl_xor_sync(0xffffffffu, ss, o);
    }
    if (lane == 0) {
        out[r]      = 1.f / (1.f + expf(-(ss + b2sg[0])));   // sg_out
        out[BB + r] = 1.f / (1.f + expf(-(su + b2ui[0])));   // ui_out
    }
}

// ---------------- host orchestration ----------------
static void gemm(const float* A, const float* W, const float* bias, float* C,
                 int M, int N, int K, int act) {
    dim3 g((M + 127) / 128, N / 64);
    gemm_act_kernel<<<g, 256>>>(A, W, bias, C, M, N, K, act);
}

extern "C" void kernel_launch(void* const* d_in, const int* in_sizes, int n_in,
                              void* d_out, int out_size) {
    const float* x        = (const float*)d_in[0];
    const float* efeat    = (const float*)d_in[1];
    const float* efeat2   = (const float*)d_in[2];
    const float* mask1    = (const float*)d_in[3];
    const float* mask2    = (const float*)d_in[4];
    const int*   src      = (const int*)d_in[5];
    const int*   dst      = (const int*)d_in[6];
    const int*   user     = (const int*)d_in[7];
    const int*   item     = (const int*)d_in[8];
    const int*   subg     = (const int*)d_in[9];
    const float* loc_wni  = (const float*)d_in[10];
    const float* loc_wnj  = (const float*)d_in[11];
    const float* loc_we   = (const float*)d_in[12];
    const float* loc_attn = (const float*)d_in[13];
    const float* loc_wnode= (const float*)d_in[14];
    const float* agg1_w   = (const float*)d_in[15];
    const float* agg1_b   = (const float*)d_in[16];
    const float* glob_wni = (const float*)d_in[17];
    const float* glob_wnj = (const float*)d_in[18];
    const float* glob_we  = (const float*)d_in[19];
    const float* glob_attn= (const float*)d_in[20];
    const float* glob_wnode=(const float*)d_in[21];
    const float* agg2_w   = (const float*)d_in[22];
    const float* agg2_b   = (const float*)d_in[23];
    const float* w1_ui    = (const float*)d_in[24];
    const float* b1_ui    = (const float*)d_in[25];
    const float* w1_sg    = (const float*)d_in[26];
    const float* b1_sg    = (const float*)d_in[27];
    const float* w2_ui    = (const float*)d_in[28];
    const float* b2_ui    = (const float*)d_in[29];
    const float* w2_sg    = (const float*)d_in[30];
    const float* b2_sg    = (const float*)d_in[31];

    float *p_xwi, *p_xwj, *p_fn, *p_agg, *p_scores;
    float *p_ui0, *p_ui1, *p_sg0, *p_sg1, *p_uix, *p_sgx, *p_hui, *p_hsg;
    int *p_deg, *p_off, *p_cur, *p_eid;
    cudaGetSymbolAddress((void**)&p_xwi, g_xwi);
    cudaGetSymbolAddress((void**)&p_xwj, g_xwj);
    cudaGetSymbolAddress((void**)&p_fn,  g_fn);
    cudaGetSymbolAddress((void**)&p_agg, g_agg);
    cudaGetSymbolAddress((void**)&p_scores, g_scores);
    cudaGetSymbolAddress((void**)&p_ui0, g_ui0);
    cudaGetSymbolAddress((void**)&p_ui1, g_ui1);
    cudaGetSymbolAddress((void**)&p_sg0, g_sg0);
    cudaGetSymbolAddress((void**)&p_sg1, g_sg1);
    cudaGetSymbolAddress((void**)&p_uix, g_uix);
    cudaGetSymbolAddress((void**)&p_sgx, g_sgx);
    cudaGetSymbolAddress((void**)&p_hui, g_hui);
    cudaGetSymbolAddress((void**)&p_hsg, g_hsg);
    cudaGetSymbolAddress((void**)&p_deg, g_deg);
    cudaGetSymbolAddress((void**)&p_off, g_off);
    cudaGetSymbolAddress((void**)&p_cur, g_cur);
    cudaGetSymbolAddress((void**)&p_eid, g_eid);

    // CSR by dst
    cudaMemsetAsync(p_deg, 0, NN * sizeof(int));
    cudaMemsetAsync(p_cur, 0, NN * sizeof(int));
    hist_kernel<<<(NE + 255) / 256, 256>>>(dst, p_deg);
    scan_kernel<<<1, 1024>>>(p_deg, p_off, NN);
    fill_kernel<<<(NE + 255) / 256, 256>>>(dst, p_off, p_cur, p_eid);

    struct Stage {
        const float* hin; const float* ef; int Ke; const float* mask;
        const float* wni; const float* wnj; const float* we; const float* attn;
        const float* wnode; const float* aggw; const float* aggb; int act; float* hout;
    };
    Stage st[4] = {
        { x,     efeat,  16, mask1, loc_wni,           loc_wnj,           loc_we,           loc_attn,         loc_wnode,           agg1_w,          agg1_b,       1, p_ui0 },
        { p_ui0, efeat2, 64, mask2, glob_wni,          glob_wnj,          glob_we,          glob_attn,        glob_wnode,          agg2_w,          agg2_b,       2, p_sg0 },
        { p_sg0, efeat,  16, mask1, loc_wni  + 64*128, loc_wnj  + 64*128, loc_we  + 16*128, loc_attn  + 128,  loc_wnode  + 64*256, agg1_w + 256*64, agg1_b + 64,  1, p_ui1 },
        { p_ui1, efeat2, 64, mask2, glob_wni + 64*128, glob_wnj + 64*128, glob_we + 64*128, glob_attn + 128,  glob_wnode + 64*256, agg2_w + 256*64, agg2_b + 64,  2, p_sg1 },
    };

    for (int s = 0; s < 4; s++) {
        node_gemm_kernel<<<dim3((NN + 127) / 128, 8), 256>>>(
            st[s].hin, st[s].wni, st[s].wnj, st[s].wnode, p_xwi, p_xwj, p_fn, NN);
        edge_score_fused_kernel<<<(NE + 63) / 64, 256>>>(
            st[s].ef, st[s].we, st[s].attn, src, dst, p_xwi, p_xwj, p_scores, st[s].Ke);
        attn_agg_kernel<<<(NN + 7) / 8, 256>>>(p_scores, st[s].mask, src, p_fn, p_off, p_eid, p_agg);
        gemm(p_agg, st[s].aggw, st[s].aggb, st[s].hout, NN, 64, 256, st[s].act);
    }

    gather_kernel<<<BB, 256>>>(p_ui0, p_ui1, p_sg0, p_sg1, user, item, subg, p_uix, p_sgx);
    gemm(p_uix, w1_ui, b1_ui, p_hui, BB, 128, 256, 3);
    gemm(p_sgx, w1_sg, b1_sg, p_hsg, BB, 128, 128, 3);
    final_out_kernel<<<BB / 8, 256>>>(p_hui, p_hsg, w2_ui, b2_ui, w2_sg, b2_sg, (float*)d_out);
}

// round 13
// speedup vs baseline: 1.1712x; 1.1185x over previous
#include <cuda_runtime.h>
#include <math.h>

#define NN 50000
#define NE 320000
#define BB 4096

typedef unsigned long long ull;

__device__ __forceinline__ ull ffma2(ull a, ull b, ull c) {
    ull d;
    asm("fma.rn.f32x2 %0, %1, %2, %3;" : "=l"(d) : "l"(a), "l"(b), "l"(c));
    return d;
}
__device__ __forceinline__ ull dup2(float x) {
    ull d;
    asm("mov.b64 %0, {%1, %1};" : "=l"(d) : "f"(x));
    return d;
}
__device__ __forceinline__ float2 unpack2(ull v) {
    float2 r;
    asm("mov.b64 {%0, %1}, %2;" : "=f"(r.x), "=f"(r.y) : "l"(v));
    return r;
}
__device__ __forceinline__ unsigned s2u(const void* p) {
    unsigned a;
    asm("{ .reg .u64 t; cvta.to.shared.u64 t, %1; cvt.u32.u64 %0, t; }" : "=r"(a) : "l"(p));
    return a;
}
__device__ __forceinline__ void cpa4(const void* smem, const void* gmem, int ok) {
    asm volatile("cp.async.ca.shared.global [%0], [%1], 4, %2;"
                 :: "r"(s2u(smem)), "l"(gmem), "r"(ok ? 4 : 0));
}
#define CP_COMMIT() asm volatile("cp.async.commit_group;" ::: "memory")
#define CP_WAIT0()  asm volatile("cp.async.wait_group 0;" ::: "memory")

// ---------------- scratch (device globals) ----------------
__device__ float g_xwi[NN * 128];
__device__ float g_xwj[NN * 128];
__device__ float g_fn [NN * 256];
__device__ float g_agg[NN * 256];
__device__ float g_scores[NE * 4];
__device__ float g_ui0[NN * 64];
__device__ float g_ui1[NN * 64];
__device__ float g_sg0[NN * 64];
__device__ float g_sg1[NN * 64];
__device__ float g_uix[BB * 256];
__device__ float g_sgx[BB * 128];
__device__ float g_hui[BB * 128];
__device__ float g_hsg[BB * 128];
__device__ int   g_deg[NN];
__device__ int   g_off[NN + 1];
__device__ int   g_cur[NN];
__device__ int   g_eid[NE];

// ---------------- CSR build ----------------
__global__ void hist_kernel(const int* __restrict__ dst, int* __restrict__ deg) {
    int e = blockIdx.x * blockDim.x + threadIdx.x;
    if (e < NE) atomicAdd(&deg[dst[e]], 1);
}

__global__ void scan_kernel(const int* __restrict__ deg, int* __restrict__ off, int n) {
    __shared__ int warp_sums[32];
    __shared__ int carry_s;
    const int tid = threadIdx.x;
    const int lane = tid & 31;
    const int wid = tid >> 5;
    if (tid == 0) carry_s = 0;
    __syncthreads();
    for (int base = 0; base < n; base += 1024) {
        int i = base + tid;
        int v = (i < n) ? deg[i] : 0;
        int x = v;
#pragma unroll
        for (int o = 1; o < 32; o <<= 1) {
            int t = __shfl_up_sync(0xffffffffu, x, o);
            if (lane >= o) x += t;
        }
        if (lane == 31) warp_sums[wid] = x;
        __syncthreads();
        if (wid == 0) {
            int s = warp_sums[lane];
#pragma unroll
            for (int o = 1; o < 32; o <<= 1) {
                int t = __shfl_up_sync(0xffffffffu, s, o);
                if (lane >= o) s += t;
            }
            warp_sums[lane] = s;
        }
        __syncthreads();
        int woff = (wid > 0) ? warp_sums[wid - 1] : 0;
        int carry = carry_s;
        if (i < n) off[i] = carry + woff + x - v;
        int total = warp_sums[31];
        __syncthreads();
        if (tid == 0) carry_s = carry + total;
        __syncthreads();
    }
    if (threadIdx.x == 0) off[n] = carry_s;
}

__global__ void fill_kernel(const int* __restrict__ dst, const int* __restrict__ off,
                            int* __restrict__ cur, int* __restrict__ eid) {
    int e = blockIdx.x * blockDim.x + threadIdx.x;
    if (e < NE) {
        int d = dst[e];
        int p = atomicAdd(&cur[d], 1);
        eid[off[d] + p] = e;
    }
}

// ---------------- generic GEMM (f32x2 8x4, square warp tile, cp.async dbuf) ------
__global__ __launch_bounds__(256, 2) void gemm_act_kernel(
    const float* __restrict__ A, const float* __restrict__ W,
    const float* __restrict__ bias, float* __restrict__ C,
    int M, int N, int K, int act)
{
    __shared__ __align__(16) float sA[2][16][132];
    __shared__ __align__(16) float sB[2][16][64];
    const int bm = blockIdx.x * 128;
    const int bn = blockIdx.y * 64;
    const int tid = threadIdx.x;
    const int lane = tid & 31;
    const int wp = tid >> 5;
    // square warp footprint: warp covers rows (wp&3)*32..+31, cols (wp>>2)*32..+31
    const int tx = ((wp >> 2) << 3) | (lane & 7);
    const int ty = ((wp & 3) << 2) | (lane >> 3);
    const int la_m = tid >> 4, la_k = tid & 15;
    const int lb_k = tid >> 6, lb_n = tid & 63;
    const int nkb = K >> 4;

    ull acc2[4][4];
#pragma unroll
    for (int r = 0; r < 4; r++)
#pragma unroll
        for (int c = 0; c < 4; c++) acc2[r][c] = 0ull;

    auto issue = [&](int kb) {
        int p = kb & 1, k0 = kb << 4;
#pragma unroll
        for (int j = 0; j < 8; j++) {
            int gm = bm + la_m + 16 * j;
            int ok = gm < M;
            cpa4(&sA[p][la_k][la_m + 16 * j],
                 A + (size_t)(ok ? gm : 0) * K + k0 + la_k, ok);
        }
#pragma unroll
        for (int j = 0; j < 4; j++)
            cpa4(&sB[p][lb_k + 4 * j][lb_n],
                 W + (size_t)(k0 + lb_k + 4 * j) * N + bn + lb_n, 1);
        CP_COMMIT();
    };
    issue(0);
    for (int kb = 0; kb < nkb; kb++) {
        CP_WAIT0();
        __syncthreads();
        if (kb + 1 < nkb) issue(kb + 1);
        const int p = kb & 1;
#pragma unroll
        for (int kk = 0; kk < 16; kk++) {
            float4 b4 = *reinterpret_cast<const float4*>(&sB[p][kk][tx * 4]);
            ull bd[4] = {dup2(b4.x), dup2(b4.y), dup2(b4.z), dup2(b4.w)};
            ulonglong2 a01 = *reinterpret_cast<const ulonglong2*>(&sA[p][kk][ty * 8]);
            ulonglong2 a23 = *reinterpret_cast<const ulonglong2*>(&sA[p][kk][ty * 8 + 4]);
            ull ap[4] = {a01.x, a01.y, a23.x, a23.y};
#pragma unroll
            for (int rp = 0; rp < 4; rp++)
#pragma unroll
                for (int c = 0; c < 4; c++)
                    acc2[rp][c] = ffma2(ap[rp], bd[c], acc2[rp][c]);
        }
    }
#pragma unroll
    for (int rp = 0; rp < 4; rp++) {
        float2 u0 = unpack2(acc2[rp][0]);
        float2 u1 = unpack2(acc2[rp][1]);
        float2 u2 = unpack2(acc2[rp][2]);
        float2 u3 = unpack2(acc2[rp][3]);
        float rowv[2][4] = {{u0.x, u1.x, u2.x, u3.x}, {u0.y, u1.y, u2.y, u3.y}};
#pragma unroll
        for (int l = 0; l < 2; l++) {
            int gm = bm + ty * 8 + rp * 2 + l;
            if (gm >= M) continue;
            float4 v4;
            float* vp = &v4.x;
#pragma unroll
            for (int c = 0; c < 4; c++) {
                int gn = bn + tx * 4 + c;
                float v = rowv[l][c];
                if (bias) v += bias[gn];
                if (act == 1) v = (v > 0.f) ? v : (expf(v) - 1.f);
                else if (act == 2) v = (v > 0.f) ? v : 0.01f * v;
                else if (act == 3) v = fmaxf(v, 0.f);
                vp[c] = v;
            }
            *reinterpret_cast<float4*>(&C[(size_t)gm * N + bn + tx * 4]) = v4;
        }
    }
}

// ---------------- fused node GEMM (f32x2 8x4, square warp tile, cp.async dbuf) ---
__global__ __launch_bounds__(256, 2) void node_gemm_kernel(
    const float* __restrict__ A,
    const float* __restrict__ wni, const float* __restrict__ wnj,
    const float* __restrict__ wnode,
    float* __restrict__ xwi, float* __restrict__ xwj, float* __restrict__ fn,
    int M)
{
    __shared__ __align__(16) float sA[2][16][132];
    __shared__ __align__(16) float sB[2][16][64];
    const int by = blockIdx.y;
    const float* W; float* C; int ldW, ldC, coloff;
    if (by < 2)      { W = wni;   C = xwi; ldW = 128; ldC = 128; coloff = by << 6; }
    else if (by < 4) { W = wnj;   C = xwj; ldW = 128; ldC = 128; coloff = (by - 2) << 6; }
    else             { W = wnode; C = fn;  ldW = 256; ldC = 256; coloff = (by - 4) << 6; }

    const int bm = blockIdx.x * 128;
    const int tid = threadIdx.x;
    const int lane = tid & 31;
    const int wp = tid >> 5;
    const int tx = ((wp >> 2) << 3) | (lane & 7);
    const int ty = ((wp & 3) << 2) | (lane >> 3);
    const int la_m = tid >> 4, la_k = tid & 15;
    const int lb_k = tid >> 6, lb_n = tid & 63;

    ull acc2[4][4];
#pragma unroll
    for (int r = 0; r < 4; r++)
#pragma unroll
        for (int c = 0; c < 4; c++) acc2[r][c] = 0ull;

    auto issue = [&](int kb) {
        int p = kb & 1, k0 = kb << 4;
#pragma unroll
        for (int j = 0; j < 8; j++) {
            int gm = bm + la_m + 16 * j;
            int ok = gm < M;
            cpa4(&sA[p][la_k][la_m + 16 * j],
                 A + (size_t)(ok ? gm : 0) * 64 + k0 + la_k, ok);
        }
#pragma unroll
        for (int j = 0; j < 4; j++)
            cpa4(&sB[p][lb_k + 4 * j][lb_n],
                 W + (size_t)(k0 + lb_k + 4 * j) * ldW + coloff + lb_n, 1);
        CP_COMMIT();
    };
    issue(0);
#pragma unroll
    for (int kb = 0; kb < 4; kb++) {
        CP_WAIT0();
        __syncthreads();
        if (kb < 3) issue(kb + 1);
        const int p = kb & 1;
#pragma unroll
        for (int kk = 0; kk < 16; kk++) {
            float4 b4 = *reinterpret_cast<const float4*>(&sB[p][kk][tx * 4]);
            ull bd[4] = {dup2(b4.x), dup2(b4.y), dup2(b4.z), dup2(b4.w)};
            ulonglong2 a01 = *reinterpret_cast<const ulonglong2*>(&sA[p][kk][ty * 8]);
            ulonglong2 a23 = *reinterpret_cast<const ulonglong2*>(&sA[p][kk][ty * 8 + 4]);
            ull ap[4] = {a01.x, a01.y, a23.x, a23.y};
#pragma unroll
            for (int rp = 0; rp < 4; rp++)
#pragma unroll
                for (int c = 0; c < 4; c++)
                    acc2[rp][c] = ffma2(ap[rp], bd[c], acc2[rp][c]);
        }
    }
#pragma unroll
    for (int rp = 0; rp < 4; rp++) {
        float2 u0 = unpack2(acc2[rp][0]);
        float2 u1 = unpack2(acc2[rp][1]);
        float2 u2 = unpack2(acc2[rp][2]);
        float2 u3 = unpack2(acc2[rp][3]);
        int gm0 = bm + ty * 8 + rp * 2;
        if (gm0 < M) {
            float4 v4 = make_float4(u0.x, u1.x, u2.x, u3.x);
            *reinterpret_cast<float4*>(&C[(size_t)gm0 * ldC + coloff + tx * 4]) = v4;
        }
        if (gm0 + 1 < M) {
            float4 v4 = make_float4(u0.y, u1.y, u2.y, u3.y);
            *reinterpret_cast<float4*>(&C[(size_t)(gm0 + 1) * ldC + coloff + tx * 4]) = v4;
        }
    }
}

// ---------------- fused edge GEMM + attention score (f32x2, square warp tile) ----
__global__ __launch_bounds__(256, 2) void edge_score_fused_kernel(
    const float* __restrict__ efeat, const float* __restrict__ we,
    const float* __restrict__ attn,
    const int* __restrict__ src, const int* __restrict__ dst,
    const float* __restrict__ xwi, const float* __restrict__ xwj,
    float* __restrict__ scores, int Ke)
{
    __shared__ __align__(16) float sE[2][16][68];
    __shared__ __align__(16) float sW[2][16][128];
    __shared__ float s_attn[128];
    __shared__ int   s_src[64], s_dst[64];

    const int tid = threadIdx.x;
    const int e0 = blockIdx.x * 64;
    const int lane = tid & 31;
    const int wp = tid >> 5;
    // square warp footprint: warp covers 32 edges x 32 cols (one head)
    const int tx = ((wp >> 1) << 2) | (lane & 3);   // 16 col groups of 8
    const int ty = ((wp & 1) << 3) | (lane >> 2);   // 16 edge groups of 4
    const int le_e = tid >> 4, le_k = tid & 15;
    const int lw_k = tid >> 7, lw_c = tid & 127;
    const int nkb = Ke >> 4;

    if (tid < 128) s_attn[tid] = attn[tid];
    if (tid < 64) {
        int ge = e0 + tid;
        s_src[tid] = (ge < NE) ? src[ge] : 0;
        s_dst[tid] = (ge < NE) ? dst[ge] : 0;
    }

    ull acc2[2][8];
#pragma unroll
    for (int r = 0; r < 2; r++)
#pragma unroll
        for (int c = 0; c < 8; c++) acc2[r][c] = 0ull;

    auto issue = [&](int kb) {
        int p = kb & 1, k0 = kb << 4;
#pragma unroll
        for (int j = 0; j < 4; j++) {
            int e = le_e + 16 * j;
            int ge = e0 + e;
            int ok = ge < NE;
            cpa4(&sE[p][le_k][e],
                 efeat + (size_t)(ok ? ge : 0) * Ke + k0 + le_k, ok);
        }
#pragma unroll
        for (int j = 0; j < 8; j++)
            cpa4(&sW[p][lw_k + 2 * j][lw_c],
                 we + (size_t)(k0 + lw_k + 2 * j) * 128 + lw_c, 1);
        CP_COMMIT();
    };
    issue(0);
    for (int kb = 0; kb < nkb; kb++) {
        CP_WAIT0();
        __syncthreads();
        if (kb + 1 < nkb) issue(kb + 1);
        const int p = kb & 1;
#pragma unroll
        for (int kk = 0; kk < 16; kk++) {
            ulonglong2 a01 = *reinterpret_cast<const ulonglong2*>(&sE[p][kk][ty * 4]);
            ull ap[2] = {a01.x, a01.y};
            float4 w0 = *reinterpret_cast<const float4*>(&sW[p][kk][tx * 8]);
            float4 w1 = *reinterpret_cast<const float4*>(&sW[p][kk][tx * 8 + 4]);
            ull bd[8] = {dup2(w0.x), dup2(w0.y), dup2(w0.z), dup2(w0.w),
                         dup2(w1.x), dup2(w1.y), dup2(w1.z), dup2(w1.w)};
#pragma unroll
            for (int rp = 0; rp < 2; rp++)
#pragma unroll
                for (int c = 0; c < 8; c++)
                    acc2[rp][c] = ffma2(ap[rp], bd[c], acc2[rp][c]);
        }
    }

    float accr[4][8];
#pragma unroll
    for (int rp = 0; rp < 2; rp++)
#pragma unroll
        for (int c = 0; c < 8; c++) {
            float2 u = unpack2(acc2[rp][c]);
            accr[rp * 2][c]     = u.x;
            accr[rp * 2 + 1][c] = u.y;
        }

    const int h = tx >> 2;
    float at[8];
#pragma unroll
    for (int c = 0; c < 8; c++) at[c] = s_attn[tx * 8 + c];

#pragma unroll
    for (int r = 0; r < 4; r++) {
        int eg = ty * 4 + r;
        int ge = e0 + eg;
        float p = 0.f;
        if (ge < NE) {
            const float* gi = &xwi[(size_t)s_src[eg] * 128 + tx * 8];
            const float* gj = &xwj[(size_t)s_dst[eg] * 128 + tx * 8];
            float4 gi0 = *reinterpret_cast<const float4*>(gi);
            float4 gi1 = *reinterpret_cast<const float4*>(gi + 4);
            float4 gj0 = *reinterpret_cast<const float4*>(gj);
            float4 gj1 = *reinterpret_cast<const float4*>(gj + 4);
            float f[8];
            f[0] = accr[r][0] + gi0.x + gj0.x;  f[1] = accr[r][1] + gi0.y + gj0.y;
            f[2] = accr[r][2] + gi0.z + gj0.z;  f[3] = accr[r][3] + gi0.w + gj0.w;
            f[4] = accr[r][4] + gi1.x + gj1.x;  f[5] = accr[r][5] + gi1.y + gj1.y;
            f[6] = accr[r][6] + gi1.z + gj1.z;  f[7] = accr[r][7] + gi1.w + gj1.w;
#pragma unroll
            for (int c = 0; c < 8; c++) {
                float v = f[c];
                v = (v > 0.f) ? v : 0.2f * v;
                p += v * at[c];
            }
        }
        // reduce across the 4 tx values of this head: lane bits 0,1
        p += __shfl_xor_sync(0xffffffffu, p, 1);
        p += __shfl_xor_sync(0xffffffffu, p, 2);
        if ((lane & 3) == 0 && ge < NE)
            scores[(size_t)ge * 4 + h] = p;
    }
}

// ---------------- fused softmax + aggregation, warp per node (smem-staged alpha) ----------------
__global__ __launch_bounds__(256) void attn_agg_kernel(
    const float* __restrict__ scores, const float* __restrict__ mask,
    const int* __restrict__ src, const float* __restrict__ fn,
    const int* __restrict__ off, const int* __restrict__ eid,
    float* __restrict__ outp)
{
    __shared__ __align__(16) float sm_a[8][32][4];
    __shared__ int sm_s[8][32];
    int w = threadIdx.x >> 5;
    int lane = threadIdx.x & 31;
    int n = blockIdx.x * 8 + w;
    if (n >= NN) return;
    int beg = off[n], end = off[n + 1];

    float4 acc0 = make_float4(0.f, 0.f, 0.f, 0.f);
    float4 acc1 = make_float4(0.f, 0.f, 0.f, 0.f);
    const int h = lane >> 3;

    if (beg < end) {
        float4 m = make_float4(-1e30f, -1e30f, -1e30f, -1e30f);
        for (int i = beg + lane; i < end; i += 32) {
            float4 s = *reinterpret_cast<const float4*>(&scores[(size_t)eid[i] * 4]);
            m.x = fmaxf(m.x, s.x); m.y = fmaxf(m.y, s.y);
            m.z = fmaxf(m.z, s.z); m.w = fmaxf(m.w, s.w);
        }
#pragma unroll
        for (int o = 16; o; o >>= 1) {
            m.x = fmaxf(m.x, __shfl_xor_sync(0xffffffffu, m.x, o));
            m.y = fmaxf(m.y, __shfl_xor_sync(0xffffffffu, m.y, o));
            m.z = fmaxf(m.z, __shfl_xor_sync(0xffffffffu, m.z, o));
            m.w = fmaxf(m.w, __shfl_xor_sync(0xffffffffu, m.w, o));
        }
        float4 d = make_float4(0.f, 0.f, 0.f, 0.f);
        for (int i = beg + lane; i < end; i += 32) {
            float4 s = *reinterpret_cast<const float4*>(&scores[(size_t)eid[i] * 4]);
            d.x += __expf(s.x - m.x); d.y += __expf(s.y - m.y);
            d.z += __expf(s.z - m.z); d.w += __expf(s.w - m.w);
        }
#pragma unroll
        for (int o = 16; o; o >>= 1) {
            d.x += __shfl_xor_sync(0xffffffffu, d.x, o);
            d.y += __shfl_xor_sync(0xffffffffu, d.y, o);
            d.z += __shfl_xor_sync(0xffffffffu, d.z, o);
            d.w += __shfl_xor_sync(0xffffffffu, d.w, o);
        }
        float4 inv = make_float4(1.f / (d.x + 1e-9f), 1.f / (d.y + 1e-9f),
                                 1.f / (d.z + 1e-9f), 1.f / (d.w + 1e-9f));

        for (int c0 = beg; c0 < end; c0 += 32) {
            int i = c0 + lane;
            if (i < end) {
                int e = eid[i];
                float4 s = *reinterpret_cast<const float4*>(&scores[(size_t)e * 4]);
                float mk = mask[e];
                float4 a4;
                a4.x = __expf(s.x - m.x) * inv.x * mk;
                a4.y = __expf(s.y - m.y) * inv.y * mk;
                a4.z = __expf(s.z - m.z) * inv.z * mk;
                a4.w = __expf(s.w - m.w) * inv.w * mk;
                *reinterpret_cast<float4*>(&sm_a[w][lane][0]) = a4;
                sm_s[w][lane] = src[e];
            }
            __syncwarp();
            int cl = min(32, end - c0);
            int j = 0;
            for (; j + 1 < cl; j += 2) {
                float a0 = sm_a[w][j][h];
                float a1 = sm_a[w][j + 1][h];
                const float4* f0p = reinterpret_cast<const float4*>(
                    &fn[(size_t)sm_s[w][j] * 256 + lane * 8]);
                const float4* f1p = reinterpret_cast<const float4*>(
                    &fn[(size_t)sm_s[w][j + 1] * 256 + lane * 8]);
                float4 f00 = f0p[0], f01 = f0p[1];
                float4 f10 = f1p[0], f11 = f1p[1];
                acc0.x += a0 * f00.x; acc0.y += a0 * f00.y;
                acc0.z += a0 * f00.z; acc0.w += a0 * f00.w;
                acc1.x += a0 * f01.x; acc1.y += a0 * f01.y;
                acc1.z += a0 * f01.z; acc1.w += a0 * f01.w;
                acc0.x += a1 * f10.x; acc0.y += a1 * f10.y;
                acc0.z += a1 * f10.z; acc0.w += a1 * f10.w;
                acc1.x += a1 * f11.x; acc1.y += a1 * f11.y;
                acc1.z += a1 * f11.z; acc1.w += a1 * f11.w;
            }
            if (j < cl) {
                float a0 = sm_a[w][j][h];
                const float4* fp = reinterpret_cast<const float4*>(
                    &fn[(size_t)sm_s[w][j] * 256 + lane * 8]);
                float4 f0 = fp[0], f1 = fp[1];
                acc0.x += a0 * f0.x; acc0.y += a0 * f0.y;
                acc0.z += a0 * f0.z; acc0.w += a0 * f0.w;
                acc1.x += a0 * f1.x; acc1.y += a0 * f1.y;
                acc1.z += a0 * f1.z; acc1.w += a0 * f1.w;
            }
            __syncwarp();
        }
    }
    float4* op = reinterpret_cast<float4*>(&outp[(size_t)n * 256 + lane * 8]);
    op[0] = acc0;
    op[1] = acc1;
}

// ---------------- readout gather + final outputs ----------------
__global__ void gather_kernel(
    const float* __restrict__ ui0, const float* __restrict__ ui1,
    const float* __restrict__ sg0, const float* __restrict__ sg1,
    const int* __restrict__ user, const int* __restrict__ item,
    const int* __restrict__ subg,
    float* __restrict__ uix, float* __restrict__ sgx)
{
    int b = blockIdx.x;
    int t = threadIdx.x;
    int u = user[b], it = item[b], s = subg[b];
    float v;
    if (t < 64)       v = ui0[(size_t)u * 64 + t];
    else if (t < 128) v = ui1[(size_t)u * 64 + t - 64];
    else if (t < 192) v = ui0[(size_t)it * 64 + t - 128];
    else              v = ui1[(size_t)it * 64 + t - 192];
    uix[(size_t)b * 256 + t] = v;
    if (t < 128) {
        float w = (t < 64) ? sg0[(size_t)s * 64 + t] : sg1[(size_t)s * 64 + t - 64];
        sgx[(size_t)b * 128 + t] = w;
    }
}

__global__ void final_out_kernel(
    const float* __restrict__ hui, const float* __restrict__ hsg,
    const float* __restrict__ w2ui, const float* __restrict__ b2ui,
    const float* __restrict__ w2sg, const float* __restrict__ b2sg,
    float* __restrict__ out)
{
    int r = blockIdx.x * 8 + (threadIdx.x >> 5);
    int lane = threadIdx.x & 31;
    if (r >= BB) return;
    float su = 0.f, ss = 0.f;
#pragma unroll
    for (int k = lane; k < 128; k += 32) {
        su += hui[(size_t)r * 128 + k] * w2ui[k];
        ss += hsg[(size_t)r * 128 + k] * w2sg[k];
    }
#pragma unroll
    for (int o = 16; o; o >>= 1) {
        su += __shfl_xor_sync(0xffffffffu, su, o);
        ss += __shfl_xor_sync(0xffffffffu, ss, o);
    }
    if (lane == 0) {
        out[r]      = 1.f / (1.f + expf(-(ss + b2sg[0])));   // sg_out
        out[BB + r] = 1.f / (1.f + expf(-(su + b2ui[0])));   // ui_out
    }
}

// ---------------- host orchestration ----------------
static void gemm(const float* A, const float* W, const float* bias, float* C,
                 int M, int N, int K, int act) {
    dim3 g((M + 127) / 128, N / 64);
    gemm_act_kernel<<<g, 256>>>(A, W, bias, C, M, N, K, act);
}

extern "C" void kernel_launch(void* const* d_in, const int* in_sizes, int n_in,
                              void* d_out, int out_size) {
    const float* x        = (const float*)d_in[0];
    const float* efeat    = (const float*)d_in[1];
    const float* efeat2   = (const float*)d_in[2];
    const float* mask1    = (const float*)d_in[3];
    const float* mask2    = (const float*)d_in[4];
    const int*   src      = (const int*)d_in[5];
    const int*   dst      = (const int*)d_in[6];
    const int*   user     = (const int*)d_in[7];
    const int*   item     = (const int*)d_in[8];
    const int*   subg     = (const int*)d_in[9];
    const float* loc_wni  = (const float*)d_in[10];
    const float* loc_wnj  = (const float*)d_in[11];
    const float* loc_we   = (const float*)d_in[12];
    const float* loc_attn = (const float*)d_in[13];
    const float* loc_wnode= (const float*)d_in[14];
    const float* agg1_w   = (const float*)d_in[15];
    const float* agg1_b   = (const float*)d_in[16];
    const float* glob_wni = (const float*)d_in[17];
    const float* glob_wnj = (const float*)d_in[18];
    const float* glob_we  = (const float*)d_in[19];
    const float* glob_attn= (const float*)d_in[20];
    const float* glob_wnode=(const float*)d_in[21];
    const float* agg2_w   = (const float*)d_in[22];
    const float* agg2_b   = (const float*)d_in[23];
    const float* w1_ui    = (const float*)d_in[24];
    const float* b1_ui    = (const float*)d_in[25];
    const float* w1_sg    = (const float*)d_in[26];
    const float* b1_sg    = (const float*)d_in[27];
    const float* w2_ui    = (const float*)d_in[28];
    const float* b2_ui    = (const float*)d_in[29];
    const float* w2_sg    = (const float*)d_in[30];
    const float* b2_sg    = (const float*)d_in[31];

    float *p_xwi, *p_xwj, *p_fn, *p_agg, *p_scores;
    float *p_ui0, *p_ui1, *p_sg0, *p_sg1, *p_uix, *p_sgx, *p_hui, *p_hsg;
    int *p_deg, *p_off, *p_cur, *p_eid;
    cudaGetSymbolAddress((void**)&p_xwi, g_xwi);
    cudaGetSymbolAddress((void**)&p_xwj, g_xwj);
    cudaGetSymbolAddress((void**)&p_fn,  g_fn);
    cudaGetSymbolAddress((void**)&p_agg, g_agg);
    cudaGetSymbolAddress((void**)&p_scores, g_scores);
    cudaGetSymbolAddress((void**)&p_ui0, g_ui0);
    cudaGetSymbolAddress((void**)&p_ui1, g_ui1);
    cudaGetSymbolAddress((void**)&p_sg0, g_sg0);
    cudaGetSymbolAddress((void**)&p_sg1, g_sg1);
    cudaGetSymbolAddress((void**)&p_uix, g_uix);
    cudaGetSymbolAddress((void**)&p_sgx, g_sgx);
    cudaGetSymbolAddress((void**)&p_hui, g_hui);
    cudaGetSymbolAddress((void**)&p_hsg, g_hsg);
    cudaGetSymbolAddress((void**)&p_deg, g_deg);
    cudaGetSymbolAddress((void**)&p_off, g_off);
    cudaGetSymbolAddress((void**)&p_cur, g_cur);
    cudaGetSymbolAddress((void**)&p_eid, g_eid);

    // CSR by dst
    cudaMemsetAsync(p_deg, 0, NN * sizeof(int));
    cudaMemsetAsync(p_cur, 0, NN * sizeof(int));
    hist_kernel<<<(NE + 255) / 256, 256>>>(dst, p_deg);
    scan_kernel<<<1, 1024>>>(p_deg, p_off, NN);
    fill_kernel<<<(NE + 255) / 256, 256>>>(dst, p_off, p_cur, p_eid);

    struct Stage {
        const float* hin; const float* ef; int Ke; const float* mask;
        const float* wni; const float* wnj; const float* we; const float* attn;
        const float* wnode; const float* aggw; const float* aggb; int act; float* hout;
    };
    Stage st[4] = {
        { x,     efeat,  16, mask1, loc_wni,           loc_wnj,           loc_we,           loc_attn,         loc_wnode,           agg1_w,          agg1_b,       1, p_ui0 },
        { p_ui0, efeat2, 64, mask2, glob_wni,          glob_wnj,          glob_we,          glob_attn,        glob_wnode,          agg2_w,          agg2_b,       2, p_sg0 },
        { p_sg0, efeat,  16, mask1, loc_wni  + 64*128, loc_wnj  + 64*128, loc_we  + 16*128, loc_attn  + 128,  loc_wnode  + 64*256, agg1_w + 256*64, agg1_b + 64,  1, p_ui1 },
        { p_ui1, efeat2, 64, mask2, glob_wni + 64*128, glob_wnj + 64*128, glob_we + 64*128, glob_attn + 128,  glob_wnode + 64*256, agg2_w + 256*64, agg2_b + 64,  2, p_sg1 },
    };

    for (int s = 0; s < 4; s++) {
        node_gemm_kernel<<<dim3((NN + 127) / 128, 8), 256>>>(
            st[s].hin, st[s].wni, st[s].wnj, st[s].wnode, p_xwi, p_xwj, p_fn, NN);
        edge_score_fused_kernel<<<(NE + 63) / 64, 256>>>(
            st[s].ef, st[s].we, st[s].attn, src, dst, p_xwi, p_xwj, p_scores, st[s].Ke);
        attn_agg_kernel<<<(NN + 7) / 8, 256>>>(p_scores, st[s].mask, src, p_fn, p_off, p_eid, p_agg);
        gemm(p_agg, st[s].aggw, st[s].aggb, st[s].hout, NN, 64, 256, st[s].act);
    }

    gather_kernel<<<BB, 256>>>(p_ui0, p_ui1, p_sg0, p_sg1, user, item, subg, p_uix, p_sgx);
    gemm(p_uix, w1_ui, b1_ui, p_hui, BB, 128, 256, 3);
    gemm(p_sgx, w1_sg, b1_sg, p_hsg, BB, 128, 128, 3);
    final_out_kernel<<<BB / 8, 256>>>(p_hui, p_hsg, w2_ui, b2_ui, w2_sg, b2_sg, (float*)d_out);
}

// round 14
// speedup vs baseline: 1.2059x; 1.0296x over previous
#include <cuda_runtime.h>
#include <math.h>

#define NN 50000
#define NE 320000
#define BB 4096

typedef unsigned long long ull;

__device__ __forceinline__ ull ffma2(ull a, ull b, ull c) {
    ull d;
    asm("fma.rn.f32x2 %0, %1, %2, %3;" : "=l"(d) : "l"(a), "l"(b), "l"(c));
    return d;
}
__device__ __forceinline__ ull dup2(float x) {
    ull d;
    asm("mov.b64 %0, {%1, %1};" : "=l"(d) : "f"(x));
    return d;
}
__device__ __forceinline__ float2 unpack2(ull v) {
    float2 r;
    asm("mov.b64 {%0, %1}, %2;" : "=f"(r.x), "=f"(r.y) : "l"(v));
    return r;
}
__device__ __forceinline__ unsigned s2u(const void* p) {
    unsigned a;
    asm("{ .reg .u64 t; cvta.to.shared.u64 t, %1; cvt.u32.u64 %0, t; }" : "=r"(a) : "l"(p));
    return a;
}
__device__ __forceinline__ void cpa4(const void* smem, const void* gmem, int ok) {
    asm volatile("cp.async.ca.shared.global [%0], [%1], 4, %2;"
                 :: "r"(s2u(smem)), "l"(gmem), "r"(ok ? 4 : 0));
}
__device__ __forceinline__ void cpa16(const void* smem, const void* gmem) {
    asm volatile("cp.async.cg.shared.global [%0], [%1], 16;"
                 :: "r"(s2u(smem)), "l"(gmem));
}
#define CP_COMMIT() asm volatile("cp.async.commit_group;" ::: "memory")
#define CP_WAIT0()  asm volatile("cp.async.wait_group 0;" ::: "memory")

// ---------------- scratch (device globals) ----------------
__device__ float g_xwi[NN * 128];
__device__ float g_xwj[NN * 128];
__device__ float g_fn [NN * 256];
__device__ float g_agg[NN * 256];
__device__ float g_scores[NE * 4];   // CSR-ordered
__device__ float g_ui0[NN * 64];
__device__ float g_ui1[NN * 64];
__device__ float g_sg0[NN * 64];
__device__ float g_sg1[NN * 64];
__device__ float g_uix[BB * 256];
__device__ float g_sgx[BB * 128];
__device__ float g_hui[BB * 128];
__device__ float g_hsg[BB * 128];
__device__ int   g_deg[NN];
__device__ int   g_off[NN + 1];
__device__ int   g_cur[NN];
__device__ int   g_eid[NE];
__device__ int   g_epos[NE];
__device__ int   g_srcc[NE];         // src in CSR order

// ---------------- CSR build ----------------
__global__ void hist_kernel(const int* __restrict__ dst, int* __restrict__ deg) {
    int e = blockIdx.x * blockDim.x + threadIdx.x;
    if (e < NE) atomicAdd(&deg[dst[e]], 1);
}

__global__ void scan_kernel(const int* __restrict__ deg, int* __restrict__ off, int n) {
    __shared__ int warp_sums[32];
    __shared__ int carry_s;
    const int tid = threadIdx.x;
    const int lane = tid & 31;
    const int wid = tid >> 5;
    if (tid == 0) carry_s = 0;
    __syncthreads();
    for (int base = 0; base < n; base += 1024) {
        int i = base + tid;
        int v = (i < n) ? deg[i] : 0;
        int x = v;
#pragma unroll
        for (int o = 1; o < 32; o <<= 1) {
            int t = __shfl_up_sync(0xffffffffu, x, o);
            if (lane >= o) x += t;
        }
        if (lane == 31) warp_sums[wid] = x;
        __syncthreads();
        if (wid == 0) {
            int s = warp_sums[lane];
#pragma unroll
            for (int o = 1; o < 32; o <<= 1) {
                int t = __shfl_up_sync(0xffffffffu, s, o);
                if (lane >= o) s += t;
            }
            warp_sums[lane] = s;
        }
        __syncthreads();
        int woff = (wid > 0) ? warp_sums[wid - 1] : 0;
        int carry = carry_s;
        if (i < n) off[i] = carry + woff + x - v;
        int total = warp_sums[31];
        __syncthreads();
        if (tid == 0) carry_s = carry + total;
        __syncthreads();
    }
    if (threadIdx.x == 0) off[n] = carry_s;
}

__global__ void fill_kernel(const int* __restrict__ dst, const int* __restrict__ src,
                            const int* __restrict__ off,
                            int* __restrict__ cur, int* __restrict__ eid,
                            int* __restrict__ epos, int* __restrict__ srcc) {
    int e = blockIdx.x * blockDim.x + threadIdx.x;
    if (e < NE) {
        int d = dst[e];
        int p = atomicAdd(&cur[d], 1);
        int pos = off[d] + p;
        eid[pos] = e;
        epos[e] = pos;
        srcc[pos] = src[e];
    }
}

// ---------------- generic GEMM (f32x2 8x4, square warp tile, cp.async dbuf) ------
__global__ __launch_bounds__(256, 2) void gemm_act_kernel(
    const float* __restrict__ A, const float* __restrict__ W,
    const float* __restrict__ bias, float* __restrict__ C,
    int M, int N, int K, int act)
{
    __shared__ __align__(16) float sA[2][16][132];
    __shared__ __align__(16) float sB[2][16][64];
    const int bm = blockIdx.x * 128;
    const int bn = blockIdx.y * 64;
    const int tid = threadIdx.x;
    const int lane = tid & 31;
    const int wp = tid >> 5;
    const int tx = ((wp >> 2) << 3) | (lane & 7);
    const int ty = ((wp & 3) << 2) | (lane >> 3);
    const int la_m = tid >> 4, la_k = tid & 15;
    const int lb_k = tid >> 4, lb_n = (tid & 15) * 4;
    const int nkb = K >> 4;

    ull acc2[4][4];
#pragma unroll
    for (int r = 0; r < 4; r++)
#pragma unroll
        for (int c = 0; c < 4; c++) acc2[r][c] = 0ull;

    auto issue = [&](int kb) {
        int p = kb & 1, k0 = kb << 4;
#pragma unroll
        for (int j = 0; j < 8; j++) {
            int gm = bm + la_m + 16 * j;
            int ok = gm < M;
            cpa4(&sA[p][la_k][la_m + 16 * j],
                 A + (size_t)(ok ? gm : 0) * K + k0 + la_k, ok);
        }
        cpa16(&sB[p][lb_k][lb_n], W + (size_t)(k0 + lb_k) * N + bn + lb_n);
        CP_COMMIT();
    };
    issue(0);
    for (int kb = 0; kb < nkb; kb++) {
        CP_WAIT0();
        __syncthreads();
        if (kb + 1 < nkb) issue(kb + 1);
        const int p = kb & 1;
#pragma unroll
        for (int kk = 0; kk < 16; kk++) {
            float4 b4 = *reinterpret_cast<const float4*>(&sB[p][kk][tx * 4]);
            ull bd[4] = {dup2(b4.x), dup2(b4.y), dup2(b4.z), dup2(b4.w)};
            ulonglong2 a01 = *reinterpret_cast<const ulonglong2*>(&sA[p][kk][ty * 8]);
            ulonglong2 a23 = *reinterpret_cast<const ulonglong2*>(&sA[p][kk][ty * 8 + 4]);
            ull ap[4] = {a01.x, a01.y, a23.x, a23.y};
#pragma unroll
            for (int rp = 0; rp < 4; rp++)
#pragma unroll
                for (int c = 0; c < 4; c++)
                    acc2[rp][c] = ffma2(ap[rp], bd[c], acc2[rp][c]);
        }
    }
#pragma unroll
    for (int rp = 0; rp < 4; rp++) {
        float2 u0 = unpack2(acc2[rp][0]);
        float2 u1 = unpack2(acc2[rp][1]);
        float2 u2 = unpack2(acc2[rp][2]);
        float2 u3 = unpack2(acc2[rp][3]);
        float rowv[2][4] = {{u0.x, u1.x, u2.x, u3.x}, {u0.y, u1.y, u2.y, u3.y}};
#pragma unroll
        for (int l = 0; l < 2; l++) {
            int gm = bm + ty * 8 + rp * 2 + l;
            if (gm >= M) continue;
            float4 v4;
            float* vp = &v4.x;
#pragma unroll
            for (int c = 0; c < 4; c++) {
                int gn = bn + tx * 4 + c;
                float v = rowv[l][c];
                if (bias) v += bias[gn];
                if (act == 1) v = (v > 0.f) ? v : (expf(v) - 1.f);
                else if (act == 2) v = (v > 0.f) ? v : 0.01f * v;
                else if (act == 3) v = fmaxf(v, 0.f);
                vp[c] = v;
            }
            *reinterpret_cast<float4*>(&C[(size_t)gm * N + bn + tx * 4]) = v4;
        }
    }
}

// ---------------- fused node GEMM (f32x2 8x4, square warp tile, cp.async dbuf) ---
__global__ __launch_bounds__(256, 2) void node_gemm_kernel(
    const float* __restrict__ A,
    const float* __restrict__ wni, const float* __restrict__ wnj,
    const float* __restrict__ wnode,
    float* __restrict__ xwi, float* __restrict__ xwj, float* __restrict__ fn,
    int M)
{
    __shared__ __align__(16) float sA[2][16][132];
    __shared__ __align__(16) float sB[2][16][64];
    const int by = blockIdx.y;
    const float* W; float* C; int ldW, ldC, coloff;
    if (by < 2)      { W = wni;   C = xwi; ldW = 128; ldC = 128; coloff = by << 6; }
    else if (by < 4) { W = wnj;   C = xwj; ldW = 128; ldC = 128; coloff = (by - 2) << 6; }
    else             { W = wnode; C = fn;  ldW = 256; ldC = 256; coloff = (by - 4) << 6; }

    const int bm = blockIdx.x * 128;
    const int tid = threadIdx.x;
    const int lane = tid & 31;
    const int wp = tid >> 5;
    const int tx = ((wp >> 2) << 3) | (lane & 7);
    const int ty = ((wp & 3) << 2) | (lane >> 3);
    const int la_m = tid >> 4, la_k = tid & 15;
    const int lb_k = tid >> 4, lb_n = (tid & 15) * 4;

    ull acc2[4][4];
#pragma unroll
    for (int r = 0; r < 4; r++)
#pragma unroll
        for (int c = 0; c < 4; c++) acc2[r][c] = 0ull;

    auto issue = [&](int kb) {
        int p = kb & 1, k0 = kb << 4;
#pragma unroll
        for (int j = 0; j < 8; j++) {
            int gm = bm + la_m + 16 * j;
            int ok = gm < M;
            cpa4(&sA[p][la_k][la_m + 16 * j],
                 A + (size_t)(ok ? gm : 0) * 64 + k0 + la_k, ok);
        }
        cpa16(&sB[p][lb_k][lb_n], W + (size_t)(k0 + lb_k) * ldW + coloff + lb_n);
        CP_COMMIT();
    };
    issue(0);
#pragma unroll
    for (int kb = 0; kb < 4; kb++) {
        CP_WAIT0();
        __syncthreads();
        if (kb < 3) issue(kb + 1);
        const int p = kb & 1;
#pragma unroll
        for (int kk = 0; kk < 16; kk++) {
            float4 b4 = *reinterpret_cast<const float4*>(&sB[p][kk][tx * 4]);
            ull bd[4] = {dup2(b4.x), dup2(b4.y), dup2(b4.z), dup2(b4.w)};
            ulonglong2 a01 = *reinterpret_cast<const ulonglong2*>(&sA[p][kk][ty * 8]);
            ulonglong2 a23 = *reinterpret_cast<const ulonglong2*>(&sA[p][kk][ty * 8 + 4]);
            ull ap[4] = {a01.x, a01.y, a23.x, a23.y};
#pragma unroll
            for (int rp = 0; rp < 4; rp++)
#pragma unroll
                for (int c = 0; c < 4; c++)
                    acc2[rp][c] = ffma2(ap[rp], bd[c], acc2[rp][c]);
        }
    }
#pragma unroll
    for (int rp = 0; rp < 4; rp++) {
        float2 u0 = unpack2(acc2[rp][0]);
        float2 u1 = unpack2(acc2[rp][1]);
        float2 u2 = unpack2(acc2[rp][2]);
        float2 u3 = unpack2(acc2[rp][3]);
        int gm0 = bm + ty * 8 + rp * 2;
        if (gm0 < M) {
            float4 v4 = make_float4(u0.x, u1.x, u2.x, u3.x);
            *reinterpret_cast<float4*>(&C[(size_t)gm0 * ldC + coloff + tx * 4]) = v4;
        }
        if (gm0 + 1 < M) {
            float4 v4 = make_float4(u0.y, u1.y, u2.y, u3.y);
            *reinterpret_cast<float4*>(&C[(size_t)(gm0 + 1) * ldC + coloff + tx * 4]) = v4;
        }
    }
}

// ---------------- fused edge GEMM + attention score (f32x2, square warp tile) ----
// scores written in CSR order via epos.
__global__ __launch_bounds__(256, 2) void edge_score_fused_kernel(
    const float* __restrict__ efeat, const float* __restrict__ we,
    const float* __restrict__ attn,
    const int* __restrict__ src, const int* __restrict__ dst,
    const int* __restrict__ epos,
    const float* __restrict__ xwi, const float* __restrict__ xwj,
    float* __restrict__ scores, int Ke)
{
    __shared__ __align__(16) float sE[2][16][68];
    __shared__ __align__(16) float sW[2][16][128];
    __shared__ float s_attn[128];
    __shared__ int   s_src[64], s_dst[64], s_ep[64];

    const int tid = threadIdx.x;
    const int e0 = blockIdx.x * 64;
    const int lane = tid & 31;
    const int wp = tid >> 5;
    const int tx = ((wp >> 1) << 2) | (lane & 3);
    const int ty = ((wp & 1) << 3) | (lane >> 2);
    const int le_e = tid >> 4, le_k = tid & 15;
    const int lw_r0 = tid >> 5, lw_c0 = (tid & 31) * 4;
    const int nkb = Ke >> 4;

    if (tid < 128) s_attn[tid] = attn[tid];
    if (tid < 64) {
        int ge = e0 + tid;
        s_src[tid] = (ge < NE) ? src[ge] : 0;
        s_dst[tid] = (ge < NE) ? dst[ge] : 0;
        s_ep[tid]  = (ge < NE) ? epos[ge] : 0;
    }

    ull acc2[2][8];
#pragma unroll
    for (int r = 0; r < 2; r++)
#pragma unroll
        for (int c = 0; c < 8; c++) acc2[r][c] = 0ull;

    auto issue = [&](int kb) {
        int p = kb & 1, k0 = kb << 4;
#pragma unroll
        for (int j = 0; j < 4; j++) {
            int e = le_e + 16 * j;
            int ge = e0 + e;
            int ok = ge < NE;
            cpa4(&sE[p][le_k][e],
                 efeat + (size_t)(ok ? ge : 0) * Ke + k0 + le_k, ok);
        }
        cpa16(&sW[p][lw_r0][lw_c0],     we + (size_t)(k0 + lw_r0) * 128 + lw_c0);
        cpa16(&sW[p][lw_r0 + 8][lw_c0], we + (size_t)(k0 + lw_r0 + 8) * 128 + lw_c0);
        CP_COMMIT();
    };
    issue(0);
    for (int kb = 0; kb < nkb; kb++) {
        CP_WAIT0();
        __syncthreads();
        if (kb + 1 < nkb) issue(kb + 1);
        const int p = kb & 1;
#pragma unroll
        for (int kk = 0; kk < 16; kk++) {
            ulonglong2 a01 = *reinterpret_cast<const ulonglong2*>(&sE[p][kk][ty * 4]);
            ull ap[2] = {a01.x, a01.y};
            float4 w0 = *reinterpret_cast<const float4*>(&sW[p][kk][tx * 8]);
            float4 w1 = *reinterpret_cast<const float4*>(&sW[p][kk][tx * 8 + 4]);
            ull bd[8] = {dup2(w0.x), dup2(w0.y), dup2(w0.z), dup2(w0.w),
                         dup2(w1.x), dup2(w1.y), dup2(w1.z), dup2(w1.w)};
#pragma unroll
            for (int rp = 0; rp < 2; rp++)
#pragma unroll
                for (int c = 0; c < 8; c++)
                    acc2[rp][c] = ffma2(ap[rp], bd[c], acc2[rp][c]);
        }
    }

    float accr[4][8];
#pragma unroll
    for (int rp = 0; rp < 2; rp++)
#pragma unroll
        for (int c = 0; c < 8; c++) {
            float2 u = unpack2(acc2[rp][c]);
            accr[rp * 2][c]     = u.x;
            accr[rp * 2 + 1][c] = u.y;
        }

    const int h = tx >> 2;
    float at[8];
#pragma unroll
    for (int c = 0; c < 8; c++) at[c] = s_attn[tx * 8 + c];

#pragma unroll
    for (int r = 0; r < 4; r++) {
        int eg = ty * 4 + r;
        int ge = e0 + eg;
        float p = 0.f;
        if (ge < NE) {
            const float* gi = &xwi[(size_t)s_src[eg] * 128 + tx * 8];
            const float* gj = &xwj[(size_t)s_dst[eg] * 128 + tx * 8];
            float4 gi0 = *reinterpret_cast<const float4*>(gi);
            float4 gi1 = *reinterpret_cast<const float4*>(gi + 4);
            float4 gj0 = *reinterpret_cast<const float4*>(gj);
            float4 gj1 = *reinterpret_cast<const float4*>(gj + 4);
            float f[8];
            f[0] = accr[r][0] + gi0.x + gj0.x;  f[1] = accr[r][1] + gi0.y + gj0.y;
            f[2] = accr[r][2] + gi0.z + gj0.z;  f[3] = accr[r][3] + gi0.w + gj0.w;
            f[4] = accr[r][4] + gi1.x + gj1.x;  f[5] = accr[r][5] + gi1.y + gj1.y;
            f[6] = accr[r][6] + gi1.z + gj1.z;  f[7] = accr[r][7] + gi1.w + gj1.w;
#pragma unroll
            for (int c = 0; c < 8; c++) {
                float v = f[c];
                v = (v > 0.f) ? v : 0.2f * v;
                p += v * at[c];
            }
        }
        p += __shfl_xor_sync(0xffffffffu, p, 1);
        p += __shfl_xor_sync(0xffffffffu, p, 2);
        if ((lane & 3) == 0 && ge < NE)
            scores[(size_t)s_ep[eg] * 4 + h] = p;
    }
}

// ---------------- fused softmax + aggregation (CSR-ordered scores/src) ----------
__global__ __launch_bounds__(256) void attn_agg_kernel(
    const float* __restrict__ scores, const float* __restrict__ mask,
    const int* __restrict__ srcc, const float* __restrict__ fn,
    const int* __restrict__ off, const int* __restrict__ eid,
    float* __restrict__ outp)
{
    __shared__ __align__(16) float sm_a[8][32][4];
    __shared__ int sm_s[8][32];
    int w = threadIdx.x >> 5;
    int lane = threadIdx.x & 31;
    int n = blockIdx.x * 8 + w;
    if (n >= NN) return;
    int beg = off[n], end = off[n + 1];

    float4 acc0 = make_float4(0.f, 0.f, 0.f, 0.f);
    float4 acc1 = make_float4(0.f, 0.f, 0.f, 0.f);
    const int h = lane >> 3;

    if (beg < end) {
        float4 m = make_float4(-1e30f, -1e30f, -1e30f, -1e30f);
        for (int i = beg + lane; i < end; i += 32) {
            float4 s = *reinterpret_cast<const float4*>(&scores[(size_t)i * 4]);
            m.x = fmaxf(m.x, s.x); m.y = fmaxf(m.y, s.y);
            m.z = fmaxf(m.z, s.z); m.w = fmaxf(m.w, s.w);
        }
#pragma unroll
        for (int o = 16; o; o >>= 1) {
            m.x = fmaxf(m.x, __shfl_xor_sync(0xffffffffu, m.x, o));
            m.y = fmaxf(m.y, __shfl_xor_sync(0xffffffffu, m.y, o));
            m.z = fmaxf(m.z, __shfl_xor_sync(0xffffffffu, m.z, o));
            m.w = fmaxf(m.w, __shfl_xor_sync(0xffffffffu, m.w, o));
        }
        float4 d = make_float4(0.f, 0.f, 0.f, 0.f);
        for (int i = beg + lane; i < end; i += 32) {
            float4 s = *reinterpret_cast<const float4*>(&scores[(size_t)i * 4]);
            d.x += __expf(s.x - m.x); d.y += __expf(s.y - m.y);
            d.z += __expf(s.z - m.z); d.w += __expf(s.w - m.w);
        }
#pragma unroll
        for (int o = 16; o; o >>= 1) {
            d.x += __shfl_xor_sync(0xffffffffu, d.x, o);
            d.y += __shfl_xor_sync(0xffffffffu, d.y, o);
            d.z += __shfl_xor_sync(0xffffffffu, d.z, o);
            d.w += __shfl_xor_sync(0xffffffffu, d.w, o);
        }
        float4 inv = make_float4(1.f / (d.x + 1e-9f), 1.f / (d.y + 1e-9f),
                                 1.f / (d.z + 1e-9f), 1.f / (d.w + 1e-9f));

        for (int c0 = beg; c0 < end; c0 += 32) {
            int i = c0 + lane;
            if (i < end) {
                float4 s = *reinterpret_cast<const float4*>(&scores[(size_t)i * 4]);
                float mk = mask[eid[i]];
                float4 a4;
                a4.x = __expf(s.x - m.x) * inv.x * mk;
                a4.y = __expf(s.y - m.y) * inv.y * mk;
                a4.z = __expf(s.z - m.z) * inv.z * mk;
                a4.w = __expf(s.w - m.w) * inv.w * mk;
                *reinterpret_cast<float4*>(&sm_a[w][lane][0]) = a4;
                sm_s[w][lane] = srcc[i];
            }
            __syncwarp();
            int cl = min(32, end - c0);
            int j = 0;
            for (; j + 1 < cl; j += 2) {
                float a0 = sm_a[w][j][h];
                float a1 = sm_a[w][j + 1][h];
                const float4* f0p = reinterpret_cast<const float4*>(
                    &fn[(size_t)sm_s[w][j] * 256 + lane * 8]);
                const float4* f1p = reinterpret_cast<const float4*>(
                    &fn[(size_t)sm_s[w][j + 1] * 256 + lane * 8]);
                float4 f00 = f0p[0], f01 = f0p[1];
                float4 f10 = f1p[0], f11 = f1p[1];
                acc0.x += a0 * f00.x; acc0.y += a0 * f00.y;
                acc0.z += a0 * f00.z; acc0.w += a0 * f00.w;
                acc1.x += a0 * f01.x; acc1.y += a0 * f01.y;
                acc1.z += a0 * f01.z; acc1.w += a0 * f01.w;
                acc0.x += a1 * f10.x; acc0.y += a1 * f10.y;
                acc0.z += a1 * f10.z; acc0.w += a1 * f10.w;
                acc1.x += a1 * f11.x; acc1.y += a1 * f11.y;
                acc1.z += a1 * f11.z; acc1.w += a1 * f11.w;
            }
            if (j < cl) {
                float a0 = sm_a[w][j][h];
                const float4* fp = reinterpret_cast<const float4*>(
                    &fn[(size_t)sm_s[w][j] * 256 + lane * 8]);
                float4 f0 = fp[0], f1 = fp[1];
                acc0.x += a0 * f0.x; acc0.y += a0 * f0.y;
                acc0.z += a0 * f0.z; acc0.w += a0 * f0.w;
                acc1.x += a0 * f1.x; acc1.y += a0 * f1.y;
                acc1.z += a0 * f1.z; acc1.w += a0 * f1.w;
            }
            __syncwarp();
        }
    }
    float4* op = reinterpret_cast<float4*>(&outp[(size_t)n * 256 + lane * 8]);
    op[0] = acc0;
    op[1] = acc1;
}

// ---------------- readout gather + final outputs ----------------
__global__ void gather_kernel(
    const float* __restrict__ ui0, const float* __restrict__ ui1,
    const float* __restrict__ sg0, const float* __restrict__ sg1,
    const int* __restrict__ user, const int* __restrict__ item,
    const int* __restrict__ subg,
    float* __restrict__ uix, float* __restrict__ sgx)
{
    int b = blockIdx.x;
    int t = threadIdx.x;
    int u = user[b], it = item[b], s = subg[b];
    float v;
    if (t < 64)       v = ui0[(size_t)u * 64 + t];
    else if (t < 128) v = ui1[(size_t)u * 64 + t - 64];
    else if (t < 192) v = ui0[(size_t)it * 64 + t - 128];
    else              v = ui1[(size_t)it * 64 + t - 192];
    uix[(size_t)b * 256 + t] = v;
    if (t < 128) {
        float w = (t < 64) ? sg0[(size_t)s * 64 + t] : sg1[(size_t)s * 64 + t - 64];
        sgx[(size_t)b * 128 + t] = w;
    }
}

__global__ void final_out_kernel(
    const float* __restrict__ hui, const float* __restrict__ hsg,
    const float* __restrict__ w2ui, const float* __restrict__ b2ui,
    const float* __restrict__ w2sg, const float* __restrict__ b2sg,
    float* __restrict__ out)
{
    int r = blockIdx.x * 8 + (threadIdx.x >> 5);
    int lane = threadIdx.x & 31;
    if (r >= BB) return;
    float su = 0.f, ss = 0.f;
#pragma unroll
    for (int k = lane; k < 128; k += 32) {
        su += hui[(size_t)r * 128 + k] * w2ui[k];
        ss += hsg[(size_t)r * 128 + k] * w2sg[k];
    }
#pragma unroll
    for (int o = 16; o; o >>= 1) {
        su += __shfl_xor_sync(0xffffffffu, su, o);
        ss += __shfl_xor_sync(0xffffffffu, ss, o);
    }
    if (lane == 0) {
        out[r]      = 1.f / (1.f + expf(-(ss + b2sg[0])));   // sg_out
        out[BB + r] = 1.f / (1.f + expf(-(su + b2ui[0])));   // ui_out
    }
}

// ---------------- host orchestration ----------------
static void gemm(const float* A, const float* W, const float* bias, float* C,
                 int M, int N, int K, int act) {
    dim3 g((M + 127) / 128, N / 64);
    gemm_act_kernel<<<g, 256>>>(A, W, bias, C, M, N, K, act);
}

extern "C" void kernel_launch(void* const* d_in, const int* in_sizes, int n_in,
                              void* d_out, int out_size) {
    const float* x        = (const float*)d_in[0];
    const float* efeat    = (const float*)d_in[1];
    const float* efeat2   = (const float*)d_in[2];
    const float* mask1    = (const float*)d_in[3];
    const float* mask2    = (const float*)d_in[4];
    const int*   src      = (const int*)d_in[5];
    const int*   dst      = (const int*)d_in[6];
    const int*   user     = (const int*)d_in[7];
    const int*   item     = (const int*)d_in[8];
    const int*   subg     = (const int*)d_in[9];
    const float* loc_wni  = (const float*)d_in[10];
    const float* loc_wnj  = (const float*)d_in[11];
    const float* loc_we   = (const float*)d_in[12];
    const float* loc_attn = (const float*)d_in[13];
    const float* loc_wnode= (const float*)d_in[14];
    const float* agg1_w   = (const float*)d_in[15];
    const float* agg1_b   = (const float*)d_in[16];
    const float* glob_wni = (const float*)d_in[17];
    const float* glob_wnj = (const float*)d_in[18];
    const float* glob_we  = (const float*)d_in[19];
    const float* glob_attn= (const float*)d_in[20];
    const float* glob_wnode=(const float*)d_in[21];
    const float* agg2_w   = (const float*)d_in[22];
    const float* agg2_b   = (const float*)d_in[23];
    const float* w1_ui    = (const float*)d_in[24];
    const float* b1_ui    = (const float*)d_in[25];
    const float* w1_sg    = (const float*)d_in[26];
    const float* b1_sg    = (const float*)d_in[27];
    const float* w2_ui    = (const float*)d_in[28];
    const float* b2_ui    = (const float*)d_in[29];
    const float* w2_sg    = (const float*)d_in[30];
    const float* b2_sg    = (const float*)d_in[31];

    float *p_xwi, *p_xwj, *p_fn, *p_agg, *p_scores;
    float *p_ui0, *p_ui1, *p_sg0, *p_sg1, *p_uix, *p_sgx, *p_hui, *p_hsg;
    int *p_deg, *p_off, *p_cur, *p_eid, *p_epos, *p_srcc;
    cudaGetSymbolAddress((void**)&p_xwi, g_xwi);
    cudaGetSymbolAddress((void**)&p_xwj, g_xwj);
    cudaGetSymbolAddress((void**)&p_fn,  g_fn);
    cudaGetSymbolAddress((void**)&p_agg, g_agg);
    cudaGetSymbolAddress((void**)&p_scores, g_scores);
    cudaGetSymbolAddress((void**)&p_ui0, g_ui0);
    cudaGetSymbolAddress((void**)&p_ui1, g_ui1);
    cudaGetSymbolAddress((void**)&p_sg0, g_sg0);
    cudaGetSymbolAddress((void**)&p_sg1, g_sg1);
    cudaGetSymbolAddress((void**)&p_uix, g_uix);
    cudaGetSymbolAddress((void**)&p_sgx, g_sgx);
    cudaGetSymbolAddress((void**)&p_hui, g_hui);
    cudaGetSymbolAddress((void**)&p_hsg, g_hsg);
    cudaGetSymbolAddress((void**)&p_deg, g_deg);
    cudaGetSymbolAddress((void**)&p_off, g_off);
    cudaGetSymbolAddress((void**)&p_cur, g_cur);
    cudaGetSymbolAddress((void**)&p_eid, g_eid);
    cudaGetSymbolAddress((void**)&p_epos, g_epos);
    cudaGetSymbolAddress((void**)&p_srcc, g_srcc);

    // CSR by dst (+ inverse map + src in CSR order)
    cudaMemsetAsync(p_deg, 0, NN * sizeof(int));
    cudaMemsetAsync(p_cur, 0, NN * sizeof(int));
    hist_kernel<<<(NE + 255) / 256, 256>>>(dst, p_deg);
    scan_kernel<<<1, 1024>>>(p_deg, p_off, NN);
    fill_kernel<<<(NE + 255) / 256, 256>>>(dst, src, p_off, p_cur, p_eid, p_epos, p_srcc);

    struct Stage {
        const float* hin; const float* ef; int Ke; const float* mask;
        const float* wni; const float* wnj; const float* we; const float* attn;
        const float* wnode; const float* aggw; const float* aggb; int act; float* hout;
    };
    Stage st[4] = {
        { x,     efeat,  16, mask1, loc_wni,           loc_wnj,           loc_we,           loc_attn,         loc_wnode,           agg1_w,          agg1_b,       1, p_ui0 },
        { p_ui0, efeat2, 64, mask2, glob_wni,          glob_wnj,          glob_we,          glob_attn,        glob_wnode,          agg2_w,          agg2_b,       2, p_sg0 },
        { p_sg0, efeat,  16, mask1, loc_wni  + 64*128, loc_wnj  + 64*128, loc_we  + 16*128, loc_attn  + 128,  loc_wnode  + 64*256, agg1_w + 256*64, agg1_b + 64,  1, p_ui1 },
        { p_ui1, efeat2, 64, mask2, glob_wni + 64*128, glob_wnj + 64*128, glob_we + 64*128, glob_attn + 128,  glob_wnode + 64*256, agg2_w + 256*64, agg2_b + 64,  2, p_sg1 },
    };

    for (int s = 0; s < 4; s++) {
        node_gemm_kernel<<<dim3((NN + 127) / 128, 8), 256>>>(
            st[s].hin, st[s].wni, st[s].wnj, st[s].wnode, p_xwi, p_xwj, p_fn, NN);
        edge_score_fused_kernel<<<(NE + 63) / 64, 256>>>(
            st[s].ef, st[s].we, st[s].attn, src, dst, p_epos, p_xwi, p_xwj, p_scores, st[s].Ke);
        attn_agg_kernel<<<(NN + 7) / 8, 256>>>(p_scores, st[s].mask, p_srcc, p_fn, p_off, p_eid, p_agg);
        gemm(p_agg, st[s].aggw, st[s].aggb, st[s].hout, NN, 64, 256, st[s].act);
    }

    gather_kernel<<<BB, 256>>>(p_ui0, p_ui1, p_sg0, p_sg1, user, item, subg, p_uix, p_sgx);
    gemm(p_uix, w1_ui, b1_ui, p_hui, BB, 128, 256, 3);
    gemm(p_sgx, w1_sg, b1_sg, p_hsg, BB, 128, 128, 3);
    final_out_kernel<<<BB / 8, 256>>>(p_hui, p_hsg, w2_ui, b2_ui, w2_sg, b2_sg, (float*)d_out);
}

// round 15
// speedup vs baseline: 1.2139x; 1.0067x over previous
#include <cuda_runtime.h>
#include <math.h>

#define NN 50000
#define NE 320000
#define BB 4096

typedef unsigned long long ull;

__device__ __forceinline__ ull ffma2(ull a, ull b, ull c) {
    ull d;
    asm("fma.rn.f32x2 %0, %1, %2, %3;" : "=l"(d) : "l"(a), "l"(b), "l"(c));
    return d;
}
__device__ __forceinline__ ull dup2(float x) {
    ull d;
    asm("mov.b64 %0, {%1, %1};" : "=l"(d) : "f"(x));
    return d;
}
__device__ __forceinline__ float2 unpack2(ull v) {
    float2 r;
    asm("mov.b64 {%0, %1}, %2;" : "=f"(r.x), "=f"(r.y) : "l"(v));
    return r;
}
__device__ __forceinline__ unsigned s2u(const void* p) {
    unsigned a;
    asm("{ .reg .u64 t; cvta.to.shared.u64 t, %1; cvt.u32.u64 %0, t; }" : "=r"(a) : "l"(p));
    return a;
}
__device__ __forceinline__ void cpa4(const void* smem, const void* gmem, int ok) {
    asm volatile("cp.async.ca.shared.global [%0], [%1], 4, %2;"
                 :: "r"(s2u(smem)), "l"(gmem), "r"(ok ? 4 : 0));
}
__device__ __forceinline__ void cpa16(const void* smem, const void* gmem) {
    asm volatile("cp.async.cg.shared.global [%0], [%1], 16;"
                 :: "r"(s2u(smem)), "l"(gmem));
}
#define CP_COMMIT() asm volatile("cp.async.commit_group;" ::: "memory")
#define CP_WAIT0()  asm volatile("cp.async.wait_group 0;" ::: "memory")

// ---------------- scratch (device globals) ----------------
__device__ float g_xwi[NN * 128];
__device__ float g_xwj[NN * 128];
__device__ float g_fn [NN * 256];
__device__ float g_agg[NN * 256];
__device__ float g_scores[NE * 4];   // CSR-ordered
__device__ float g_ui0[NN * 64];
__device__ float g_ui1[NN * 64];
__device__ float g_sg0[NN * 64];
__device__ float g_sg1[NN * 64];
__device__ float g_uix[BB * 256];
__device__ float g_sgx[BB * 128];
__device__ float g_hui[BB * 128];
__device__ float g_hsg[BB * 128];
__device__ int   g_deg[NN];
__device__ int   g_off[NN + 1];
__device__ int   g_cur[NN];
__device__ int   g_eid[NE];
__device__ int   g_epos[NE];
__device__ int   g_srcc[NE];         // src in CSR order

// ---------------- CSR build ----------------
__global__ void hist_kernel(const int* __restrict__ dst, int* __restrict__ deg) {
    int e = blockIdx.x * blockDim.x + threadIdx.x;
    if (e < NE) atomicAdd(&deg[dst[e]], 1);
}

__global__ void scan_kernel(const int* __restrict__ deg, int* __restrict__ off,
                            int* __restrict__ cur, int n) {
    __shared__ int warp_sums[32];
    __shared__ int carry_s;
    const int tid = threadIdx.x;
    const int lane = tid & 31;
    const int wid = tid >> 5;
    if (tid == 0) carry_s = 0;
    __syncthreads();
    for (int base = 0; base < n; base += 1024) {
        int i = base + tid;
        int v = (i < n) ? deg[i] : 0;
        int x = v;
#pragma unroll
        for (int o = 1; o < 32; o <<= 1) {
            int t = __shfl_up_sync(0xffffffffu, x, o);
            if (lane >= o) x += t;
        }
        if (lane == 31) warp_sums[wid] = x;
        __syncthreads();
        if (wid == 0) {
            int s = warp_sums[lane];
#pragma unroll
            for (int o = 1; o < 32; o <<= 1) {
                int t = __shfl_up_sync(0xffffffffu, s, o);
                if (lane >= o) s += t;
            }
            warp_sums[lane] = s;
        }
        __syncthreads();
        int woff = (wid > 0) ? warp_sums[wid - 1] : 0;
        int carry = carry_s;
        if (i < n) { off[i] = carry + woff + x - v; cur[i] = 0; }
        int total = warp_sums[31];
        __syncthreads();
        if (tid == 0) carry_s = carry + total;
        __syncthreads();
    }
    if (threadIdx.x == 0) off[n] = carry_s;
}

__global__ void fill_kernel(const int* __restrict__ dst, const int* __restrict__ src,
                            const int* __restrict__ off,
                            int* __restrict__ cur, int* __restrict__ eid,
                            int* __restrict__ epos, int* __restrict__ srcc) {
    int e = blockIdx.x * blockDim.x + threadIdx.x;
    if (e < NE) {
        int d = dst[e];
        int p = atomicAdd(&cur[d], 1);
        int pos = off[d] + p;
        eid[pos] = e;
        epos[e] = pos;
        srcc[pos] = src[e];
    }
}

// ---------------- generic GEMM (f32x2 8x4, square warp tile, cp.async dbuf) ------
__global__ __launch_bounds__(256, 2) void gemm_act_kernel(
    const float* __restrict__ A, const float* __restrict__ W,
    const float* __restrict__ bias, float* __restrict__ C,
    int M, int N, int K, int act)
{
    __shared__ __align__(16) float sA[2][16][132];
    __shared__ __align__(16) float sB[2][16][64];
    const int bm = blockIdx.x * 128;
    const int bn = blockIdx.y * 64;
    const int tid = threadIdx.x;
    const int lane = tid & 31;
    const int wp = tid >> 5;
    const int tx = ((wp >> 2) << 3) | (lane & 7);
    const int ty = ((wp & 3) << 2) | (lane >> 3);
    const int la_m = tid >> 4, la_k = tid & 15;
    const int lb_k = tid >> 4, lb_n = (tid & 15) * 4;
    const int nkb = K >> 4;

    ull acc2[4][4];
#pragma unroll
    for (int r = 0; r < 4; r++)
#pragma unroll
        for (int c = 0; c < 4; c++) acc2[r][c] = 0ull;

    auto issue = [&](int kb) {
        int p = kb & 1, k0 = kb << 4;
#pragma unroll
        for (int j = 0; j < 8; j++) {
            int gm = bm + la_m + 16 * j;
            int ok = gm < M;
            cpa4(&sA[p][la_k][la_m + 16 * j],
                 A + (size_t)(ok ? gm : 0) * K + k0 + la_k, ok);
        }
        cpa16(&sB[p][lb_k][lb_n], W + (size_t)(k0 + lb_k) * N + bn + lb_n);
        CP_COMMIT();
    };
    issue(0);
    for (int kb = 0; kb < nkb; kb++) {
        CP_WAIT0();
        __syncthreads();
        if (kb + 1 < nkb) issue(kb + 1);
        const int p = kb & 1;
#pragma unroll
        for (int kk = 0; kk < 16; kk++) {
            float4 b4 = *reinterpret_cast<const float4*>(&sB[p][kk][tx * 4]);
            ull bd[4] = {dup2(b4.x), dup2(b4.y), dup2(b4.z), dup2(b4.w)};
            ulonglong2 a01 = *reinterpret_cast<const ulonglong2*>(&sA[p][kk][ty * 8]);
            ulonglong2 a23 = *reinterpret_cast<const ulonglong2*>(&sA[p][kk][ty * 8 + 4]);
            ull ap[4] = {a01.x, a01.y, a23.x, a23.y};
#pragma unroll
            for (int rp = 0; rp < 4; rp++)
#pragma unroll
                for (int c = 0; c < 4; c++)
                    acc2[rp][c] = ffma2(ap[rp], bd[c], acc2[rp][c]);
        }
    }
#pragma unroll
    for (int rp = 0; rp < 4; rp++) {
        float2 u0 = unpack2(acc2[rp][0]);
        float2 u1 = unpack2(acc2[rp][1]);
        float2 u2 = unpack2(acc2[rp][2]);
        float2 u3 = unpack2(acc2[rp][3]);
        float rowv[2][4] = {{u0.x, u1.x, u2.x, u3.x}, {u0.y, u1.y, u2.y, u3.y}};
#pragma unroll
        for (int l = 0; l < 2; l++) {
            int gm = bm + ty * 8 + rp * 2 + l;
            if (gm >= M) continue;
            float4 v4;
            float* vp = &v4.x;
#pragma unroll
            for (int c = 0; c < 4; c++) {
                int gn = bn + tx * 4 + c;
                float v = rowv[l][c];
                if (bias) v += bias[gn];
                if (act == 1) v = (v > 0.f) ? v : (expf(v) - 1.f);
                else if (act == 2) v = (v > 0.f) ? v : 0.01f * v;
                else if (act == 3) v = fmaxf(v, 0.f);
                vp[c] = v;
            }
            *reinterpret_cast<float4*>(&C[(size_t)gm * N + bn + tx * 4]) = v4;
        }
    }
}

// ---------------- fused node GEMM: full-K A resident, 2 slices per block ---------
// grid.y = 4: 0 -> xwi, 1 -> xwj, 2 -> fn[0:128), 3 -> fn[128:256)
__global__ __launch_bounds__(256, 2) void node_gemm_kernel(
    const float* __restrict__ A,
    const float* __restrict__ wni, const float* __restrict__ wnj,
    const float* __restrict__ wnode,
    float* __restrict__ xwi, float* __restrict__ xwj, float* __restrict__ fn,
    int M)
{
    __shared__ __align__(16) float sA[64][132];
    __shared__ __align__(16) float sB[2][16][64];
    const int by = blockIdx.y;
    const float* W; float* C; int ldW, ldC, base;
    if (by == 0)      { W = wni;   C = xwi; ldW = 128; ldC = 128; base = 0; }
    else if (by == 1) { W = wnj;   C = xwj; ldW = 128; ldC = 128; base = 0; }
    else if (by == 2) { W = wnode; C = fn;  ldW = 256; ldC = 256; base = 0; }
    else              { W = wnode; C = fn;  ldW = 256; ldC = 256; base = 128; }

    const int bm = blockIdx.x * 128;
    const int tid = threadIdx.x;
    const int lane = tid & 31;
    const int wp = tid >> 5;
    const int tx = ((wp >> 2) << 3) | (lane & 7);
    const int ty = ((wp & 3) << 2) | (lane >> 3);
    const int la_m = tid >> 4, la_k = tid & 15;
    const int lb_k = tid >> 4, lb_n = (tid & 15) * 4;

    // load full A tile (128 x 64) once
#pragma unroll
    for (int kb = 0; kb < 4; kb++)
#pragma unroll
        for (int j = 0; j < 8; j++) {
            int gm = bm + la_m + 16 * j;
            int ok = gm < M;
            cpa4(&sA[kb * 16 + la_k][la_m + 16 * j],
                 A + (size_t)(ok ? gm : 0) * 64 + kb * 16 + la_k, ok);
        }
    CP_COMMIT();

    auto issueB = [&](int t) {
        int p = t & 1, s = t >> 2, kb = t & 3;
        int coloff = base + s * 64;
        cpa16(&sB[p][lb_k][lb_n], W + (size_t)(kb * 16 + lb_k) * ldW + coloff + lb_n);
        CP_COMMIT();
    };
    issueB(0);

    ull acc2[4][4];
#pragma unroll
    for (int r = 0; r < 4; r++)
#pragma unroll
        for (int c = 0; c < 4; c++) acc2[r][c] = 0ull;

#pragma unroll
    for (int t = 0; t < 8; t++) {
        CP_WAIT0();
        __syncthreads();
        if (t + 1 < 8) issueB(t + 1);
        const int p = t & 1, kb = t & 3;
#pragma unroll
        for (int kk = 0; kk < 16; kk++) {
            float4 b4 = *reinterpret_cast<const float4*>(&sB[p][kk][tx * 4]);
            ull bd[4] = {dup2(b4.x), dup2(b4.y), dup2(b4.z), dup2(b4.w)};
            ulonglong2 a01 = *reinterpret_cast<const ulonglong2*>(&sA[kb * 16 + kk][ty * 8]);
            ulonglong2 a23 = *reinterpret_cast<const ulonglong2*>(&sA[kb * 16 + kk][ty * 8 + 4]);
            ull ap[4] = {a01.x, a01.y, a23.x, a23.y};
#pragma unroll
            for (int rp = 0; rp < 4; rp++)
#pragma unroll
                for (int c = 0; c < 4; c++)
                    acc2[rp][c] = ffma2(ap[rp], bd[c], acc2[rp][c]);
        }
        if ((t & 3) == 3) {
            int coloff = base + (t >> 2) * 64;
#pragma unroll
            for (int rp = 0; rp < 4; rp++) {
                float2 u0 = unpack2(acc2[rp][0]);
                float2 u1 = unpack2(acc2[rp][1]);
                float2 u2 = unpack2(acc2[rp][2]);
                float2 u3 = unpack2(acc2[rp][3]);
                int gm0 = bm + ty * 8 + rp * 2;
                if (gm0 < M) {
                    float4 v4 = make_float4(u0.x, u1.x, u2.x, u3.x);
                    *reinterpret_cast<float4*>(&C[(size_t)gm0 * ldC + coloff + tx * 4]) = v4;
                }
                if (gm0 + 1 < M) {
                    float4 v4 = make_float4(u0.y, u1.y, u2.y, u3.y);
                    *reinterpret_cast<float4*>(&C[(size_t)(gm0 + 1) * ldC + coloff + tx * 4]) = v4;
                }
#pragma unroll
                for (int c = 0; c < 4; c++) acc2[rp][c] = 0ull;
            }
        }
    }
}

// ---------------- fused edge GEMM + attention score (f32x2, square warp tile) ----
__global__ __launch_bounds__(256, 2) void edge_score_fused_kernel(
    const float* __restrict__ efeat, const float* __restrict__ we,
    const float* __restrict__ attn,
    const int* __restrict__ src, const int* __restrict__ dst,
    const int* __restrict__ epos,
    const float* __restrict__ xwi, const float* __restrict__ xwj,
    float* __restrict__ scores, int Ke)
{
    __shared__ __align__(16) float sE[2][16][68];
    __shared__ __align__(16) float sW[2][16][128];
    __shared__ float s_attn[128];
    __shared__ int   s_src[64], s_dst[64], s_ep[64];

    const int tid = threadIdx.x;
    const int e0 = blockIdx.x * 64;
    const int lane = tid & 31;
    const int wp = tid >> 5;
    const int tx = ((wp >> 1) << 2) | (lane & 3);
    const int ty = ((wp & 1) << 3) | (lane >> 2);
    const int le_e = tid >> 4, le_k = tid & 15;
    const int lw_r0 = tid >> 5, lw_c0 = (tid & 31) * 4;
    const int nkb = Ke >> 4;

    if (tid < 128) s_attn[tid] = attn[tid];
    if (tid < 64) {
        int ge = e0 + tid;
        s_src[tid] = (ge < NE) ? src[ge] : 0;
        s_dst[tid] = (ge < NE) ? dst[ge] : 0;
        s_ep[tid]  = (ge < NE) ? epos[ge] : 0;
    }

    ull acc2[2][8];
#pragma unroll
    for (int r = 0; r < 2; r++)
#pragma unroll
        for (int c = 0; c < 8; c++) acc2[r][c] = 0ull;

    auto issue = [&](int kb) {
        int p = kb & 1, k0 = kb << 4;
#pragma unroll
        for (int j = 0; j < 4; j++) {
            int e = le_e + 16 * j;
            int ge = e0 + e;
            int ok = ge < NE;
            cpa4(&sE[p][le_k][e],
                 efeat + (size_t)(ok ? ge : 0) * Ke + k0 + le_k, ok);
        }
        cpa16(&sW[p][lw_r0][lw_c0],     we + (size_t)(k0 + lw_r0) * 128 + lw_c0);
        cpa16(&sW[p][lw_r0 + 8][lw_c0], we + (size_t)(k0 + lw_r0 + 8) * 128 + lw_c0);
        CP_COMMIT();
    };
    issue(0);
    for (int kb = 0; kb < nkb; kb++) {
        CP_WAIT0();
        __syncthreads();
        if (kb + 1 < nkb) issue(kb + 1);
        const int p = kb & 1;
#pragma unroll
        for (int kk = 0; kk < 16; kk++) {
            ulonglong2 a01 = *reinterpret_cast<const ulonglong2*>(&sE[p][kk][ty * 4]);
            ull ap[2] = {a01.x, a01.y};
            float4 w0 = *reinterpret_cast<const float4*>(&sW[p][kk][tx * 8]);
            float4 w1 = *reinterpret_cast<const float4*>(&sW[p][kk][tx * 8 + 4]);
            ull bd[8] = {dup2(w0.x), dup2(w0.y), dup2(w0.z), dup2(w0.w),
                         dup2(w1.x), dup2(w1.y), dup2(w1.z), dup2(w1.w)};
#pragma unroll
            for (int rp = 0; rp < 2; rp++)
#pragma unroll
                for (int c = 0; c < 8; c++)
                    acc2[rp][c] = ffma2(ap[rp], bd[c], acc2[rp][c]);
        }
    }

    float accr[4][8];
#pragma unroll
    for (int rp = 0; rp < 2; rp++)
#pragma unroll
        for (int c = 0; c < 8; c++) {
            float2 u = unpack2(acc2[rp][c]);
            accr[rp * 2][c]     = u.x;
            accr[rp * 2 + 1][c] = u.y;
        }

    const int h = tx >> 2;
    float at[8];
#pragma unroll
    for (int c = 0; c < 8; c++) at[c] = s_attn[tx * 8 + c];

#pragma unroll
    for (int r = 0; r < 4; r++) {
        int eg = ty * 4 + r;
        int ge = e0 + eg;
        float p = 0.f;
        if (ge < NE) {
            const float* gi = &xwi[(size_t)s_src[eg] * 128 + tx * 8];
            const float* gj = &xwj[(size_t)s_dst[eg] * 128 + tx * 8];
            float4 gi0 = *reinterpret_cast<const float4*>(gi);
            float4 gi1 = *reinterpret_cast<const float4*>(gi + 4);
            float4 gj0 = *reinterpret_cast<const float4*>(gj);
            float4 gj1 = *reinterpret_cast<const float4*>(gj + 4);
            float f[8];
            f[0] = accr[r][0] + gi0.x + gj0.x;  f[1] = accr[r][1] + gi0.y + gj0.y;
            f[2] = accr[r][2] + gi0.z + gj0.z;  f[3] = accr[r][3] + gi0.w + gj0.w;
            f[4] = accr[r][4] + gi1.x + gj1.x;  f[5] = accr[r][5] + gi1.y + gj1.y;
            f[6] = accr[r][6] + gi1.z + gj1.z;  f[7] = accr[r][7] + gi1.w + gj1.w;
#pragma unroll
            for (int c = 0; c < 8; c++) {
                float v = f[c];
                v = (v > 0.f) ? v : 0.2f * v;
                p += v * at[c];
            }
        }
        p += __shfl_xor_sync(0xffffffffu, p, 1);
        p += __shfl_xor_sync(0xffffffffu, p, 2);
        if ((lane & 3) == 0 && ge < NE)
            scores[(size_t)s_ep[eg] * 4 + h] = p;
    }
}

// ---------------- fused softmax + aggregation (CSR-ordered scores/src) ----------
__global__ __launch_bounds__(256) void attn_agg_kernel(
    const float* __restrict__ scores, const float* __restrict__ mask,
    const int* __restrict__ srcc, const float* __restrict__ fn,
    const int* __restrict__ off, const int* __restrict__ eid,
    float* __restrict__ outp)
{
    __shared__ __align__(16) float sm_a[8][32][4];
    __shared__ int sm_s[8][32];
    int w = threadIdx.x >> 5;
    int lane = threadIdx.x & 31;
    int n = blockIdx.x * 8 + w;
    if (n >= NN) return;
    int beg = off[n], end = off[n + 1];

    float4 acc0 = make_float4(0.f, 0.f, 0.f, 0.f);
    float4 acc1 = make_float4(0.f, 0.f, 0.f, 0.f);
    const int h = lane >> 3;

    if (beg < end) {
        float4 m = make_float4(-1e30f, -1e30f, -1e30f, -1e30f);
        for (int i = beg + lane; i < end; i += 32) {
            float4 s = *reinterpret_cast<const float4*>(&scores[(size_t)i * 4]);
            m.x = fmaxf(m.x, s.x); m.y = fmaxf(m.y, s.y);
            m.z = fmaxf(m.z, s.z); m.w = fmaxf(m.w, s.w);
        }
#pragma unroll
        for (int o = 16; o; o >>= 1) {
            m.x = fmaxf(m.x, __shfl_xor_sync(0xffffffffu, m.x, o));
            m.y = fmaxf(m.y, __shfl_xor_sync(0xffffffffu, m.y, o));
            m.z = fmaxf(m.z, __shfl_xor_sync(0xffffffffu, m.z, o));
            m.w = fmaxf(m.w, __shfl_xor_sync(0xffffffffu, m.w, o));
        }
        float4 d = make_float4(0.f, 0.f, 0.f, 0.f);
        for (int i = beg + lane; i < end; i += 32) {
            float4 s = *reinterpret_cast<const float4*>(&scores[(size_t)i * 4]);
            d.x += __expf(s.x - m.x); d.y += __expf(s.y - m.y);
            d.z += __expf(s.z - m.z); d.w += __expf(s.w - m.w);
        }
#pragma unroll
        for (int o = 16; o; o >>= 1) {
            d.x += __shfl_xor_sync(0xffffffffu, d.x, o);
            d.y += __shfl_xor_sync(0xffffffffu, d.y, o);
            d.z += __shfl_xor_sync(0xffffffffu, d.z, o);
            d.w += __shfl_xor_sync(0xffffffffu, d.w, o);
        }
        float4 inv = make_float4(1.f / (d.x + 1e-9f), 1.f / (d.y + 1e-9f),
                                 1.f / (d.z + 1e-9f), 1.f / (d.w + 1e-9f));

        for (int c0 = beg; c0 < end; c0 += 32) {
            int i = c0 + lane;
            if (i < end) {
                float4 s = *reinterpret_cast<const float4*>(&scores[(size_t)i * 4]);
                float mk = mask[eid[i]];
                float4 a4;
                a4.x = __expf(s.x - m.x) * inv.x * mk;
                a4.y = __expf(s.y - m.y) * inv.y * mk;
                a4.z = __expf(s.z - m.z) * inv.z * mk;
                a4.w = __expf(s.w - m.w) * inv.w * mk;
                *reinterpret_cast<float4*>(&sm_a[w][lane][0]) = a4;
                sm_s[w][lane] = srcc[i];
            }
            __syncwarp();
            int cl = min(32, end - c0);
            int j = 0;
            for (; j + 1 < cl; j += 2) {
                float a0 = sm_a[w][j][h];
                float a1 = sm_a[w][j + 1][h];
                const float4* f0p = reinterpret_cast<const float4*>(
                    &fn[(size_t)sm_s[w][j] * 256 + lane * 8]);
                const float4* f1p = reinterpret_cast<const float4*>(
                    &fn[(size_t)sm_s[w][j + 1] * 256 + lane * 8]);
                float4 f00 = f0p[0], f01 = f0p[1];
                float4 f10 = f1p[0], f11 = f1p[1];
                acc0.x += a0 * f00.x; acc0.y += a0 * f00.y;
                acc0.z += a0 * f00.z; acc0.w += a0 * f00.w;
                acc1.x += a0 * f01.x; acc1.y += a0 * f01.y;
                acc1.z += a0 * f01.z; acc1.w += a0 * f01.w;
                acc0.x += a1 * f10.x; acc0.y += a1 * f10.y;
                acc0.z += a1 * f10.z; acc0.w += a1 * f10.w;
                acc1.x += a1 * f11.x; acc1.y += a1 * f11.y;
                acc1.z += a1 * f11.z; acc1.w += a1 * f11.w;
            }
            if (j < cl) {
                float a0 = sm_a[w][j][h];
                const float4* fp = reinterpret_cast<const float4*>(
                    &fn[(size_t)sm_s[w][j] * 256 + lane * 8]);
                float4 f0 = fp[0], f1 = fp[1];
                acc0.x += a0 * f0.x; acc0.y += a0 * f0.y;
                acc0.z += a0 * f0.z; acc0.w += a0 * f0.w;
                acc1.x += a0 * f1.x; acc1.y += a0 * f1.y;
                acc1.z += a0 * f1.z; acc1.w += a0 * f1.w;
            }
            __syncwarp();
        }
    }
    float4* op = reinterpret_cast<float4*>(&outp[(size_t)n * 256 + lane * 8]);
    op[0] = acc0;
    op[1] = acc1;
}

// ---------------- readout gather + final outputs ----------------
__global__ void gather_kernel(
    const float* __restrict__ ui0, const float* __restrict__ ui1,
    const float* __restrict__ sg0, const float* __restrict__ sg1,
    const int* __restrict__ user, const int* __restrict__ item,
    const int* __restrict__ subg,
    float* __restrict__ uix, float* __restrict__ sgx)
{
    int b = blockIdx.x;
    int t = threadIdx.x;
    int u = user[b], it = item[b], s = subg[b];
    float v;
    if (t < 64)       v = ui0[(size_t)u * 64 + t];
    else if (t < 128) v = ui1[(size_t)u * 64 + t - 64];
    else if (t < 192) v = ui0[(size_t)it * 64 + t - 128];
    else              v = ui1[(size_t)it * 64 + t - 192];
    uix[(size_t)b * 256 + t] = v;
    if (t < 128) {
        float w = (t < 64) ? sg0[(size_t)s * 64 + t] : sg1[(size_t)s * 64 + t - 64];
        sgx[(size_t)b * 128 + t] = w;
    }
}

__global__ void final_out_kernel(
    const float* __restrict__ hui, const float* __restrict__ hsg,
    const float* __restrict__ w2ui, const float* __restrict__ b2ui,
    const float* __restrict__ w2sg, const float* __restrict__ b2sg,
    float* __restrict__ out)
{
    int r = blockIdx.x * 8 + (threadIdx.x >> 5);
    int lane = threadIdx.x & 31;
    if (r >= BB) return;
    float su = 0.f, ss = 0.f;
#pragma unroll
    for (int k = lane; k < 128; k += 32) {
        su += hui[(size_t)r * 128 + k] * w2ui[k];
        ss += hsg[(size_t)r * 128 + k] * w2sg[k];
    }
#pragma unroll
    for (int o = 16; o; o >>= 1) {
        su += __shfl_xor_sync(0xffffffffu, su, o);
        ss += __shfl_xor_sync(0xffffffffu, ss, o);
    }
    if (lane == 0) {
        out[r]      = 1.f / (1.f + expf(-(ss + b2sg[0])));   // sg_out
        out[BB + r] = 1.f / (1.f + expf(-(su + b2ui[0])));   // ui_out
    }
}

// ---------------- host orchestration ----------------
static void gemm(const float* A, const float* W, const float* bias, float* C,
                 int M, int N, int K, int act) {
    dim3 g((M + 127) / 128, N / 64);
    gemm_act_kernel<<<g, 256>>>(A, W, bias, C, M, N, K, act);
}

extern "C" void kernel_launch(void* const* d_in, const int* in_sizes, int n_in,
                              void* d_out, int out_size) {
    const float* x        = (const float*)d_in[0];
    const float* efeat    = (const float*)d_in[1];
    const float* efeat2   = (const float*)d_in[2];
    const float* mask1    = (const float*)d_in[3];
    const float* mask2    = (const float*)d_in[4];
    const int*   src      = (const int*)d_in[5];
    const int*   dst      = (const int*)d_in[6];
    const int*   user     = (const int*)d_in[7];
    const int*   item     = (const int*)d_in[8];
    const int*   subg     = (const int*)d_in[9];
    const float* loc_wni  = (const float*)d_in[10];
    const float* loc_wnj  = (const float*)d_in[11];
    const float* loc_we   = (const float*)d_in[12];
    const float* loc_attn = (const float*)d_in[13];
    const float* loc_wnode= (const float*)d_in[14];
    const float* agg1_w   = (const float*)d_in[15];
    const float* agg1_b   = (const float*)d_in[16];
    const float* glob_wni = (const float*)d_in[17];
    const float* glob_wnj = (const float*)d_in[18];
    const float* glob_we  = (const float*)d_in[19];
    const float* glob_attn= (const float*)d_in[20];
    const float* glob_wnode=(const float*)d_in[21];
    const float* agg2_w   = (const float*)d_in[22];
    const float* agg2_b   = (const float*)d_in[23];
    const float* w1_ui    = (const float*)d_in[24];
    const float* b1_ui    = (const float*)d_in[25];
    const float* w1_sg    = (const float*)d_in[26];
    const float* b1_sg    = (const float*)d_in[27];
    const float* w2_ui    = (const float*)d_in[28];
    const float* b2_ui    = (const float*)d_in[29];
    const float* w2_sg    = (const float*)d_in[30];
    const float* b2_sg    = (const float*)d_in[31];

    float *p_xwi, *p_xwj, *p_fn, *p_agg, *p_scores;
    float *p_ui0, *p_ui1, *p_sg0, *p_sg1, *p_uix, *p_sgx, *p_hui, *p_hsg;
    int *p_deg, *p_off, *p_cur, *p_eid, *p_epos, *p_srcc;
    cudaGetSymbolAddress((void**)&p_xwi, g_xwi);
    cudaGetSymbolAddress((void**)&p_xwj, g_xwj);
    cudaGetSymbolAddress((void**)&p_fn,  g_fn);
    cudaGetSymbolAddress((void**)&p_agg, g_agg);
    cudaGetSymbolAddress((void**)&p_scores, g_scores);
    cudaGetSymbolAddress((void**)&p_ui0, g_ui0);
    cudaGetSymbolAddress((void**)&p_ui1, g_ui1);
    cudaGetSymbolAddress((void**)&p_sg0, g_sg0);
    cudaGetSymbolAddress((void**)&p_sg1, g_sg1);
    cudaGetSymbolAddress((void**)&p_uix, g_uix);
    cudaGetSymbolAddress((void**)&p_sgx, g_sgx);
    cudaGetSymbolAddress((void**)&p_hui, g_hui);
    cudaGetSymbolAddress((void**)&p_hsg, g_hsg);
    cudaGetSymbolAddress((void**)&p_deg, g_deg);
    cudaGetSymbolAddress((void**)&p_off, g_off);
    cudaGetSymbolAddress((void**)&p_cur, g_cur);
    cudaGetSymbolAddress((void**)&p_eid, g_eid);
    cudaGetSymbolAddress((void**)&p_epos, g_epos);
    cudaGetSymbolAddress((void**)&p_srcc, g_srcc);

    // CSR by dst (+ inverse map + src in CSR order)
    cudaMemsetAsync(p_deg, 0, NN * sizeof(int));
    hist_kernel<<<(NE + 255) / 256, 256>>>(dst, p_deg);
    scan_kernel<<<1, 1024>>>(p_deg, p_off, p_cur, NN);
    fill_kernel<<<(NE + 255) / 256, 256>>>(dst, src, p_off, p_cur, p_eid, p_epos, p_srcc);

    struct Stage {
        const float* hin; const float* ef; int Ke; const float* mask;
        const float* wni; const float* wnj; const float* we; const float* attn;
        const float* wnode; const float* aggw; const float* aggb; int act; float* hout;
    };
    Stage st[4] = {
        { x,     efeat,  16, mask1, loc_wni,           loc_wnj,           loc_we,           loc_attn,         loc_wnode,           agg1_w,          agg1_b,       1, p_ui0 },
        { p_ui0, efeat2, 64, mask2, glob_wni,          glob_wnj,          glob_we,          glob_attn,        glob_wnode,          agg2_w,          agg2_b,       2, p_sg0 },
        { p_sg0, efeat,  16, mask1, loc_wni  + 64*128, loc_wnj  + 64*128, loc_we  + 16*128, loc_attn  + 128,  loc_wnode  + 64*256, agg1_w + 256*64, agg1_b + 64,  1, p_ui1 },
        { p_ui1, efeat2, 64, mask2, glob_wni + 64*128, glob_wnj + 64*128, glob_we + 64*128, glob_attn + 128,  glob_wnode + 64*256, agg2_w + 256*64, agg2_b + 64,  2, p_sg1 },
    };

    for (int s = 0; s < 4; s++) {
        node_gemm_kernel<<<dim3((NN + 127) / 128, 4), 256>>>(
            st[s].hin, st[s].wni, st[s].wnj, st[s].wnode, p_xwi, p_xwj, p_fn, NN);
        edge_score_fused_kernel<<<(NE + 63) / 64, 256>>>(
            st[s].ef, st[s].we, st[s].attn, src, dst, p_epos, p_xwi, p_xwj, p_scores, st[s].Ke);
        attn_agg_kernel<<<(NN + 7) / 8, 256>>>(p_scores, st[s].mask, p_srcc, p_fn, p_off, p_eid, p_agg);
        gemm(p_agg, st[s].aggw, st[s].aggb, st[s].hout, NN, 64, 256, st[s].act);
    }

    gather_kernel<<<BB, 256>>>(p_ui0, p_ui1, p_sg0, p_sg1, user, item, subg, p_uix, p_sgx);
    gemm(p_uix, w1_ui, b1_ui, p_hui, BB, 128, 256, 3);
    gemm(p_sgx, w1_sg, b1_sg, p_hsg, BB, 128, 128, 3);
    final_out_kernel<<<BB / 8, 256>>>(p_hui, p_hsg, w2_ui, b2_ui, w2_sg, b2_sg, (float*)d_out);
}

// round 16
// speedup vs baseline: 1.2267x; 1.0105x over previous
#include <cuda_runtime.h>
#include <math.h>

#define NN 50000
#define NE 320000
#define BB 4096

typedef unsigned long long ull;

__device__ __forceinline__ ull ffma2(ull a, ull b, ull c) {
    ull d;
    asm("fma.rn.f32x2 %0, %1, %2, %3;" : "=l"(d) : "l"(a), "l"(b), "l"(c));
    return d;
}
__device__ __forceinline__ ull dup2(float x) {
    ull d;
    asm("mov.b64 %0, {%1, %1};" : "=l"(d) : "f"(x));
    return d;
}
__device__ __forceinline__ float2 unpack2(ull v) {
    float2 r;
    asm("mov.b64 {%0, %1}, %2;" : "=f"(r.x), "=f"(r.y) : "l"(v));
    return r;
}
__device__ __forceinline__ unsigned s2u(const void* p) {
    unsigned a;
    asm("{ .reg .u64 t; cvta.to.shared.u64 t, %1; cvt.u32.u64 %0, t; }" : "=r"(a) : "l"(p));
    return a;
}
__device__ __forceinline__ void cpa4(const void* smem, const void* gmem, int ok) {
    asm volatile("cp.async.ca.shared.global [%0], [%1], 4, %2;"
                 :: "r"(s2u(smem)), "l"(gmem), "r"(ok ? 4 : 0));
}
__device__ __forceinline__ void cpa16(const void* smem, const void* gmem) {
    asm volatile("cp.async.cg.shared.global [%0], [%1], 16;"
                 :: "r"(s2u(smem)), "l"(gmem));
}
#define CP_COMMIT() asm volatile("cp.async.commit_group;" ::: "memory")
#define CP_WAIT0()  asm volatile("cp.async.wait_group 0;" ::: "memory")

// ---------------- scratch (device globals) ----------------
__device__ float g_xwi[NN * 128];
__device__ float g_xwj[NN * 128];
__device__ float g_fn [NN * 256];
__device__ float g_agg[NN * 256];
__device__ float g_scores[NE * 4];   // CSR-ordered
__device__ float g_ui0[NN * 64];
__device__ float g_ui1[NN * 64];
__device__ float g_sg0[NN * 64];
__device__ float g_sg1[NN * 64];
__device__ float g_uix[BB * 256];
__device__ float g_sgx[BB * 128];
__device__ float g_hui[BB * 128];
__device__ float g_hsg[BB * 128];
__device__ float g_mkc1[NE];         // mask1 in CSR order
__device__ float g_mkc2[NE];         // mask2 in CSR order
__device__ int   g_deg[NN];
__device__ int   g_off[NN + 1];
__device__ int   g_cur[NN];
__device__ int   g_eid[NE];
__device__ int   g_epos[NE];
__device__ int   g_srcc[NE];         // src in CSR order

// ---------------- CSR build ----------------
__global__ void hist_kernel(const int* __restrict__ dst, int* __restrict__ deg) {
    int e = blockIdx.x * blockDim.x + threadIdx.x;
    if (e < NE) atomicAdd(&deg[dst[e]], 1);
}

__global__ void scan_kernel(const int* __restrict__ deg, int* __restrict__ off,
                            int* __restrict__ cur, int n) {
    __shared__ int warp_sums[32];
    __shared__ int carry_s;
    const int tid = threadIdx.x;
    const int lane = tid & 31;
    const int wid = tid >> 5;
    if (tid == 0) carry_s = 0;
    __syncthreads();
    for (int base = 0; base < n; base += 1024) {
        int i = base + tid;
        int v = (i < n) ? deg[i] : 0;
        int x = v;
#pragma unroll
        for (int o = 1; o < 32; o <<= 1) {
            int t = __shfl_up_sync(0xffffffffu, x, o);
            if (lane >= o) x += t;
        }
        if (lane == 31) warp_sums[wid] = x;
        __syncthreads();
        if (wid == 0) {
            int s = warp_sums[lane];
#pragma unroll
            for (int o = 1; o < 32; o <<= 1) {
                int t = __shfl_up_sync(0xffffffffu, s, o);
                if (lane >= o) s += t;
            }
            warp_sums[lane] = s;
        }
        __syncthreads();
        int woff = (wid > 0) ? warp_sums[wid - 1] : 0;
        int carry = carry_s;
        if (i < n) { off[i] = carry + woff + x - v; cur[i] = 0; }
        int total = warp_sums[31];
        __syncthreads();
        if (tid == 0) carry_s = carry + total;
        __syncthreads();
    }
    if (threadIdx.x == 0) off[n] = carry_s;
}

__global__ void fill_kernel(const int* __restrict__ dst, const int* __restrict__ src,
                            const float* __restrict__ mask1, const float* __restrict__ mask2,
                            const int* __restrict__ off,
                            int* __restrict__ cur, int* __restrict__ eid,
                            int* __restrict__ epos, int* __restrict__ srcc,
                            float* __restrict__ mkc1, float* __restrict__ mkc2) {
    int e = blockIdx.x * blockDim.x + threadIdx.x;
    if (e < NE) {
        int d = dst[e];
        int p = atomicAdd(&cur[d], 1);
        int pos = off[d] + p;
        eid[pos] = e;
        epos[e] = pos;
        srcc[pos] = src[e];
        mkc1[pos] = mask1[e];
        mkc2[pos] = mask2[e];
    }
}

// ---------------- generic GEMM (f32x2 8x4, square warp tile, cp.async dbuf) ------
__global__ __launch_bounds__(256, 2) void gemm_act_kernel(
    const float* __restrict__ A, const float* __restrict__ W,
    const float* __restrict__ bias, float* __restrict__ C,
    int M, int N, int K, int act)
{
    __shared__ __align__(16) float sA[2][16][132];
    __shared__ __align__(16) float sB[2][16][64];
    const int bm = blockIdx.x * 128;
    const int bn = blockIdx.y * 64;
    const int tid = threadIdx.x;
    const int lane = tid & 31;
    const int wp = tid >> 5;
    const int tx = ((wp >> 2) << 3) | (lane & 7);
    const int ty = ((wp & 3) << 2) | (lane >> 3);
    const int la_m = tid >> 4, la_k = tid & 15;
    const int lb_k = tid >> 4, lb_n = (tid & 15) * 4;
    const int nkb = K >> 4;

    ull acc2[4][4];
#pragma unroll
    for (int r = 0; r < 4; r++)
#pragma unroll
        for (int c = 0; c < 4; c++) acc2[r][c] = 0ull;

    auto issue = [&](int kb) {
        int p = kb & 1, k0 = kb << 4;
#pragma unroll
        for (int j = 0; j < 8; j++) {
            int gm = bm + la_m + 16 * j;
            int ok = gm < M;
            cpa4(&sA[p][la_k][la_m + 16 * j],
                 A + (size_t)(ok ? gm : 0) * K + k0 + la_k, ok);
        }
        cpa16(&sB[p][lb_k][lb_n], W + (size_t)(k0 + lb_k) * N + bn + lb_n);
        CP_COMMIT();
    };
    issue(0);
    for (int kb = 0; kb < nkb; kb++) {
        CP_WAIT0();
        __syncthreads();
        if (kb + 1 < nkb) issue(kb + 1);
        const int p = kb & 1;
#pragma unroll
        for (int kk = 0; kk < 16; kk++) {
            float4 b4 = *reinterpret_cast<const float4*>(&sB[p][kk][tx * 4]);
            ull bd[4] = {dup2(b4.x), dup2(b4.y), dup2(b4.z), dup2(b4.w)};
            ulonglong2 a01 = *reinterpret_cast<const ulonglong2*>(&sA[p][kk][ty * 8]);
            ulonglong2 a23 = *reinterpret_cast<const ulonglong2*>(&sA[p][kk][ty * 8 + 4]);
            ull ap[4] = {a01.x, a01.y, a23.x, a23.y};
#pragma unroll
            for (int rp = 0; rp < 4; rp++)
#pragma unroll
                for (int c = 0; c < 4; c++)
                    acc2[rp][c] = ffma2(ap[rp], bd[c], acc2[rp][c]);
        }
    }
#pragma unroll
    for (int rp = 0; rp < 4; rp++) {
        float2 u0 = unpack2(acc2[rp][0]);
        float2 u1 = unpack2(acc2[rp][1]);
        float2 u2 = unpack2(acc2[rp][2]);
        float2 u3 = unpack2(acc2[rp][3]);
        float rowv[2][4] = {{u0.x, u1.x, u2.x, u3.x}, {u0.y, u1.y, u2.y, u3.y}};
#pragma unroll
        for (int l = 0; l < 2; l++) {
            int gm = bm + ty * 8 + rp * 2 + l;
            if (gm >= M) continue;
            float4 v4;
            float* vp = &v4.x;
#pragma unroll
            for (int c = 0; c < 4; c++) {
                int gn = bn + tx * 4 + c;
                float v = rowv[l][c];
                if (bias) v += bias[gn];
                if (act == 1) v = (v > 0.f) ? v : (expf(v) - 1.f);
                else if (act == 2) v = (v > 0.f) ? v : 0.01f * v;
                else if (act == 3) v = fmaxf(v, 0.f);
                vp[c] = v;
            }
            *reinterpret_cast<float4*>(&C[(size_t)gm * N + bn + tx * 4]) = v4;
        }
    }
}

// ---------------- fused node GEMM: full-K A resident, 2 slices per block ---------
__global__ __launch_bounds__(256, 2) void node_gemm_kernel(
    const float* __restrict__ A,
    const float* __restrict__ wni, const float* __restrict__ wnj,
    const float* __restrict__ wnode,
    float* __restrict__ xwi, float* __restrict__ xwj, float* __restrict__ fn,
    int M)
{
    __shared__ __align__(16) float sA[64][132];
    __shared__ __align__(16) float sB[2][16][64];
    const int by = blockIdx.y;
    const float* W; float* C; int ldW, ldC, base;
    if (by == 0)      { W = wni;   C = xwi; ldW = 128; ldC = 128; base = 0; }
    else if (by == 1) { W = wnj;   C = xwj; ldW = 128; ldC = 128; base = 0; }
    else if (by == 2) { W = wnode; C = fn;  ldW = 256; ldC = 256; base = 0; }
    else              { W = wnode; C = fn;  ldW = 256; ldC = 256; base = 128; }

    const int bm = blockIdx.x * 128;
    const int tid = threadIdx.x;
    const int lane = tid & 31;
    const int wp = tid >> 5;
    const int tx = ((wp >> 2) << 3) | (lane & 7);
    const int ty = ((wp & 3) << 2) | (lane >> 3);
    const int la_m = tid >> 4, la_k = tid & 15;
    const int lb_k = tid >> 4, lb_n = (tid & 15) * 4;

#pragma unroll
    for (int kb = 0; kb < 4; kb++)
#pragma unroll
        for (int j = 0; j < 8; j++) {
            int gm = bm + la_m + 16 * j;
            int ok = gm < M;
            cpa4(&sA[kb * 16 + la_k][la_m + 16 * j],
                 A + (size_t)(ok ? gm : 0) * 64 + kb * 16 + la_k, ok);
        }
    CP_COMMIT();

    auto issueB = [&](int t) {
        int p = t & 1, s = t >> 2, kb = t & 3;
        int coloff = base + s * 64;
        cpa16(&sB[p][lb_k][lb_n], W + (size_t)(kb * 16 + lb_k) * ldW + coloff + lb_n);
        CP_COMMIT();
    };
    issueB(0);

    ull acc2[4][4];
#pragma unroll
    for (int r = 0; r < 4; r++)
#pragma unroll
        for (int c = 0; c < 4; c++) acc2[r][c] = 0ull;

#pragma unroll
    for (int t = 0; t < 8; t++) {
        CP_WAIT0();
        __syncthreads();
        if (t + 1 < 8) issueB(t + 1);
        const int p = t & 1, kb = t & 3;
#pragma unroll
        for (int kk = 0; kk < 16; kk++) {
            float4 b4 = *reinterpret_cast<const float4*>(&sB[p][kk][tx * 4]);
            ull bd[4] = {dup2(b4.x), dup2(b4.y), dup2(b4.z), dup2(b4.w)};
            ulonglong2 a01 = *reinterpret_cast<const ulonglong2*>(&sA[kb * 16 + kk][ty * 8]);
            ulonglong2 a23 = *reinterpret_cast<const ulonglong2*>(&sA[kb * 16 + kk][ty * 8 + 4]);
            ull ap[4] = {a01.x, a01.y, a23.x, a23.y};
#pragma unroll
            for (int rp = 0; rp < 4; rp++)
#pragma unroll
                for (int c = 0; c < 4; c++)
                    acc2[rp][c] = ffma2(ap[rp], bd[c], acc2[rp][c]);
        }
        if ((t & 3) == 3) {
            int coloff = base + (t >> 2) * 64;
#pragma unroll
            for (int rp = 0; rp < 4; rp++) {
                float2 u0 = unpack2(acc2[rp][0]);
                float2 u1 = unpack2(acc2[rp][1]);
                float2 u2 = unpack2(acc2[rp][2]);
                float2 u3 = unpack2(acc2[rp][3]);
                int gm0 = bm + ty * 8 + rp * 2;
                if (gm0 < M) {
                    float4 v4 = make_float4(u0.x, u1.x, u2.x, u3.x);
                    *reinterpret_cast<float4*>(&C[(size_t)gm0 * ldC + coloff + tx * 4]) = v4;
                }
                if (gm0 + 1 < M) {
                    float4 v4 = make_float4(u0.y, u1.y, u2.y, u3.y);
                    *reinterpret_cast<float4*>(&C[(size_t)(gm0 + 1) * ldC + coloff + tx * 4]) = v4;
                }
#pragma unroll
                for (int c = 0; c < 4; c++) acc2[rp][c] = 0ull;
            }
        }
    }
}

// ---------------- fused edge GEMM + attention score (f32x2, square warp tile) ----
__global__ __launch_bounds__(256, 2) void edge_score_fused_kernel(
    const float* __restrict__ efeat, const float* __restrict__ we,
    const float* __restrict__ attn,
    const int* __restrict__ src, const int* __restrict__ dst,
    const int* __restrict__ epos,
    const float* __restrict__ xwi, const float* __restrict__ xwj,
    float* __restrict__ scores, int Ke)
{
    __shared__ __align__(16) float sE[2][16][68];
    __shared__ __align__(16) float sW[2][16][128];
    __shared__ float s_attn[128];
    __shared__ int   s_src[64], s_dst[64], s_ep[64];

    const int tid = threadIdx.x;
    const int e0 = blockIdx.x * 64;
    const int lane = tid & 31;
    const int wp = tid >> 5;
    const int tx = ((wp >> 1) << 2) | (lane & 3);
    const int ty = ((wp & 1) << 3) | (lane >> 2);
    const int le_e = tid >> 4, le_k = tid & 15;
    const int lw_r0 = tid >> 5, lw_c0 = (tid & 31) * 4;
    const int nkb = Ke >> 4;

    if (tid < 128) s_attn[tid] = attn[tid];
    if (tid < 64) {
        int ge = e0 + tid;
        s_src[tid] = (ge < NE) ? src[ge] : 0;
        s_dst[tid] = (ge < NE) ? dst[ge] : 0;
        s_ep[tid]  = (ge < NE) ? epos[ge] : 0;
    }

    ull acc2[2][8];
#pragma unroll
    for (int r = 0; r < 2; r++)
#pragma unroll
        for (int c = 0; c < 8; c++) acc2[r][c] = 0ull;

    auto issue = [&](int kb) {
        int p = kb & 1, k0 = kb << 4;
#pragma unroll
        for (int j = 0; j < 4; j++) {
            int e = le_e + 16 * j;
            int ge = e0 + e;
            int ok = ge < NE;
            cpa4(&sE[p][le_k][e],
                 efeat + (size_t)(ok ? ge : 0) * Ke + k0 + le_k, ok);
        }
        cpa16(&sW[p][lw_r0][lw_c0],     we + (size_t)(k0 + lw_r0) * 128 + lw_c0);
        cpa16(&sW[p][lw_r0 + 8][lw_c0], we + (size_t)(k0 + lw_r0 + 8) * 128 + lw_c0);
        CP_COMMIT();
    };
    issue(0);
    for (int kb = 0; kb < nkb; kb++) {
        CP_WAIT0();
        __syncthreads();
        if (kb + 1 < nkb) issue(kb + 1);
        const int p = kb & 1;
#pragma unroll
        for (int kk = 0; kk < 16; kk++) {
            ulonglong2 a01 = *reinterpret_cast<const ulonglong2*>(&sE[p][kk][ty * 4]);
            ull ap[2] = {a01.x, a01.y};
            float4 w0 = *reinterpret_cast<const float4*>(&sW[p][kk][tx * 8]);
            float4 w1 = *reinterpret_cast<const float4*>(&sW[p][kk][tx * 8 + 4]);
            ull bd[8] = {dup2(w0.x), dup2(w0.y), dup2(w0.z), dup2(w0.w),
                         dup2(w1.x), dup2(w1.y), dup2(w1.z), dup2(w1.w)};
#pragma unroll
            for (int rp = 0; rp < 2; rp++)
#pragma unroll
                for (int c = 0; c < 8; c++)
                    acc2[rp][c] = ffma2(ap[rp], bd[c], acc2[rp][c]);
        }
    }

    float accr[4][8];
#pragma unroll
    for (int rp = 0; rp < 2; rp++)
#pragma unroll
        for (int c = 0; c < 8; c++) {
            float2 u = unpack2(acc2[rp][c]);
            accr[rp * 2][c]     = u.x;
            accr[rp * 2 + 1][c] = u.y;
        }

    const int h = tx >> 2;
    float at[8];
#pragma unroll
    for (int c = 0; c < 8; c++) at[c] = s_attn[tx * 8 + c];

#pragma unroll
    for (int r = 0; r < 4; r++) {
        int eg = ty * 4 + r;
        int ge = e0 + eg;
        float p = 0.f;
        if (ge < NE) {
            const float* gi = &xwi[(size_t)s_src[eg] * 128 + tx * 8];
            const float* gj = &xwj[(size_t)s_dst[eg] * 128 + tx * 8];
            float4 gi0 = *reinterpret_cast<const float4*>(gi);
            float4 gi1 = *reinterpret_cast<const float4*>(gi + 4);
            float4 gj0 = *reinterpret_cast<const float4*>(gj);
            float4 gj1 = *reinterpret_cast<const float4*>(gj + 4);
            float f[8];
            f[0] = accr[r][0] + gi0.x + gj0.x;  f[1] = accr[r][1] + gi0.y + gj0.y;
            f[2] = accr[r][2] + gi0.z + gj0.z;  f[3] = accr[r][3] + gi0.w + gj0.w;
            f[4] = accr[r][4] + gi1.x + gj1.x;  f[5] = accr[r][5] + gi1.y + gj1.y;
            f[6] = accr[r][6] + gi1.z + gj1.z;  f[7] = accr[r][7] + gi1.w + gj1.w;
#pragma unroll
            for (int c = 0; c < 8; c++) {
                float v = f[c];
                v = (v > 0.f) ? v : 0.2f * v;
                p += v * at[c];
            }
        }
        p += __shfl_xor_sync(0xffffffffu, p, 1);
        p += __shfl_xor_sync(0xffffffffu, p, 2);
        if ((lane & 3) == 0 && ge < NE)
            scores[(size_t)s_ep[eg] * 4 + h] = p;
    }
}

// ---------------- fused softmax + aggregation (fully CSR-ordered) ---------------
__global__ __launch_bounds__(256) void attn_agg_kernel(
    const float* __restrict__ scores, const float* __restrict__ maskc,
    const int* __restrict__ srcc, const float* __restrict__ fn,
    const int* __restrict__ off,
    float* __restrict__ outp)
{
    __shared__ __align__(16) float sm_a[8][32][4];
    __shared__ int sm_s[8][32];
    int w = threadIdx.x >> 5;
    int lane = threadIdx.x & 31;
    int n = blockIdx.x * 8 + w;
    if (n >= NN) return;
    int beg = off[n], end = off[n + 1];

    float4 acc0 = make_float4(0.f, 0.f, 0.f, 0.f);
    float4 acc1 = make_float4(0.f, 0.f, 0.f, 0.f);
    const int h = lane >> 3;

    if (beg < end) {
        float4 m = make_float4(-1e30f, -1e30f, -1e30f, -1e30f);
        for (int i = beg + lane; i < end; i += 32) {
            float4 s = *reinterpret_cast<const float4*>(&scores[(size_t)i * 4]);
            m.x = fmaxf(m.x, s.x); m.y = fmaxf(m.y, s.y);
            m.z = fmaxf(m.z, s.z); m.w = fmaxf(m.w, s.w);
        }
#pragma unroll
        for (int o = 16; o; o >>= 1) {
            m.x = fmaxf(m.x, __shfl_xor_sync(0xffffffffu, m.x, o));
            m.y = fmaxf(m.y, __shfl_xor_sync(0xffffffffu, m.y, o));
            m.z = fmaxf(m.z, __shfl_xor_sync(0xffffffffu, m.z, o));
            m.w = fmaxf(m.w, __shfl_xor_sync(0xffffffffu, m.w, o));
        }
        float4 d = make_float4(0.f, 0.f, 0.f, 0.f);
        for (int i = beg + lane; i < end; i += 32) {
            float4 s = *reinterpret_cast<const float4*>(&scores[(size_t)i * 4]);
            d.x += __expf(s.x - m.x); d.y += __expf(s.y - m.y);
            d.z += __expf(s.z - m.z); d.w += __expf(s.w - m.w);
        }
#pragma unroll
        for (int o = 16; o; o >>= 1) {
            d.x += __shfl_xor_sync(0xffffffffu, d.x, o);
            d.y += __shfl_xor_sync(0xffffffffu, d.y, o);
            d.z += __shfl_xor_sync(0xffffffffu, d.z, o);
            d.w += __shfl_xor_sync(0xffffffffu, d.w, o);
        }
        float4 inv = make_float4(1.f / (d.x + 1e-9f), 1.f / (d.y + 1e-9f),
                                 1.f / (d.z + 1e-9f), 1.f / (d.w + 1e-9f));

        for (int c0 = beg; c0 < end; c0 += 32) {
            int i = c0 + lane;
            if (i < end) {
                float4 s = *reinterpret_cast<const float4*>(&scores[(size_t)i * 4]);
                float mk = maskc[i];
                float4 a4;
                a4.x = __expf(s.x - m.x) * inv.x * mk;
                a4.y = __expf(s.y - m.y) * inv.y * mk;
                a4.z = __expf(s.z - m.z) * inv.z * mk;
                a4.w = __expf(s.w - m.w) * inv.w * mk;
                *reinterpret_cast<float4*>(&sm_a[w][lane][0]) = a4;
                sm_s[w][lane] = srcc[i];
            }
            __syncwarp();
            int cl = min(32, end - c0);
            int j = 0;
            for (; j + 1 < cl; j += 2) {
                float a0 = sm_a[w][j][h];
                float a1 = sm_a[w][j + 1][h];
                const float4* f0p = reinterpret_cast<const float4*>(
                    &fn[(size_t)sm_s[w][j] * 256 + lane * 8]);
                const float4* f1p = reinterpret_cast<const float4*>(
                    &fn[(size_t)sm_s[w][j + 1] * 256 + lane * 8]);
                float4 f00 = f0p[0], f01 = f0p[1];
                float4 f10 = f1p[0], f11 = f1p[1];
                acc0.x += a0 * f00.x; acc0.y += a0 * f00.y;
                acc0.z += a0 * f00.z; acc0.w += a0 * f00.w;
                acc1.x += a0 * f01.x; acc1.y += a0 * f01.y;
                acc1.z += a0 * f01.z; acc1.w += a0 * f01.w;
                acc0.x += a1 * f10.x; acc0.y += a1 * f10.y;
                acc0.z += a1 * f10.z; acc0.w += a1 * f10.w;
                acc1.x += a1 * f11.x; acc1.y += a1 * f11.y;
                acc1.z += a1 * f11.z; acc1.w += a1 * f11.w;
            }
            if (j < cl) {
                float a0 = sm_a[w][j][h];
                const float4* fp = reinterpret_cast<const float4*>(
                    &fn[(size_t)sm_s[w][j] * 256 + lane * 8]);
                float4 f0 = fp[0], f1 = fp[1];
                acc0.x += a0 * f0.x; acc0.y += a0 * f0.y;
                acc0.z += a0 * f0.z; acc0.w += a0 * f0.w;
                acc1.x += a0 * f1.x; acc1.y += a0 * f1.y;
                acc1.z += a0 * f1.z; acc1.w += a0 * f1.w;
            }
            __syncwarp();
        }
    }
    float4* op = reinterpret_cast<float4*>(&outp[(size_t)n * 256 + lane * 8]);
    op[0] = acc0;
    op[1] = acc1;
}

// ---------------- readout gathers ----------------
__global__ void gather_ui_kernel(
    const float* __restrict__ ui0, const float* __restrict__ ui1,
    const int* __restrict__ user, const int* __restrict__ item,
    float* __restrict__ uix)
{
    int b = blockIdx.x;
    int t = threadIdx.x;   // 256
    int u = user[b], it = item[b];
    float v;
    if (t < 64)       v = ui0[(size_t)u * 64 + t];
    else if (t < 128) v = ui1[(size_t)u * 64 + t - 64];
    else if (t < 192) v = ui0[(size_t)it * 64 + t - 128];
    else              v = ui1[(size_t)it * 64 + t - 192];
    uix[(size_t)b * 256 + t] = v;
}

__global__ void gather_sg_kernel(
    const float* __restrict__ sg0, const float* __restrict__ sg1,
    const int* __restrict__ subg, float* __restrict__ sgx)
{
    int b = blockIdx.x;
    int t = threadIdx.x;   // 128
    int s = subg[b];
    float w = (t < 64) ? sg0[(size_t)s * 64 + t] : sg1[(size_t)s * 64 + t - 64];
    sgx[(size_t)b * 128 + t] = w;
}

__global__ void final_out_kernel(
    const float* __restrict__ hui, const float* __restrict__ hsg,
    const float* __restrict__ w2ui, const float* __restrict__ b2ui,
    const float* __restrict__ w2sg, const float* __restrict__ b2sg,
    float* __restrict__ out)
{
    int r = blockIdx.x * 8 + (threadIdx.x >> 5);
    int lane = threadIdx.x & 31;
    if (r >= BB) return;
    float su = 0.f, ss = 0.f;
#pragma unroll
    for (int k = lane; k < 128; k += 32) {
        su += hui[(size_t)r * 128 + k] * w2ui[k];
        ss += hsg[(size_t)r * 128 + k] * w2sg[k];
    }
#pragma unroll
    for (int o = 16; o; o >>= 1) {
        su += __shfl_xor_sync(0xffffffffu, su, o);
        ss += __shfl_xor_sync(0xffffffffu, ss, o);
    }
    if (lane == 0) {
        out[r]      = 1.f / (1.f + expf(-(ss + b2sg[0])));   // sg_out
        out[BB + r] = 1.f / (1.f + expf(-(su + b2ui[0])));   // ui_out
    }
}

// ---------------- host orchestration ----------------
static void gemm_s(const float* A, const float* W, const float* bias, float* C,
                   int M, int N, int K, int act, cudaStream_t st) {
    dim3 g((M + 127) / 128, N / 64);
    gemm_act_kernel<<<g, 256, 0, st>>>(A, W, bias, C, M, N, K, act);
}

extern "C" void kernel_launch(void* const* d_in, const int* in_sizes, int n_in,
                              void* d_out, int out_size) {
    const float* x        = (const float*)d_in[0];
    const float* efeat    = (const float*)d_in[1];
    const float* efeat2   = (const float*)d_in[2];
    const float* mask1    = (const float*)d_in[3];
    const float* mask2    = (const float*)d_in[4];
    const int*   src      = (const int*)d_in[5];
    const int*   dst      = (const int*)d_in[6];
    const int*   user     = (const int*)d_in[7];
    const int*   item     = (const int*)d_in[8];
    const int*   subg     = (const int*)d_in[9];
    const float* loc_wni  = (const float*)d_in[10];
    const float* loc_wnj  = (const float*)d_in[11];
    const float* loc_we   = (const float*)d_in[12];
    const float* loc_attn = (const float*)d_in[13];
    const float* loc_wnode= (const float*)d_in[14];
    const float* agg1_w   = (const float*)d_in[15];
    const float* agg1_b   = (const float*)d_in[16];
    const float* glob_wni = (const float*)d_in[17];
    const float* glob_wnj = (const float*)d_in[18];
    const float* glob_we  = (const float*)d_in[19];
    const float* glob_attn= (const float*)d_in[20];
    const float* glob_wnode=(const float*)d_in[21];
    const float* agg2_w   = (const float*)d_in[22];
    const float* agg2_b   = (const float*)d_in[23];
    const float* w1_ui    = (const float*)d_in[24];
    const float* b1_ui    = (const float*)d_in[25];
    const float* w1_sg    = (const float*)d_in[26];
    const float* b1_sg    = (const float*)d_in[27];
    const float* w2_ui    = (const float*)d_in[28];
    const float* b2_ui    = (const float*)d_in[29];
    const float* w2_sg    = (const float*)d_in[30];
    const float* b2_sg    = (const float*)d_in[31];

    float *p_xwi, *p_xwj, *p_fn, *p_agg, *p_scores, *p_mkc1, *p_mkc2;
    float *p_ui0, *p_ui1, *p_sg0, *p_sg1, *p_uix, *p_sgx, *p_hui, *p_hsg;
    int *p_deg, *p_off, *p_cur, *p_eid, *p_epos, *p_srcc;
    cudaGetSymbolAddress((void**)&p_xwi, g_xwi);
    cudaGetSymbolAddress((void**)&p_xwj, g_xwj);
    cudaGetSymbolAddress((void**)&p_fn,  g_fn);
    cudaGetSymbolAddress((void**)&p_agg, g_agg);
    cudaGetSymbolAddress((void**)&p_scores, g_scores);
    cudaGetSymbolAddress((void**)&p_mkc1, g_mkc1);
    cudaGetSymbolAddress((void**)&p_mkc2, g_mkc2);
    cudaGetSymbolAddress((void**)&p_ui0, g_ui0);
    cudaGetSymbolAddress((void**)&p_ui1, g_ui1);
    cudaGetSymbolAddress((void**)&p_sg0, g_sg0);
    cudaGetSymbolAddress((void**)&p_sg1, g_sg1);
    cudaGetSymbolAddress((void**)&p_uix, g_uix);
    cudaGetSymbolAddress((void**)&p_sgx, g_sgx);
    cudaGetSymbolAddress((void**)&p_hui, g_hui);
    cudaGetSymbolAddress((void**)&p_hsg, g_hsg);
    cudaGetSymbolAddress((void**)&p_deg, g_deg);
    cudaGetSymbolAddress((void**)&p_off, g_off);
    cudaGetSymbolAddress((void**)&p_cur, g_cur);
    cudaGetSymbolAddress((void**)&p_eid, g_eid);
    cudaGetSymbolAddress((void**)&p_epos, g_epos);
    cudaGetSymbolAddress((void**)&p_srcc, g_srcc);

    // side stream + events (leaked intentionally: no device allocations involved,
    // and capture must not see a destroy of an in-use stream)
    cudaStream_t s1;
    cudaStreamCreateWithFlags(&s1, cudaStreamNonBlocking);
    cudaEvent_t ev0, ev1, ev2, ev3;
    cudaEventCreateWithFlags(&ev0, cudaEventDisableTiming);
    cudaEventCreateWithFlags(&ev1, cudaEventDisableTiming);
    cudaEventCreateWithFlags(&ev2, cudaEventDisableTiming);
    cudaEventCreateWithFlags(&ev3, cudaEventDisableTiming);

    // fork: CSR build on s1, overlapped with stage-0 node GEMM
    cudaEventRecord(ev0, 0);
    cudaStreamWaitEvent(s1, ev0, 0);
    cudaMemsetAsync(p_deg, 0, NN * sizeof(int), s1);
    hist_kernel<<<(NE + 255) / 256, 256, 0, s1>>>(dst, p_deg);
    scan_kernel<<<1, 1024, 0, s1>>>(p_deg, p_off, p_cur, NN);
    fill_kernel<<<(NE + 255) / 256, 256, 0, s1>>>(dst, src, mask1, mask2, p_off,
                                                  p_cur, p_eid, p_epos, p_srcc,
                                                  p_mkc1, p_mkc2);
    cudaEventRecord(ev1, s1);

    struct Stage {
        const float* hin; const float* ef; int Ke; const float* mkc;
        const float* wni; const float* wnj; const float* we; const float* attn;
        const float* wnode; const float* aggw; const float* aggb; int act; float* hout;
    };
    Stage st[4] = {
        { x,     efeat,  16, p_mkc1, loc_wni,           loc_wnj,           loc_we,           loc_attn,         loc_wnode,           agg1_w,          agg1_b,       1, p_ui0 },
        { p_ui0, efeat2, 64, p_mkc2, glob_wni,          glob_wnj,          glob_we,          glob_attn,        glob_wnode,          agg2_w,          agg2_b,       2, p_sg0 },
        { p_sg0, efeat,  16, p_mkc1, loc_wni  + 64*128, loc_wnj  + 64*128, loc_we  + 16*128, loc_attn  + 128,  loc_wnode  + 64*256, agg1_w + 256*64, agg1_b + 64,  1, p_ui1 },
        { p_ui1, efeat2, 64, p_mkc2, glob_wni + 64*128, glob_wnj + 64*128, glob_we + 64*128, glob_attn + 128,  glob_wnode + 64*256, agg2_w + 256*64, agg2_b + 64,  2, p_sg1 },
    };

    for (int s = 0; s < 4; s++) {
        node_gemm_kernel<<<dim3((NN + 127) / 128, 4), 256>>>(
            st[s].hin, st[s].wni, st[s].wnj, st[s].wnode, p_xwi, p_xwj, p_fn, NN);
        if (s == 0) cudaStreamWaitEvent(0, ev1, 0);   // join: edge_score needs epos
        edge_score_fused_kernel<<<(NE + 63) / 64, 256>>>(
            st[s].ef, st[s].we, st[s].attn, src, dst, p_epos, p_xwi, p_xwj, p_scores, st[s].Ke);
        attn_agg_kernel<<<(NN + 7) / 8, 256>>>(p_scores, st[s].mkc, p_srcc, p_fn, p_off, p_agg);
        gemm_s(p_agg, st[s].aggw, st[s].aggb, st[s].hout, NN, 64, 256, st[s].act, 0);
        if (s == 2) {
            // ui0/ui1 ready: run ui readout branch on s1 concurrent with stage 3
            cudaEventRecord(ev2, 0);
            cudaStreamWaitEvent(s1, ev2, 0);
            gather_ui_kernel<<<BB, 256, 0, s1>>>(p_ui0, p_ui1, user, item, p_uix);
            gemm_s(p_uix, w1_ui, b1_ui, p_hui, BB, 128, 256, 3, s1);
            cudaEventRecord(ev3, s1);
        }
    }

    gather_sg_kernel<<<BB, 128>>>(p_sg0, p_sg1, subg, p_sgx);
    gemm_s(p_sgx, w1_sg, b1_sg, p_hsg, BB, 128, 128, 3, 0);
    cudaStreamWaitEvent(0, ev3, 0);   // join ui branch
    final_out_kernel<<<BB / 8, 256>>>(p_hui, p_hsg, w2_ui, b2_ui, w2_sg, b2_sg, (float*)d_out);
}

// round 17
// speedup vs baseline: 1.2393x; 1.0103x over previous
#include <cuda_runtime.h>
#include <math.h>

#define NN 50000
#define NE 320000
#define BB 4096

typedef unsigned long long ull;

__device__ __forceinline__ ull ffma2(ull a, ull b, ull c) {
    ull d;
    asm("fma.rn.f32x2 %0, %1, %2, %3;" : "=l"(d) : "l"(a), "l"(b), "l"(c));
    return d;
}
__device__ __forceinline__ ull dup2(float x) {
    ull d;
    asm("mov.b64 %0, {%1, %1};" : "=l"(d) : "f"(x));
    return d;
}
__device__ __forceinline__ float2 unpack2(ull v) {
    float2 r;
    asm("mov.b64 {%0, %1}, %2;" : "=f"(r.x), "=f"(r.y) : "l"(v));
    return r;
}
__device__ __forceinline__ unsigned s2u(const void* p) {
    unsigned a;
    asm("{ .reg .u64 t; cvta.to.shared.u64 t, %1; cvt.u32.u64 %0, t; }" : "=r"(a) : "l"(p));
    return a;
}
__device__ __forceinline__ void cpa4(const void* smem, const void* gmem, int ok) {
    asm volatile("cp.async.ca.shared.global [%0], [%1], 4, %2;"
                 :: "r"(s2u(smem)), "l"(gmem), "r"(ok ? 4 : 0));
}
__device__ __forceinline__ void cpa16(const void* smem, const void* gmem) {
    asm volatile("cp.async.cg.shared.global [%0], [%1], 16;"
                 :: "r"(s2u(smem)), "l"(gmem));
}
#define CP_COMMIT() asm volatile("cp.async.commit_group;" ::: "memory")
#define CP_WAIT0()  asm volatile("cp.async.wait_group 0;" ::: "memory")

// ---------------- scratch (device globals) ----------------
__device__ float g_xwi[NN * 128];
__device__ float g_xwj[NN * 128];
__device__ float g_fn [NN * 256];
__device__ float g_agg[NN * 256];
__device__ float g_scores[NE * 4];   // CSR-ordered
__device__ float g_ui0[NN * 64];
__device__ float g_ui1[NN * 64];
__device__ float g_sg0[NN * 64];
__device__ float g_sg1[NN * 64];
__device__ float g_uix[BB * 256];
__device__ float g_sgx[BB * 128];
__device__ float g_hui[BB * 128];
__device__ float g_hsg[BB * 128];
__device__ float g_mkc1[NE];
__device__ float g_mkc2[NE];
__device__ int   g_deg[NN];
__device__ int   g_off[NN + 1];
__device__ int   g_cur[NN];
__device__ int   g_eid[NE];
__device__ int   g_epos[NE];
__device__ int   g_srcc[NE];

// ---------------- CSR build ----------------
__global__ void hist_kernel(const int* __restrict__ dst, int* __restrict__ deg) {
    int e = blockIdx.x * blockDim.x + threadIdx.x;
    if (e < NE) atomicAdd(&deg[dst[e]], 1);
}

__global__ void scan_kernel(const int* __restrict__ deg, int* __restrict__ off,
                            int* __restrict__ cur, int n) {
    __shared__ int warp_sums[32];
    __shared__ int carry_s;
    const int tid = threadIdx.x;
    const int lane = tid & 31;
    const int wid = tid >> 5;
    if (tid == 0) carry_s = 0;
    __syncthreads();
    for (int base = 0; base < n; base += 1024) {
        int i = base + tid;
        int v = (i < n) ? deg[i] : 0;
        int x = v;
#pragma unroll
        for (int o = 1; o < 32; o <<= 1) {
            int t = __shfl_up_sync(0xffffffffu, x, o);
            if (lane >= o) x += t;
        }
        if (lane == 31) warp_sums[wid] = x;
        __syncthreads();
        if (wid == 0) {
            int s = warp_sums[lane];
#pragma unroll
            for (int o = 1; o < 32; o <<= 1) {
                int t = __shfl_up_sync(0xffffffffu, s, o);
                if (lane >= o) s += t;
            }
            warp_sums[lane] = s;
        }
        __syncthreads();
        int woff = (wid > 0) ? warp_sums[wid - 1] : 0;
        int carry = carry_s;
        if (i < n) { off[i] = carry + woff + x - v; cur[i] = 0; }
        int total = warp_sums[31];
        __syncthreads();
        if (tid == 0) carry_s = carry + total;
        __syncthreads();
    }
    if (threadIdx.x == 0) off[n] = carry_s;
}

__global__ void fill_kernel(const int* __restrict__ dst, const int* __restrict__ src,
                            const float* __restrict__ mask1, const float* __restrict__ mask2,
                            const int* __restrict__ off,
                            int* __restrict__ cur, int* __restrict__ eid,
                            int* __restrict__ epos, int* __restrict__ srcc,
                            float* __restrict__ mkc1, float* __restrict__ mkc2) {
    int e = blockIdx.x * blockDim.x + threadIdx.x;
    if (e < NE) {
        int d = dst[e];
        int p = atomicAdd(&cur[d], 1);
        int pos = off[d] + p;
        eid[pos] = e;
        epos[e] = pos;
        srcc[pos] = src[e];
        mkc1[pos] = mask1[e];
        mkc2[pos] = mask2[e];
    }
}

// ---------------- generic GEMM (f32x2 8x4, square warp tile, PDL) ------
__global__ __launch_bounds__(256, 2) void gemm_act_kernel(
    const float* __restrict__ A, const float* __restrict__ W,
    const float* __restrict__ bias, float* __restrict__ C,
    int M, int N, int K, int act)
{
    __shared__ __align__(16) float sA[2][16][132];
    __shared__ __align__(16) float sB[2][16][64];
    const int bm = blockIdx.x * 128;
    const int bn = blockIdx.y * 64;
    const int tid = threadIdx.x;
    const int lane = tid & 31;
    const int wp = tid >> 5;
    const int tx = ((wp >> 2) << 3) | (lane & 7);
    const int ty = ((wp & 3) << 2) | (lane >> 3);
    const int la_m = tid >> 4, la_k = tid & 15;
    const int lb_k = tid >> 4, lb_n = (tid & 15) * 4;
    const int nkb = K >> 4;

    // pre-sync: weight tile 0 (inputs only)
    cpa16(&sB[0][lb_k][lb_n], W + (size_t)lb_k * N + bn + lb_n);
    CP_COMMIT();
    cudaGridDependencySynchronize();
    // A tile 0 (may depend on prior kernel)
#pragma unroll
    for (int j = 0; j < 8; j++) {
        int gm = bm + la_m + 16 * j;
        int ok = gm < M;
        cpa4(&sA[0][la_k][la_m + 16 * j], A + (size_t)(ok ? gm : 0) * K + la_k, ok);
    }
    CP_COMMIT();

    ull acc2[4][4];
#pragma unroll
    for (int r = 0; r < 4; r++)
#pragma unroll
        for (int c = 0; c < 4; c++) acc2[r][c] = 0ull;

    auto issue = [&](int kb) {
        int p = kb & 1, k0 = kb << 4;
#pragma unroll
        for (int j = 0; j < 8; j++) {
            int gm = bm + la_m + 16 * j;
            int ok = gm < M;
            cpa4(&sA[p][la_k][la_m + 16 * j],
                 A + (size_t)(ok ? gm : 0) * K + k0 + la_k, ok);
        }
        cpa16(&sB[p][lb_k][lb_n], W + (size_t)(k0 + lb_k) * N + bn + lb_n);
        CP_COMMIT();
    };
    for (int kb = 0; kb < nkb; kb++) {
        CP_WAIT0();
        __syncthreads();
        if (kb + 1 < nkb) issue(kb + 1);
        const int p = kb & 1;
#pragma unroll
        for (int kk = 0; kk < 16; kk++) {
            float4 b4 = *reinterpret_cast<const float4*>(&sB[p][kk][tx * 4]);
            ull bd[4] = {dup2(b4.x), dup2(b4.y), dup2(b4.z), dup2(b4.w)};
            ulonglong2 a01 = *reinterpret_cast<const ulonglong2*>(&sA[p][kk][ty * 8]);
            ulonglong2 a23 = *reinterpret_cast<const ulonglong2*>(&sA[p][kk][ty * 8 + 4]);
            ull ap[4] = {a01.x, a01.y, a23.x, a23.y};
#pragma unroll
            for (int rp = 0; rp < 4; rp++)
#pragma unroll
                for (int c = 0; c < 4; c++)
                    acc2[rp][c] = ffma2(ap[rp], bd[c], acc2[rp][c]);
        }
    }
#pragma unroll
    for (int rp = 0; rp < 4; rp++) {
        float2 u0 = unpack2(acc2[rp][0]);
        float2 u1 = unpack2(acc2[rp][1]);
        float2 u2 = unpack2(acc2[rp][2]);
        float2 u3 = unpack2(acc2[rp][3]);
        float rowv[2][4] = {{u0.x, u1.x, u2.x, u3.x}, {u0.y, u1.y, u2.y, u3.y}};
#pragma unroll
        for (int l = 0; l < 2; l++) {
            int gm = bm + ty * 8 + rp * 2 + l;
            if (gm >= M) continue;
            float4 v4;
            float* vp = &v4.x;
#pragma unroll
            for (int c = 0; c < 4; c++) {
                int gn = bn + tx * 4 + c;
                float v = rowv[l][c];
                if (bias) v += bias[gn];
                if (act == 1) v = (v > 0.f) ? v : (expf(v) - 1.f);
                else if (act == 2) v = (v > 0.f) ? v : 0.01f * v;
                else if (act == 3) v = fmaxf(v, 0.f);
                vp[c] = v;
            }
            *reinterpret_cast<float4*>(&C[(size_t)gm * N + bn + tx * 4]) = v4;
        }
    }
}

// ---------------- fused node GEMM: full-K A resident, 2 slices per block, PDL ----
__global__ __launch_bounds__(256, 2) void node_gemm_kernel(
    const float* __restrict__ A,
    const float* __restrict__ wni, const float* __restrict__ wnj,
    const float* __restrict__ wnode,
    float* __restrict__ xwi, float* __restrict__ xwj, float* __restrict__ fn,
    int M)
{
    __shared__ __align__(16) float sA[64][132];
    __shared__ __align__(16) float sB[2][16][64];
    const int by = blockIdx.y;
    const float* W; float* C; int ldW, ldC, base;
    if (by == 0)      { W = wni;   C = xwi; ldW = 128; ldC = 128; base = 0; }
    else if (by == 1) { W = wnj;   C = xwj; ldW = 128; ldC = 128; base = 0; }
    else if (by == 2) { W = wnode; C = fn;  ldW = 256; ldC = 256; base = 0; }
    else              { W = wnode; C = fn;  ldW = 256; ldC = 256; base = 128; }

    const int bm = blockIdx.x * 128;
    const int tid = threadIdx.x;
    const int lane = tid & 31;
    const int wp = tid >> 5;
    const int tx = ((wp >> 2) << 3) | (lane & 7);
    const int ty = ((wp & 3) << 2) | (lane >> 3);
    const int la_m = tid >> 4, la_k = tid & 15;
    const int lb_k = tid >> 4, lb_n = (tid & 15) * 4;

    auto issueB = [&](int t) {
        int p = t & 1, s = t >> 2, kb = t & 3;
        int coloff = base + s * 64;
        cpa16(&sB[p][lb_k][lb_n], W + (size_t)(kb * 16 + lb_k) * ldW + coloff + lb_n);
        CP_COMMIT();
    };
    // pre-sync: weight tile 0 (inputs only)
    issueB(0);
    cudaGridDependencySynchronize();
    // full A tile (may depend on prior agg GEMM)
#pragma unroll
    for (int kb = 0; kb < 4; kb++)
#pragma unroll
        for (int j = 0; j < 8; j++) {
            int gm = bm + la_m + 16 * j;
            int ok = gm < M;
            cpa4(&sA[kb * 16 + la_k][la_m + 16 * j],
                 A + (size_t)(ok ? gm : 0) * 64 + kb * 16 + la_k, ok);
        }
    CP_COMMIT();

    ull acc2[4][4];
#pragma unroll
    for (int r = 0; r < 4; r++)
#pragma unroll
        for (int c = 0; c < 4; c++) acc2[r][c] = 0ull;

#pragma unroll
    for (int t = 0; t < 8; t++) {
        CP_WAIT0();
        __syncthreads();
        if (t + 1 < 8) issueB(t + 1);
        const int p = t & 1, kb = t & 3;
#pragma unroll
        for (int kk = 0; kk < 16; kk++) {
            float4 b4 = *reinterpret_cast<const float4*>(&sB[p][kk][tx * 4]);
            ull bd[4] = {dup2(b4.x), dup2(b4.y), dup2(b4.z), dup2(b4.w)};
            ulonglong2 a01 = *reinterpret_cast<const ulonglong2*>(&sA[kb * 16 + kk][ty * 8]);
            ulonglong2 a23 = *reinterpret_cast<const ulonglong2*>(&sA[kb * 16 + kk][ty * 8 + 4]);
            ull ap[4] = {a01.x, a01.y, a23.x, a23.y};
#pragma unroll
            for (int rp = 0; rp < 4; rp++)
#pragma unroll
                for (int c = 0; c < 4; c++)
                    acc2[rp][c] = ffma2(ap[rp], bd[c], acc2[rp][c]);
        }
        if ((t & 3) == 3) {
            int coloff = base + (t >> 2) * 64;
#pragma unroll
            for (int rp = 0; rp < 4; rp++) {
                float2 u0 = unpack2(acc2[rp][0]);
                float2 u1 = unpack2(acc2[rp][1]);
                float2 u2 = unpack2(acc2[rp][2]);
                float2 u3 = unpack2(acc2[rp][3]);
                int gm0 = bm + ty * 8 + rp * 2;
                if (gm0 < M) {
                    float4 v4 = make_float4(u0.x, u1.x, u2.x, u3.x);
                    *reinterpret_cast<float4*>(&C[(size_t)gm0 * ldC + coloff + tx * 4]) = v4;
                }
                if (gm0 + 1 < M) {
                    float4 v4 = make_float4(u0.y, u1.y, u2.y, u3.y);
                    *reinterpret_cast<float4*>(&C[(size_t)(gm0 + 1) * ldC + coloff + tx * 4]) = v4;
                }
#pragma unroll
                for (int c = 0; c < 4; c++) acc2[rp][c] = 0ull;
            }
        }
    }
}

// ---------------- fused edge GEMM + attention score (PDL: late sync) ----
__global__ __launch_bounds__(256, 2) void edge_score_fused_kernel(
    const float* __restrict__ efeat, const float* __restrict__ we,
    const float* __restrict__ attn,
    const int* __restrict__ src, const int* __restrict__ dst,
    const int* __restrict__ epos,
    const float* __restrict__ xwi, const float* __restrict__ xwj,
    float* __restrict__ scores, int Ke)
{
    __shared__ __align__(16) float sE[2][16][68];
    __shared__ __align__(16) float sW[2][16][128];
    __shared__ float s_attn[128];
    __shared__ int   s_src[64], s_dst[64], s_ep[64];

    const int tid = threadIdx.x;
    const int e0 = blockIdx.x * 64;
    const int lane = tid & 31;
    const int wp = tid >> 5;
    const int tx = ((wp >> 1) << 2) | (lane & 3);
    const int ty = ((wp & 1) << 3) | (lane >> 2);
    const int le_e = tid >> 4, le_k = tid & 15;
    const int lw_r0 = tid >> 5, lw_c0 = (tid & 31) * 4;
    const int nkb = Ke >> 4;

    if (tid < 128) s_attn[tid] = attn[tid];
    if (tid < 64) {
        int ge = e0 + tid;
        s_src[tid] = (ge < NE) ? src[ge] : 0;
        s_dst[tid] = (ge < NE) ? dst[ge] : 0;
        s_ep[tid]  = (ge < NE) ? epos[ge] : 0;
    }

    ull acc2[2][8];
#pragma unroll
    for (int r = 0; r < 2; r++)
#pragma unroll
        for (int c = 0; c < 8; c++) acc2[r][c] = 0ull;

    auto issue = [&](int kb) {
        int p = kb & 1, k0 = kb << 4;
#pragma unroll
        for (int j = 0; j < 4; j++) {
            int e = le_e + 16 * j;
            int ge = e0 + e;
            int ok = ge < NE;
            cpa4(&sE[p][le_k][e],
                 efeat + (size_t)(ok ? ge : 0) * Ke + k0 + le_k, ok);
        }
        cpa16(&sW[p][lw_r0][lw_c0],     we + (size_t)(k0 + lw_r0) * 128 + lw_c0);
        cpa16(&sW[p][lw_r0 + 8][lw_c0], we + (size_t)(k0 + lw_r0 + 8) * 128 + lw_c0);
        CP_COMMIT();
    };
    issue(0);
    for (int kb = 0; kb < nkb; kb++) {
        CP_WAIT0();
        __syncthreads();
        if (kb + 1 < nkb) issue(kb + 1);
        const int p = kb & 1;
#pragma unroll
        for (int kk = 0; kk < 16; kk++) {
            ulonglong2 a01 = *reinterpret_cast<const ulonglong2*>(&sE[p][kk][ty * 4]);
            ull ap[2] = {a01.x, a01.y};
            float4 w0 = *reinterpret_cast<const float4*>(&sW[p][kk][tx * 8]);
            float4 w1 = *reinterpret_cast<const float4*>(&sW[p][kk][tx * 8 + 4]);
            ull bd[8] = {dup2(w0.x), dup2(w0.y), dup2(w0.z), dup2(w0.w),
                         dup2(w1.x), dup2(w1.y), dup2(w1.z), dup2(w1.w)};
#pragma unroll
            for (int rp = 0; rp < 2; rp++)
#pragma unroll
                for (int c = 0; c < 8; c++)
                    acc2[rp][c] = ffma2(ap[rp], bd[c], acc2[rp][c]);
        }
    }

    // mainloop used inputs only; wait for node GEMM outputs before the gather
    cudaGridDependencySynchronize();

    float accr[4][8];
#pragma unroll
    for (int rp = 0; rp < 2; rp++)
#pragma unroll
        for (int c = 0; c < 8; c++) {
            float2 u = unpack2(acc2[rp][c]);
            accr[rp * 2][c]     = u.x;
            accr[rp * 2 + 1][c] = u.y;
        }

    const int h = tx >> 2;
    float at[8];
#pragma unroll
    for (int c = 0; c < 8; c++) at[c] = s_attn[tx * 8 + c];

#pragma unroll
    for (int r = 0; r < 4; r++) {
        int eg = ty * 4 + r;
        int ge = e0 + eg;
        float p = 0.f;
        if (ge < NE) {
            const float* gi = &xwi[(size_t)s_src[eg] * 128 + tx * 8];
            const float* gj = &xwj[(size_t)s_dst[eg] * 128 + tx * 8];
            float4 gi0 = *reinterpret_cast<const float4*>(gi);
            float4 gi1 = *reinterpret_cast<const float4*>(gi + 4);
            float4 gj0 = *reinterpret_cast<const float4*>(gj);
            float4 gj1 = *reinterpret_cast<const float4*>(gj + 4);
            float f[8];
            f[0] = accr[r][0] + gi0.x + gj0.x;  f[1] = accr[r][1] + gi0.y + gj0.y;
            f[2] = accr[r][2] + gi0.z + gj0.z;  f[3] = accr[r][3] + gi0.w + gj0.w;
            f[4] = accr[r][4] + gi1.x + gj1.x;  f[5] = accr[r][5] + gi1.y + gj1.y;
            f[6] = accr[r][6] + gi1.z + gj1.z;  f[7] = accr[r][7] + gi1.w + gj1.w;
#pragma unroll
            for (int c = 0; c < 8; c++) {
                float v = f[c];
                v = (v > 0.f) ? v : 0.2f * v;
                p += v * at[c];
            }
        }
        p += __shfl_xor_sync(0xffffffffu, p, 1);
        p += __shfl_xor_sync(0xffffffffu, p, 2);
        if ((lane & 3) == 0 && ge < NE)
            scores[(size_t)s_ep[eg] * 4 + h] = p;
    }
}

// ---------------- fused softmax + aggregation (fully CSR-ordered, PDL top) ------
__global__ __launch_bounds__(256) void attn_agg_kernel(
    const float* __restrict__ scores, const float* __restrict__ maskc,
    const int* __restrict__ srcc, const float* __restrict__ fn,
    const int* __restrict__ off,
    float* __restrict__ outp)
{
    cudaGridDependencySynchronize();
    __shared__ __align__(16) float sm_a[8][32][4];
    __shared__ int sm_s[8][32];
    int w = threadIdx.x >> 5;
    int lane = threadIdx.x & 31;
    int n = blockIdx.x * 8 + w;
    if (n >= NN) return;
    int beg = off[n], end = off[n + 1];

    float4 acc0 = make_float4(0.f, 0.f, 0.f, 0.f);
    float4 acc1 = make_float4(0.f, 0.f, 0.f, 0.f);
    const int h = lane >> 3;

    if (beg < end) {
        float4 m = make_float4(-1e30f, -1e30f, -1e30f, -1e30f);
        for (int i = beg + lane; i < end; i += 32) {
            float4 s = *reinterpret_cast<const float4*>(&scores[(size_t)i * 4]);
            m.x = fmaxf(m.x, s.x); m.y = fmaxf(m.y, s.y);
            m.z = fmaxf(m.z, s.z); m.w = fmaxf(m.w, s.w);
        }
#pragma unroll
        for (int o = 16; o; o >>= 1) {
            m.x = fmaxf(m.x, __shfl_xor_sync(0xffffffffu, m.x, o));
            m.y = fmaxf(m.y, __shfl_xor_sync(0xffffffffu, m.y, o));
            m.z = fmaxf(m.z, __shfl_xor_sync(0xffffffffu, m.z, o));
            m.w = fmaxf(m.w, __shfl_xor_sync(0xffffffffu, m.w, o));
        }
        float4 d = make_float4(0.f, 0.f, 0.f, 0.f);
        for (int i = beg + lane; i < end; i += 32) {
            float4 s = *reinterpret_cast<const float4*>(&scores[(size_t)i * 4]);
            d.x += __expf(s.x - m.x); d.y += __expf(s.y - m.y);
            d.z += __expf(s.z - m.z); d.w += __expf(s.w - m.w);
        }
#pragma unroll
        for (int o = 16; o; o >>= 1) {
            d.x += __shfl_xor_sync(0xffffffffu, d.x, o);
            d.y += __shfl_xor_sync(0xffffffffu, d.y, o);
            d.z += __shfl_xor_sync(0xffffffffu, d.z, o);
            d.w += __shfl_xor_sync(0xffffffffu, d.w, o);
        }
        float4 inv = make_float4(1.f / (d.x + 1e-9f), 1.f / (d.y + 1e-9f),
                                 1.f / (d.z + 1e-9f), 1.f / (d.w + 1e-9f));

        for (int c0 = beg; c0 < end; c0 += 32) {
            int i = c0 + lane;
            if (i < end) {
                float4 s = *reinterpret_cast<const float4*>(&scores[(size_t)i * 4]);
                float mk = maskc[i];
                float4 a4;
                a4.x = __expf(s.x - m.x) * inv.x * mk;
                a4.y = __expf(s.y - m.y) * inv.y * mk;
                a4.z = __expf(s.z - m.z) * inv.z * mk;
                a4.w = __expf(s.w - m.w) * inv.w * mk;
                *reinterpret_cast<float4*>(&sm_a[w][lane][0]) = a4;
                sm_s[w][lane] = srcc[i];
            }
            __syncwarp();
            int cl = min(32, end - c0);
            int j = 0;
            for (; j + 1 < cl; j += 2) {
                float a0 = sm_a[w][j][h];
                float a1 = sm_a[w][j + 1][h];
                const float4* f0p = reinterpret_cast<const float4*>(
                    &fn[(size_t)sm_s[w][j] * 256 + lane * 8]);
                const float4* f1p = reinterpret_cast<const float4*>(
                    &fn[(size_t)sm_s[w][j + 1] * 256 + lane * 8]);
                float4 f00 = f0p[0], f01 = f0p[1];
                float4 f10 = f1p[0], f11 = f1p[1];
                acc0.x += a0 * f00.x; acc0.y += a0 * f00.y;
                acc0.z += a0 * f00.z; acc0.w += a0 * f00.w;
                acc1.x += a0 * f01.x; acc1.y += a0 * f01.y;
                acc1.z += a0 * f01.z; acc1.w += a0 * f01.w;
                acc0.x += a1 * f10.x; acc0.y += a1 * f10.y;
                acc0.z += a1 * f10.z; acc0.w += a1 * f10.w;
                acc1.x += a1 * f11.x; acc1.y += a1 * f11.y;
                acc1.z += a1 * f11.z; acc1.w += a1 * f11.w;
            }
            if (j < cl) {
                float a0 = sm_a[w][j][h];
                const float4* fp = reinterpret_cast<const float4*>(
                    &fn[(size_t)sm_s[w][j] * 256 + lane * 8]);
                float4 f0 = fp[0], f1 = fp[1];
                acc0.x += a0 * f0.x; acc0.y += a0 * f0.y;
                acc0.z += a0 * f0.z; acc0.w += a0 * f0.w;
                acc1.x += a0 * f1.x; acc1.y += a0 * f1.y;
                acc1.z += a0 * f1.z; acc1.w += a0 * f1.w;
            }
            __syncwarp();
        }
    }
    float4* op = reinterpret_cast<float4*>(&outp[(size_t)n * 256 + lane * 8]);
    op[0] = acc0;
    op[1] = acc1;
}

// ---------------- readout gathers ----------------
__global__ void gather_ui_kernel(
    const float* __restrict__ ui0, const float* __restrict__ ui1,
    const int* __restrict__ user, const int* __restrict__ item,
    float* __restrict__ uix)
{
    int b = blockIdx.x;
    int t = threadIdx.x;
    int u = user[b], it = item[b];
    float v;
    if (t < 64)       v = ui0[(size_t)u * 64 + t];
    else if (t < 128) v = ui1[(size_t)u * 64 + t - 64];
    else if (t < 192) v = ui0[(size_t)it * 64 + t - 128];
    else              v = ui1[(size_t)it * 64 + t - 192];
    uix[(size_t)b * 256 + t] = v;
}

__global__ void gather_sg_kernel(
    const float* __restrict__ sg0, const float* __restrict__ sg1,
    const int* __restrict__ subg, float* __restrict__ sgx)
{
    int b = blockIdx.x;
    int t = threadIdx.x;
    int s = subg[b];
    float w = (t < 64) ? sg0[(size_t)s * 64 + t] : sg1[(size_t)s * 64 + t - 64];
    sgx[(size_t)b * 128 + t] = w;
}

__global__ void final_out_kernel(
    const float* __restrict__ hui, const float* __restrict__ hsg,
    const float* __restrict__ w2ui, const float* __restrict__ b2ui,
    const float* __restrict__ w2sg, const float* __restrict__ b2sg,
    float* __restrict__ out)
{
    int r = blockIdx.x * 8 + (threadIdx.x >> 5);
    int lane = threadIdx.x & 31;
    if (r >= BB) return;
    float su = 0.f, ss = 0.f;
#pragma unroll
    for (int k = lane; k < 128; k += 32) {
        su += hui[(size_t)r * 128 + k] * w2ui[k];
        ss += hsg[(size_t)r * 128 + k] * w2sg[k];
    }
#pragma unroll
    for (int o = 16; o; o >>= 1) {
        su += __shfl_xor_sync(0xffffffffu, su, o);
        ss += __shfl_xor_sync(0xffffffffu, ss, o);
    }
    if (lane == 0) {
        out[r]      = 1.f / (1.f + expf(-(ss + b2sg[0])));   // sg_out
        out[BB + r] = 1.f / (1.f + expf(-(su + b2ui[0])));   // ui_out
    }
}

// ---------------- host orchestration ----------------
template <typename K, typename... Args>
static void launch_pdl(K kernel, dim3 grid, dim3 block, cudaStream_t st, Args... args) {
    cudaLaunchAttribute at;
    at.id = cudaLaunchAttributeProgrammaticStreamSerialization;
    at.val.programmaticStreamSerializationAllowed = 1;
    cudaLaunchConfig_t cfg = {};
    cfg.gridDim = grid; cfg.blockDim = block; cfg.stream = st;
    cfg.attrs = &at; cfg.numAttrs = 1;
    cudaLaunchKernelEx(&cfg, kernel, args...);
}

static void gemm_s(const float* A, const float* W, const float* bias, float* C,
                   int M, int N, int K, int act, cudaStream_t st, bool pdl) {
    dim3 g((M + 127) / 128, N / 64);
    if (pdl) launch_pdl(gemm_act_kernel, g, dim3(256), st, A, W, bias, C, M, N, K, act);
    else     gemm_act_kernel<<<g, 256, 0, st>>>(A, W, bias, C, M, N, K, act);
}

extern "C" void kernel_launch(void* const* d_in, const int* in_sizes, int n_in,
                              void* d_out, int out_size) {
    const float* x        = (const float*)d_in[0];
    const float* efeat    = (const float*)d_in[1];
    const float* efeat2   = (const float*)d_in[2];
    const float* mask1    = (const float*)d_in[3];
    const float* mask2    = (const float*)d_in[4];
    const int*   src      = (const int*)d_in[5];
    const int*   dst      = (const int*)d_in[6];
    const int*   user     = (const int*)d_in[7];
    const int*   item     = (const int*)d_in[8];
    const int*   subg     = (const int*)d_in[9];
    const float* loc_wni  = (const float*)d_in[10];
    const float* loc_wnj  = (const float*)d_in[11];
    const float* loc_we   = (const float*)d_in[12];
    const float* loc_attn = (const float*)d_in[13];
    const float* loc_wnode= (const float*)d_in[14];
    const float* agg1_w   = (const float*)d_in[15];
    const float* agg1_b   = (const float*)d_in[16];
    const float* glob_wni = (const float*)d_in[17];
    const float* glob_wnj = (const float*)d_in[18];
    const float* glob_we  = (const float*)d_in[19];
    const float* glob_attn= (const float*)d_in[20];
    const float* glob_wnode=(const float*)d_in[21];
    const float* agg2_w   = (const float*)d_in[22];
    const float* agg2_b   = (const float*)d_in[23];
    const float* w1_ui    = (const float*)d_in[24];
    const float* b1_ui    = (const float*)d_in[25];
    const float* w1_sg    = (const float*)d_in[26];
    const float* b1_sg    = (const float*)d_in[27];
    const float* w2_ui    = (const float*)d_in[28];
    const float* b2_ui    = (const float*)d_in[29];
    const float* w2_sg    = (const float*)d_in[30];
    const float* b2_sg    = (const float*)d_in[31];

    float *p_xwi, *p_xwj, *p_fn, *p_agg, *p_scores, *p_mkc1, *p_mkc2;
    float *p_ui0, *p_ui1, *p_sg0, *p_sg1, *p_uix, *p_sgx, *p_hui, *p_hsg;
    int *p_deg, *p_off, *p_cur, *p_eid, *p_epos, *p_srcc;
    cudaGetSymbolAddress((void**)&p_xwi, g_xwi);
    cudaGetSymbolAddress((void**)&p_xwj, g_xwj);
    cudaGetSymbolAddress((void**)&p_fn,  g_fn);
    cudaGetSymbolAddress((void**)&p_agg, g_agg);
    cudaGetSymbolAddress((void**)&p_scores, g_scores);
    cudaGetSymbolAddress((void**)&p_mkc1, g_mkc1);
    cudaGetSymbolAddress((void**)&p_mkc2, g_mkc2);
    cudaGetSymbolAddress((void**)&p_ui0, g_ui0);
    cudaGetSymbolAddress((void**)&p_ui1, g_ui1);
    cudaGetSymbolAddress((void**)&p_sg0, g_sg0);
    cudaGetSymbolAddress((void**)&p_sg1, g_sg1);
    cudaGetSymbolAddress((void**)&p_uix, g_uix);
    cudaGetSymbolAddress((void**)&p_sgx, g_sgx);
    cudaGetSymbolAddress((void**)&p_hui, g_hui);
    cudaGetSymbolAddress((void**)&p_hsg, g_hsg);
    cudaGetSymbolAddress((void**)&p_deg, g_deg);
    cudaGetSymbolAddress((void**)&p_off, g_off);
    cudaGetSymbolAddress((void**)&p_cur, g_cur);
    cudaGetSymbolAddress((void**)&p_eid, g_eid);
    cudaGetSymbolAddress((void**)&p_epos, g_epos);
    cudaGetSymbolAddress((void**)&p_srcc, g_srcc);

    cudaStream_t s1;
    cudaStreamCreateWithFlags(&s1, cudaStreamNonBlocking);
    cudaEvent_t ev0, ev1, ev2, ev3;
    cudaEventCreateWithFlags(&ev0, cudaEventDisableTiming);
    cudaEventCreateWithFlags(&ev1, cudaEventDisableTiming);
    cudaEventCreateWithFlags(&ev2, cudaEventDisableTiming);
    cudaEventCreateWithFlags(&ev3, cudaEventDisableTiming);

    // fork: CSR build on s1, overlapped with stage-0 node GEMM
    cudaEventRecord(ev0, 0);
    cudaStreamWaitEvent(s1, ev0, 0);
    cudaMemsetAsync(p_deg, 0, NN * sizeof(int), s1);
    hist_kernel<<<(NE + 255) / 256, 256, 0, s1>>>(dst, p_deg);
    scan_kernel<<<1, 1024, 0, s1>>>(p_deg, p_off, p_cur, NN);
    fill_kernel<<<(NE + 255) / 256, 256, 0, s1>>>(dst, src, mask1, mask2, p_off,
                                                  p_cur, p_eid, p_epos, p_srcc,
                                                  p_mkc1, p_mkc2);
    cudaEventRecord(ev1, s1);

    struct Stage {
        const float* hin; const float* ef; int Ke; const float* mkc;
        const float* wni; const float* wnj; const float* we; const float* attn;
        const float* wnode; const float* aggw; const float* aggb; int act; float* hout;
    };
    Stage st[4] = {
        { x,     efeat,  16, p_mkc1, loc_wni,           loc_wnj,           loc_we,           loc_attn,         loc_wnode,           agg1_w,          agg1_b,       1, p_ui0 },
        { p_ui0, efeat2, 64, p_mkc2, glob_wni,          glob_wnj,          glob_we,          glob_attn,        glob_wnode,          agg2_w,          agg2_b,       2, p_sg0 },
        { p_sg0, efeat,  16, p_mkc1, loc_wni  + 64*128, loc_wnj  + 64*128, loc_we  + 16*128, loc_attn  + 128,  loc_wnode  + 64*256, agg1_w + 256*64, agg1_b + 64,  1, p_ui1 },
        { p_ui1, efeat2, 64, p_mkc2, glob_wni + 64*128, glob_wnj + 64*128, glob_we + 64*128, glob_attn + 128,  glob_wnode + 64*256, agg2_w + 256*64, agg2_b + 64,  2, p_sg1 },
    };

    for (int s = 0; s < 4; s++) {
        launch_pdl(node_gemm_kernel, dim3((NN + 127) / 128, 4), dim3(256), (cudaStream_t)0,
                   st[s].hin, st[s].wni, st[s].wnj, st[s].wnode, p_xwi, p_xwj, p_fn, (int)NN);
        if (s == 0) cudaStreamWaitEvent(0, ev1, 0);   // join: edge_score needs epos
        launch_pdl(edge_score_fused_kernel, dim3((NE + 63) / 64), dim3(256), (cudaStream_t)0,
                   st[s].ef, st[s].we, st[s].attn, src, dst, p_epos, p_xwi, p_xwj,
                   p_scores, st[s].Ke);
        launch_pdl(attn_agg_kernel, dim3((NN + 7) / 8), dim3(256), (cudaStream_t)0,
                   (const float*)p_scores, st[s].mkc, (const int*)p_srcc,
                   (const float*)p_fn, (const int*)p_off, p_agg);
        gemm_s(p_agg, st[s].aggw, st[s].aggb, st[s].hout, NN, 64, 256, st[s].act, 0, true);
        if (s == 2) {
            cudaEventRecord(ev2, 0);
            cudaStreamWaitEvent(s1, ev2, 0);
            gather_ui_kernel<<<BB, 256, 0, s1>>>(p_ui0, p_ui1, user, item, p_uix);
            gemm_s(p_uix, w1_ui, b1_ui, p_hui, BB, 128, 256, 3, s1, false);
            cudaEventRecord(ev3, s1);
        }
    }

    gather_sg_kernel<<<BB, 128>>>(p_sg0, p_sg1, subg, p_sgx);
    gemm_s(p_sgx, w1_sg, b1_sg, p_hsg, BB, 128, 128, 3, 0, false);
    cudaStreamWaitEvent(0, ev3, 0);   // join ui branch
    final_out_kernel<<<BB / 8, 256>>>(p_hui, p_hsg, w2_ui, b2_ui, w2_sg, b2_sg, (float*)d_out);
}